// round 14
// baseline (speedup 1.0000x reference)
#include <cuda_runtime.h>
#include <cuda_fp16.h>
#include <math.h>
#include <stdint.h>

#define BB 32
#define TT 12
#define NN 512
#define HH 64
#define EE 16
#define BTN (BB*TT*NN)
#define BTNH (BTN*HH)
#define ZT (BB*TT)
#define GRID_P 256
#define RECUR_SMEM 51712
#define TAIL_SMEM  78848

__device__ float g_adj[NN*NN];
__device__ __half g_adjh[NN*NN];
__device__ float g_gW[NN*2*128*128];
__device__ float g_gb[NN*128];
__device__ float g_uW[NN*2*128*64];
__device__ float g_ub[NN*64];
__device__ float g_state[BB*NN*HH];
__device__ __half g_sh[BB*NN*HH];    // half mirror of state, same [b][n][c] layout
__device__ __half g_zsh[BB*NN*HH];   // half mirror of zs
__device__ float g_mixs[BB*NN*HH];
__device__ float g_zs[BB*NN*HH];
__device__ float g_mixzs[BB*NN*HH];
__device__ float g_r[BB*NN*HH];
__device__ float g_cg[TT*BB*NN*128];
__device__ float g_cu[TT*BB*NN*64];
__device__ float g_mxt[ZT*NN*64];
__device__ float g_xt0t[TT*NN*64];
__device__ float g_hs0[BTNH];
__device__ float g_hs1[BTNH];
__device__ float g_fs[NN*TT];
__device__ float g_hlin[NN*48];
__device__ float g_hv[BB*NN*HH];
__device__ float g_q[BTNH];
__device__ float g_k[BTNH];
__device__ float g_v[BB*NN*HH];
__device__ float g_o[BTNH];
__device__ unsigned g_bar;

__device__ __forceinline__ float to_tf32(float x) {
    uint32_t u; asm("cvt.rna.tf32.f32 %0, %1;" : "=r"(u) : "f"(x));
    return __uint_as_float(u);
}
__device__ __forceinline__ uint32_t cvu(float x) {
    uint32_t u; asm("cvt.rna.tf32.f32 %0, %1;" : "=r"(u) : "f"(x));
    return u;
}
__device__ __forceinline__ float4 tf32x4(float4 v) {
    float4 w; w.x=to_tf32(v.x); w.y=to_tf32(v.y); w.z=to_tf32(v.z); w.w=to_tf32(v.w);
    return w;
}
__device__ __forceinline__ void mma_tf32(float* c, const uint32_t* a, uint32_t b0, uint32_t b1) {
    asm volatile("mma.sync.aligned.m16n8k8.row.col.f32.tf32.tf32.f32 "
        "{%0,%1,%2,%3}, {%4,%5,%6,%7}, {%8,%9}, {%0,%1,%2,%3};"
        : "+f"(c[0]), "+f"(c[1]), "+f"(c[2]), "+f"(c[3])
        : "r"(a[0]), "r"(a[1]), "r"(a[2]), "r"(a[3]), "r"(b0), "r"(b1));
}
__device__ __forceinline__ void mma_f16(float* c, const uint32_t* a, uint32_t b0, uint32_t b1) {
    asm volatile("mma.sync.aligned.m16n8k16.row.col.f32.f16.f16.f32 "
        "{%0,%1,%2,%3}, {%4,%5,%6,%7}, {%8,%9}, {%0,%1,%2,%3};"
        : "+f"(c[0]), "+f"(c[1]), "+f"(c[2]), "+f"(c[3])
        : "r"(a[0]), "r"(a[1]), "r"(a[2]), "r"(a[3]), "r"(b0), "r"(b1));
}
__device__ __forceinline__ void ldsm4(uint32_t& r0, uint32_t& r1, uint32_t& r2, uint32_t& r3, uint32_t addr) {
    asm volatile("ldmatrix.sync.aligned.m8n8.x4.shared.b16 {%0,%1,%2,%3}, [%4];"
        : "=r"(r0), "=r"(r1), "=r"(r2), "=r"(r3) : "r"(addr));
}
__device__ __forceinline__ void ldsm4t(uint32_t& r0, uint32_t& r1, uint32_t& r2, uint32_t& r3, uint32_t addr) {
    asm volatile("ldmatrix.sync.aligned.m8n8.x4.trans.shared.b16 {%0,%1,%2,%3}, [%4];"
        : "=r"(r0), "=r"(r1), "=r"(r2), "=r"(r3) : "r"(addr));
}
__device__ __forceinline__ float sigm(float v) { return 1.f / (1.f + __expf(-v)); }
__device__ __forceinline__ float tanhfast(float v) { return 1.f - 2.f / (__expf(2.f*v) + 1.f); }

__device__ __forceinline__ void gbar(unsigned n) {
    __syncthreads();
    if (threadIdx.x == 0) {
        __threadfence();
        atomicAdd(&g_bar, 1u);
        unsigned target = n * GRID_P;
        volatile unsigned* p = &g_bar;
        while (*p < target) __nanosleep(64);
        __threadfence();
    }
    __syncthreads();
}

// ---------------- fused pre-kernel: adjacency (fp32 tf32 + half) + matpools + layer0 transpose ----------------
__global__ void k_fused_pre(const float* __restrict__ emb,
                            const float* __restrict__ gwp, const float* __restrict__ gbp,
                            const float* __restrict__ uwp, const float* __restrict__ ubp,
                            float* __restrict__ gW, float* __restrict__ gb,
                            float* __restrict__ uW, float* __restrict__ ub,
                            int SgW4, int SuW4,
                            const float* __restrict__ src, float* __restrict__ xt0,
                            int do_adj) {
    __shared__ float semb[NN*EE];
    __shared__ float row[NN];
    __shared__ float red[256];
    if (blockIdx.x < NN) {
        if (!do_adj) return;
        if (blockIdx.x == 0 && threadIdx.x == 0) g_bar = 0u;
        for (int i = blockIdx.x*256 + threadIdx.x; i < NN*48; i += NN*256) g_hlin[i] = 0.f;
        int n = blockIdx.x;
        for (int i = threadIdx.x; i < NN*EE; i += 256) semb[i] = emb[i];
        __syncthreads();
        float lmax = -1e30f;
        for (int m = threadIdx.x; m < NN; m += 256) {
            float s = 0.f;
            #pragma unroll
            for (int e = 0; e < EE; ++e) s += semb[n*EE+e] * semb[m*EE+e];
            s = fmaxf(s, 0.f);
            row[m] = s;
            lmax = fmaxf(lmax, s);
        }
        red[threadIdx.x] = lmax; __syncthreads();
        for (int s = 128; s > 0; s >>= 1) {
            if (threadIdx.x < s) red[threadIdx.x] = fmaxf(red[threadIdx.x], red[threadIdx.x+s]);
            __syncthreads();
        }
        float mx = red[0];
        __syncthreads();
        float lsum = 0.f;
        for (int m = threadIdx.x; m < NN; m += 256) {
            float v = expf(row[m] - mx);
            row[m] = v; lsum += v;
        }
        red[threadIdx.x] = lsum; __syncthreads();
        for (int s = 128; s > 0; s >>= 1) {
            if (threadIdx.x < s) red[threadIdx.x] += red[threadIdx.x+s];
            __syncthreads();
        }
        float inv = 1.f / red[0];
        for (int m = threadIdx.x; m < NN; m += 256) {
            float a = row[m] * inv;
            g_adj[n*NN + m] = to_tf32(a);
            g_adjh[n*NN + m] = __float2half_rn(a);
        }
        return;
    }
    int idx = (blockIdx.x - NN)*256 + threadIdx.x;
    int t0 = NN*SgW4, t1 = t0 + NN*32, t2 = t1 + NN*SuW4, t3 = t2 + NN*16;
    if (idx < t3) {
        const float* pool; float* out; int S4, local, rnd;
        if (idx < t0)      { pool = gwp; out = gW; S4 = SgW4; local = idx;      rnd = 1; }
        else if (idx < t1) { pool = gbp; out = gb; S4 = 32;   local = idx - t0; rnd = 0; }
        else if (idx < t2) { pool = uwp; out = uW; S4 = SuW4; local = idx - t1; rnd = 1; }
        else               { pool = ubp; out = ub; S4 = 16;   local = idx - t2; rnd = 0; }
        int n = local / S4, i = local - n*S4;
        float4 a = make_float4(0.f,0.f,0.f,0.f);
        const float* e = emb + n*EE;
        const float4* p4 = (const float4*)pool;
        #pragma unroll
        for (int k = 0; k < EE; ++k) {
            float w = e[k];
            float4 p = p4[(size_t)k*S4 + i];
            a.x += w*p.x; a.y += w*p.y; a.z += w*p.z; a.w += w*p.w;
        }
        if (rnd) a = tf32x4(a);
        ((float4*)out)[local] = a;
    } else if (src) {
        int t = idx - t3;
        if (t < ZT*NN*2) {
            int c = t & 1, m = (t >> 1) & 511, z = t >> 10;
            int g = z*2 + c;
            xt0[((size_t)(g>>6)*NN + m)*64 + (g&63)] = src[t];
        }
    }
}

// ---------------- fp32 tf32 mix tile (premix only; unchanged from R12) ----------------
__device__ __forceinline__ void mix_tile(const float* __restrict__ X, float* __restrict__ Y,
                                         float* sm, int tid, int z, int r0) {
    int warp = tid >> 5, lane = tid & 31;
    int wm = warp >> 1, wn = warp & 1;
    const float* Xb = X + (size_t)z * (NN*64);
    float* Yb = Y + (size_t)z * (NN*64);
    float acc[4][4];
    #pragma unroll
    for (int j=0;j<4;++j){acc[j][0]=0.f;acc[j][1]=0.f;acc[j][2]=0.f;acc[j][3]=0.f;}
    float4 ar0, ar1, xr0, xr1;
    int i0 = tid, i1 = tid + 256;
    ar0 = *(const float4*)&g_adj[(size_t)(r0 + (i0>>3))*NN + (i0&7)*4];
    ar1 = *(const float4*)&g_adj[(size_t)(r0 + (i1>>3))*NN + (i1&7)*4];
    xr0 = *(const float4*)&Xb[(size_t)(i0>>4)*64 + (i0&15)*4];
    xr1 = *(const float4*)&Xb[(size_t)(i1>>4)*64 + (i1&15)*4];
    {
        float* As = sm; float* Xs = sm + 4608;
        *(float4*)&As[(i0>>3)*36 + (i0&7)*4] = ar0;
        *(float4*)&As[(i1>>3)*36 + (i1&7)*4] = ar1;
        *(float4*)&Xs[(i0>>4)*72 + (i0&15)*4] = tf32x4(xr0);
        *(float4*)&Xs[(i1>>4)*72 + (i1&15)*4] = tf32x4(xr1);
    }
    for (int c = 0; c < 16; ++c) {
        __syncthreads();
        if (c < 15) {
            int kc = (c+1)*32;
            ar0 = *(const float4*)&g_adj[(size_t)(r0 + (i0>>3))*NN + kc + (i0&7)*4];
            ar1 = *(const float4*)&g_adj[(size_t)(r0 + (i1>>3))*NN + kc + (i1&7)*4];
            xr0 = *(const float4*)&Xb[(size_t)(kc + (i0>>4))*64 + (i0&15)*4];
            xr1 = *(const float4*)&Xb[(size_t)(kc + (i1>>4))*64 + (i1&15)*4];
        }
        float* As = sm + (c&1)*2304;
        float* Xs = sm + 4608 + (c&1)*2304;
        #pragma unroll
        for (int k8 = 0; k8 < 32; k8 += 8) {
            uint32_t a[4];
            int arow = wm*16 + (lane>>2);
            int ac = k8 + (lane&3);
            a[0] = __float_as_uint(As[arow*36 + ac]);
            a[1] = __float_as_uint(As[(arow+8)*36 + ac]);
            a[2] = __float_as_uint(As[arow*36 + ac + 4]);
            a[3] = __float_as_uint(As[(arow+8)*36 + ac + 4]);
            #pragma unroll
            for (int j = 0; j < 4; ++j) {
                int col = wn*32 + j*8 + (lane>>2);
                uint32_t b0 = __float_as_uint(Xs[(k8+(lane&3))*72 + col]);
                uint32_t b1 = __float_as_uint(Xs[(k8+(lane&3)+4)*72 + col]);
                mma_tf32(acc[j], a, b0, b1);
            }
        }
        if (c < 15) {
            float* Asn = sm + ((c+1)&1)*2304;
            float* Xsn = sm + 4608 + ((c+1)&1)*2304;
            *(float4*)&Asn[(i0>>3)*36 + (i0&7)*4] = ar0;
            *(float4*)&Asn[(i1>>3)*36 + (i1&7)*4] = ar1;
            *(float4*)&Xsn[(i0>>4)*72 + (i0&15)*4] = tf32x4(xr0);
            *(float4*)&Xsn[(i1>>4)*72 + (i1&15)*4] = tf32x4(xr1);
        }
    }
    int row = r0 + wm*16 + (lane>>2);
    #pragma unroll
    for (int j = 0; j < 4; ++j) {
        int col = wn*32 + j*8 + (lane&3)*2;
        *(float2*)&Yb[(size_t)row*64 + col] = make_float2(acc[j][0], acc[j][1]);
        *(float2*)&Yb[(size_t)(row+8)*64 + col] = make_float2(acc[j][2], acc[j][3]);
    }
}

__global__ void __launch_bounds__(256) k_mix64(const float* __restrict__ X, float* __restrict__ Y) {
    __shared__ float sm[9216];
    mix_tile(X, Y, sm, threadIdx.x, blockIdx.y, blockIdx.x*64);
}

// ---------------- fp16 ldmatrix mix tile (recurrence) ----------------
// smem bytes: A0@0 (64x40h=5120), A1@5120, X0@10240 (32x72h=4608), X1@14848
__device__ __forceinline__ void mix16(const __half* __restrict__ Xh, float* __restrict__ Y,
                                      float* smf, int tid, int z, int r0) {
    char* smb = (char*)smf;
    uint32_t sb = (uint32_t)__cvta_generic_to_shared(smb);
    int warp = tid >> 5, lane = tid & 31;
    int wm = warp >> 1, wn = warp & 1;
    const __half* Xz = Xh + (size_t)z * (NN*64);
    float* Yb = Y + (size_t)z * (NN*64);
    float acc[4][4];
    #pragma unroll
    for (int j=0;j<4;++j){acc[j][0]=0.f;acc[j][1]=0.f;acc[j][2]=0.f;acc[j][3]=0.f;}
    int arow = tid >> 2, acolh = (tid & 3) * 8;
    int xrow = tid >> 3, xcolh = (tid & 7) * 8;
    uint4 av = *(const uint4*)&g_adjh[(size_t)(r0 + arow)*NN + acolh];
    uint4 xv = *(const uint4*)&Xz[(size_t)xrow*64 + xcolh];
    *(uint4*)(smb + arow*80 + (tid&3)*16) = av;
    *(uint4*)(smb + 10240 + xrow*144 + (tid&7)*16) = xv;
    uint32_t a_l = (wm*16 + (lane & 15)) * 80 + ((lane >> 4) * 8) * 2;
    uint32_t xk_l = (lane & 7) + ((lane >> 3) & 1) * 8;
    uint32_t xn_l = (lane >> 4) * 8;
    for (int c = 0; c < 16; ++c) {
        __syncthreads();
        if (c < 15) {
            int kc = (c+1)*32;
            av = *(const uint4*)&g_adjh[(size_t)(r0 + arow)*NN + kc + acolh];
            xv = *(const uint4*)&Xz[(size_t)(kc + xrow)*64 + xcolh];
        }
        uint32_t ab = sb + (c&1)*5120;
        uint32_t xb = sb + 10240 + (c&1)*4608;
        #pragma unroll
        for (int kb = 0; kb < 2; ++kb) {
            uint32_t a[4];
            ldsm4(a[0], a[1], a[2], a[3], ab + a_l + kb*32);
            #pragma unroll
            for (int cg = 0; cg < 2; ++cg) {
                int c0 = wn*32 + cg*16;
                uint32_t b0, b1, b2, b3;
                ldsm4t(b0, b1, b2, b3, xb + (kb*16 + xk_l)*144 + (c0 + xn_l)*2);
                mma_f16(acc[cg*2+0], a, b0, b1);
                mma_f16(acc[cg*2+1], a, b2, b3);
            }
        }
        if (c < 15) {
            *(uint4*)(smb + ((c+1)&1)*5120 + arow*80 + (tid&3)*16) = av;
            *(uint4*)(smb + 10240 + ((c+1)&1)*4608 + xrow*144 + (tid&7)*16) = xv;
        }
    }
    int row = r0 + wm*16 + (lane>>2);
    #pragma unroll
    for (int j = 0; j < 4; ++j) {
        int col = wn*32 + j*8 + (lane&3)*2;
        *(float2*)&Yb[(size_t)row*64 + col] = make_float2(acc[j][0], acc[j][1]);
        *(float2*)&Yb[(size_t)(row+8)*64 + col] = make_float2(acc[j][2], acc[j][3]);
    }
}

// ---------------- persistent recurrence phases ----------------
__device__ __forceinline__ void phase_gate(const float* __restrict__ gW, const float* __restrict__ cg_t,
                                           int C, int Cin, float* sm, int tid) {
    int warp = tid >> 5, lane = tid & 31;
    int wm = warp >> 2, wn = warp & 3;
    float (*As)[132] = (float(*)[132])sm;
    for (int n = blockIdx.x; n < NN; n += GRID_P) {
        __syncthreads();
        #pragma unroll
        for (int i = 0; i < 4; ++i) {
            int idx = tid + i*256;
            int row = idx >> 5;
            int c4 = (idx & 31) * 4;
            float4 v = (c4 < 64)
                ? *(const float4*)&g_state[((size_t)row*NN + n)*64 + c4]
                : *(const float4*)&g_mixs[((size_t)row*NN + n)*64 + c4 - 64];
            *(float4*)&As[row][c4] = v;
        }
        {
            float* Bs = sm + 4224;
            #pragma unroll
            for (int i = 0; i < 4; ++i) {
                int idx = tid + i*256;
                int kk = idx >> 5;
                int c4 = (idx & 31) * 4;
                float4 v = *(const float4*)&gW[((size_t)(2*n + (kk>=64))*C + Cin + (kk&63))*128 + c4];
                *(float4*)&Bs[kk*136 + c4] = v;
            }
        }
        float acc[4][4];
        #pragma unroll
        for (int j=0;j<4;++j){acc[j][0]=0.f;acc[j][1]=0.f;acc[j][2]=0.f;acc[j][3]=0.f;}
        float4 bv[4];
        for (int c = 0; c < 4; ++c) {
            __syncthreads();
            if (c < 3) {
                int kc = (c+1)*32;
                #pragma unroll
                for (int i = 0; i < 4; ++i) {
                    int idx = tid + i*256;
                    int kk = kc + (idx >> 5);
                    int c4 = (idx & 31) * 4;
                    bv[i] = *(const float4*)&gW[((size_t)(2*n + (kk>=64))*C + Cin + (kk&63))*128 + c4];
                }
            }
            float* Bs = sm + 4224 + (c&1)*4352;
            #pragma unroll
            for (int k8 = 0; k8 < 32; k8 += 8) {
                int arow = wm*16 + (lane>>2);
                int ac = c*32 + k8 + (lane&3);
                uint32_t a[4];
                a[0] = cvu(As[arow][ac]);
                a[1] = cvu(As[arow+8][ac]);
                a[2] = cvu(As[arow][ac+4]);
                a[3] = cvu(As[arow+8][ac+4]);
                #pragma unroll
                for (int j = 0; j < 4; ++j) {
                    int col = wn*32 + j*8 + (lane>>2);
                    uint32_t b0 = __float_as_uint(Bs[(k8+(lane&3))*136 + col]);
                    uint32_t b1 = __float_as_uint(Bs[(k8+(lane&3)+4)*136 + col]);
                    mma_tf32(acc[j], a, b0, b1);
                }
            }
            if (c < 3) {
                float* Bsn = sm + 4224 + ((c+1)&1)*4352;
                #pragma unroll
                for (int i = 0; i < 4; ++i) {
                    int idx = tid + i*256;
                    int c4 = (idx & 31) * 4;
                    *(float4*)&Bsn[(idx>>5)*136 + c4] = bv[i];
                }
            }
        }
        #pragma unroll
        for (int j = 0; j < 4; ++j) {
            int col = wn*32 + j*8 + (lane&3)*2;
            #pragma unroll
            for (int half = 0; half < 2; ++half) {
                int b = wm*16 + (lane>>2) + half*8;
                float v0 = acc[j][half*2], v1 = acc[j][half*2+1];
                size_t base = (size_t)b*NN + n;
                float2 cgv = *(const float2*)&cg_t[base*128 + col];
                v0 += cgv.x; v1 += cgv.y;
                if (col < 64) {
                    float z0 = sigm(v0) * As[b][col];
                    float z1 = sigm(v1) * As[b][col+1];
                    *(float2*)&g_zs[base*64 + col] = make_float2(z0, z1);
                    *(__half2*)&g_zsh[base*64 + col] = __floats2half2_rn(z0, z1);
                } else {
                    *(float2*)&g_r[base*64 + col - 64] = make_float2(sigm(v0), sigm(v1));
                }
            }
        }
    }
}

__device__ __forceinline__ void phase_upd(const float* __restrict__ uW, const float* __restrict__ cu_t,
                                          int C, int Cin, float* __restrict__ hs, int t,
                                          float* sm, int tid, float* __restrict__ hv) {
    int warp = tid >> 5, lane = tid & 31;
    int wm = warp >> 2, wn = warp & 3;
    float (*As)[132] = (float(*)[132])sm;
    for (int n = blockIdx.x; n < NN; n += GRID_P) {
        __syncthreads();
        #pragma unroll
        for (int i = 0; i < 4; ++i) {
            int idx = tid + i*256;
            int row = idx >> 5;
            int c4 = (idx & 31) * 4;
            float4 v = (c4 < 64)
                ? *(const float4*)&g_zs[((size_t)row*NN + n)*64 + c4]
                : *(const float4*)&g_mixzs[((size_t)row*NN + n)*64 + c4 - 64];
            *(float4*)&As[row][c4] = v;
        }
        {
            float* Bs = sm + 4224;
            #pragma unroll
            for (int i = 0; i < 2; ++i) {
                int idx = tid + i*256;
                int kk = idx >> 4;
                int c4 = (idx & 15) * 4;
                float4 v = *(const float4*)&uW[((size_t)(2*n + (kk>=64))*C + Cin + (kk&63))*64 + c4];
                *(float4*)&Bs[kk*72 + c4] = v;
            }
        }
        float acc[2][4];
        #pragma unroll
        for (int j=0;j<2;++j){acc[j][0]=0.f;acc[j][1]=0.f;acc[j][2]=0.f;acc[j][3]=0.f;}
        float4 bv[2];
        for (int c = 0; c < 4; ++c) {
            __syncthreads();
            if (c < 3) {
                int kc = (c+1)*32;
                #pragma unroll
                for (int i = 0; i < 2; ++i) {
                    int idx = tid + i*256;
                    int kk = kc + (idx >> 4);
                    int c4 = (idx & 15) * 4;
                    bv[i] = *(const float4*)&uW[((size_t)(2*n + (kk>=64))*C + Cin + (kk&63))*64 + c4];
                }
            }
            float* Bs = sm + 4224 + (c&1)*2304;
            #pragma unroll
            for (int k8 = 0; k8 < 32; k8 += 8) {
                int arow = wm*16 + (lane>>2);
                int ac = c*32 + k8 + (lane&3);
                uint32_t a[4];
                a[0] = cvu(As[arow][ac]);
                a[1] = cvu(As[arow+8][ac]);
                a[2] = cvu(As[arow][ac+4]);
                a[3] = cvu(As[arow+8][ac+4]);
                #pragma unroll
                for (int j = 0; j < 2; ++j) {
                    int col = wn*16 + j*8 + (lane>>2);
                    uint32_t b0 = __float_as_uint(Bs[(k8+(lane&3))*72 + col]);
                    uint32_t b1 = __float_as_uint(Bs[(k8+(lane&3)+4)*72 + col]);
                    mma_tf32(acc[j], a, b0, b1);
                }
            }
            if (c < 3) {
                float* Bsn = sm + 4224 + ((c+1)&1)*2304;
                #pragma unroll
                for (int i = 0; i < 2; ++i) {
                    int idx = tid + i*256;
                    int c4 = (idx & 15) * 4;
                    *(float4*)&Bsn[(idx>>4)*72 + c4] = bv[i];
                }
            }
        }
        #pragma unroll
        for (int j = 0; j < 2; ++j) {
            int col = wn*16 + j*8 + (lane&3)*2;
            #pragma unroll
            for (int half = 0; half < 2; ++half) {
                int b = wm*16 + (lane>>2) + half*8;
                float v0 = acc[j][half*2], v1 = acc[j][half*2+1];
                size_t base = (size_t)b*NN + n;
                float2 cuv = *(const float2*)&cu_t[base*64 + col];
                float hc0 = tanhfast(v0 + cuv.x), hc1 = tanhfast(v1 + cuv.y);
                size_t idx = base*64 + col;
                float2 rr = *(const float2*)&g_r[idx];
                float2 st = *(const float2*)&g_state[idx];
                float h0 = rr.x*st.x + (1.f-rr.x)*hc0;
                float h1 = rr.y*st.y + (1.f-rr.y)*hc1;
                *(float2*)&g_state[idx] = make_float2(h0, h1);
                *(__half2*)&g_sh[idx] = __floats2half2_rn(h0, h1);
                *(float2*)&hs[(((size_t)b*TT + t)*NN + n)*64 + col] = make_float2(h0, h1);
                if (hv && t == TT-1)
                    *(float2*)&hv[idx] = make_float2(h0, h1);
            }
        }
    }
}

__global__ void __launch_bounds__(256, 2) k_recur(
        const float* __restrict__ gW, const float* __restrict__ uW,
        const float* __restrict__ cg, const float* __restrict__ cu,
        float* __restrict__ hs, int C, int Cin, unsigned nbar,
        float* __restrict__ hv) {
    extern __shared__ float sm[];
    int tid = threadIdx.x;
    for (int idx = blockIdx.x*256 + tid; idx < BB*NN*64; idx += GRID_P*256) {
        int c = idx & 63;
        int n = (idx >> 6) & 511;
        int b = idx >> 15;
        size_t base = (size_t)b*NN + n;
        float r = sigm(cg[base*128 + 64 + c]);
        float hc = tanhfast(cu[base*64 + c]);
        float h = (1.f - r) * hc;
        g_state[base*64 + c] = h;
        g_sh[base*64 + c] = __float2half_rn(h);
        hs[(((size_t)b*TT)*NN + n)*64 + c] = h;
    }
    gbar(++nbar);
    int z = blockIdx.x >> 3;
    int r0 = (blockIdx.x & 7) * 64;
    for (int t = 1; t < TT; ++t) {
        const float* cg_t = cg + (size_t)t*BB*NN*128;
        const float* cu_t = cu + (size_t)t*BB*NN*64;
        mix16(g_sh, g_mixs, sm, tid, z, r0);
        gbar(++nbar);
        phase_gate(gW, cg_t, C, Cin, sm, tid);
        gbar(++nbar);
        mix16(g_zsh, g_mixzs, sm, tid, z, r0);
        gbar(++nbar);
        phase_upd(uW, cu_t, C, Cin, hs, t, sm, tid, hv);
        gbar(++nbar);
    }
}

// ---------------- precompute ----------------
__global__ void __launch_bounds__(192) k_precomp(
        const float* __restrict__ xt, const float* __restrict__ mxt,
        const float* __restrict__ gW, const float* __restrict__ uW,
        const float* __restrict__ gb, const float* __restrict__ ub,
        float* __restrict__ cg, float* __restrict__ cu, int Cin) {
    const int C = Cin + HH;
    __shared__ float xs[64][2];
    __shared__ float ms[64][2];
    int n = blockIdx.x;
    int r0 = blockIdx.y * 64;
    int tid = threadIdx.x;
    for (int idx = tid; idx < 64*Cin; idx += 192) {
        int r = idx / Cin, c = idx - r*Cin;
        int z = r0 + r;
        xs[r][c] = xt[((size_t)z*NN + n)*Cin + c];
        int g = z*Cin + c;
        ms[r][c] = mxt[((size_t)(g>>6)*NN + n)*64 + (g&63)];
    }
    __syncthreads();
    float a[64];
    #pragma unroll
    for (int i = 0; i < 64; ++i) a[i] = 0.f;
    if (tid < 128) {
        int o = tid;
        const float* W0 = gW + (size_t)(n*2)*C*128 + o;
        const float* W1 = gW + (size_t)(n*2+1)*C*128 + o;
        for (int c = 0; c < Cin; ++c) {
            float w0 = W0[c*128], w1 = W1[c*128];
            #pragma unroll
            for (int r = 0; r < 64; ++r) a[r] += xs[r][c]*w0 + ms[r][c]*w1;
        }
        float bias = gb[n*128 + o];
        for (int r = 0; r < 64; ++r) {
            int z = r0 + r; int b = z / 12, t = z - b*12;
            cg[(((size_t)t*BB + b)*NN + n)*128 + o] = a[r] + bias;
        }
    } else {
        int o = tid - 128;
        const float* W0 = uW + (size_t)(n*2)*C*64 + o;
        const float* W1 = uW + (size_t)(n*2+1)*C*64 + o;
        for (int c = 0; c < Cin; ++c) {
            float w0 = W0[c*64], w1 = W1[c*64];
            #pragma unroll
            for (int r = 0; r < 64; ++r) a[r] += xs[r][c]*w0 + ms[r][c]*w1;
        }
        float bias = ub[n*64 + o];
        for (int r = 0; r < 64; ++r) {
            int z = r0 + r; int b = z / 12, t = z - b*12;
            cu[(((size_t)t*BB + b)*NN + n)*64 + o] = a[r] + bias;
        }
    }
}

__global__ void __launch_bounds__(256) k_precomp_mma(
        const float* __restrict__ xt, const float* __restrict__ mxt,
        const float* __restrict__ gW, const float* __restrict__ uW,
        const float* __restrict__ gb, const float* __restrict__ ub,
        float* __restrict__ cg, float* __restrict__ cu) {
    const int C = 128;
    __shared__ float As[128][36];
    __shared__ float Bs[32][200];
    int n = blockIdx.x;
    int m0 = blockIdx.y * 128;
    int tid = threadIdx.x;
    int warp = tid >> 5, lane = tid & 31;
    int wm = warp >> 1, wn = warp & 1;
    float acc[2][12][4];
    #pragma unroll
    for (int mt=0;mt<2;++mt) for (int j=0;j<12;++j) for (int q=0;q<4;++q) acc[mt][j][q]=0.f;
    for (int kc = 0; kc < 128; kc += 32) {
        #pragma unroll
        for (int i = 0; i < 4; ++i) {
            int idx = tid + i*256;
            int row = idx >> 3;
            int c4 = (idx & 7) * 4;
            int z = m0 + row;
            int k = kc + c4;
            float4 v = (k < 64)
                ? *(const float4*)&xt[((size_t)z*NN + n)*64 + k]
                : *(const float4*)&mxt[((size_t)z*NN + n)*64 + k - 64];
            *(float4*)&As[row][c4] = tf32x4(v);
        }
        #pragma unroll
        for (int i = 0; i < 6; ++i) {
            int idx = tid + i*256;
            int krow = idx / 48;
            int c4 = (idx % 48) * 4;
            int kk = kc + krow;
            const float* src = (c4 < 128)
                ? gW + ((size_t)(2*n + (kk>=64))*C + (kk&63))*128 + c4
                : uW + ((size_t)(2*n + (kk>=64))*C + (kk&63))*64 + (c4 - 128);
            *(float4*)&Bs[krow][c4] = *(const float4*)src;
        }
        __syncthreads();
        #pragma unroll
        for (int k8 = 0; k8 < 32; k8 += 8) {
            uint32_t a[2][4];
            int ac = k8 + (lane&3);
            #pragma unroll
            for (int mt = 0; mt < 2; ++mt) {
                int rr = wm*32 + mt*16 + (lane>>2);
                a[mt][0] = __float_as_uint(As[rr][ac]);
                a[mt][1] = __float_as_uint(As[rr+8][ac]);
                a[mt][2] = __float_as_uint(As[rr][ac+4]);
                a[mt][3] = __float_as_uint(As[rr+8][ac+4]);
            }
            #pragma unroll
            for (int j = 0; j < 12; ++j) {
                int col = wn*96 + j*8 + (lane>>2);
                uint32_t b0 = __float_as_uint(Bs[k8 + (lane&3)][col]);
                uint32_t b1 = __float_as_uint(Bs[k8 + (lane&3) + 4][col]);
                mma_tf32(acc[0][j], a[0], b0, b1);
                mma_tf32(acc[1][j], a[1], b0, b1);
            }
        }
        __syncthreads();
    }
    #pragma unroll
    for (int mt = 0; mt < 2; ++mt) {
        #pragma unroll
        for (int j = 0; j < 12; ++j) {
            int col = wn*96 + j*8 + (lane&3)*2;
            #pragma unroll
            for (int half = 0; half < 2; ++half) {
                int z = m0 + wm*32 + mt*16 + (lane>>2) + half*8;
                int b = z / 12, t = z - b*12;
                float v0 = acc[mt][j][half*2], v1 = acc[mt][j][half*2+1];
                if (col < 128) {
                    float2 bb = *(const float2*)&gb[n*128 + col];
                    *(float2*)&cg[(((size_t)t*BB + b)*NN + n)*128 + col] =
                        make_float2(v0 + bb.x, v1 + bb.y);
                } else {
                    int o = col - 128;
                    float2 bb = *(const float2*)&ub[n*64 + o];
                    *(float2*)&cu[(((size_t)t*BB + b)*NN + n)*64 + o] =
                        make_float2(v0 + bb.x, v1 + bb.y);
                }
            }
        }
    }
}

// ---------------- hypernetwork: split-K MMA GEMM ----------------
__global__ void __launch_bounds__(256) k_hyp_mma(const float* __restrict__ hypW) {
    __shared__ float As[128][36];
    __shared__ float Bs[32][56];
    int m0 = blockIdx.x * 128;
    int k0 = blockIdx.y * 1024;
    int tid = threadIdx.x, warp = tid >> 5, lane = tid & 31;
    int wm = warp >> 1, wn = warp & 1;
    float acc[2][3][4];
    #pragma unroll
    for (int mt=0;mt<2;++mt) for (int j=0;j<3;++j) for (int q=0;q<4;++q) acc[mt][j][q]=0.f;
    for (int kc = k0; kc < k0 + 1024; kc += 32) {
        #pragma unroll
        for (int i = 0; i < 4; ++i) {
            int idx = tid + i*256;
            int row = idx >> 3;
            int c4 = (idx & 7) * 4;
            *(float4*)&As[row][c4] = *(const float4*)&g_uW[(size_t)(m0+row)*16384 + kc + c4];
        }
        if (tid < 128) {
            int krow = tid / 4, c4a = (tid % 4) * 4;
            #pragma unroll
            for (int seg = 0; seg < 3; ++seg) {
                int c4 = c4a + seg*16;
                if (c4 < 48)
                    *(float4*)&Bs[krow][c4] = tf32x4(*(const float4*)&hypW[(size_t)(kc+krow)*48 + c4]);
            }
        }
        __syncthreads();
        #pragma unroll
        for (int k8 = 0; k8 < 32; k8 += 8) {
            uint32_t a[2][4];
            int ac = k8 + (lane&3);
            #pragma unroll
            for (int mt = 0; mt < 2; ++mt) {
                int rr = wm*32 + mt*16 + (lane>>2);
                a[mt][0] = __float_as_uint(As[rr][ac]);
                a[mt][1] = __float_as_uint(As[rr+8][ac]);
                a[mt][2] = __float_as_uint(As[rr][ac+4]);
                a[mt][3] = __float_as_uint(As[rr+8][ac+4]);
            }
            #pragma unroll
            for (int j = 0; j < 3; ++j) {
                int col = wn*24 + j*8 + (lane>>2);
                uint32_t b0 = __float_as_uint(Bs[k8 + (lane&3)][col]);
                uint32_t b1 = __float_as_uint(Bs[k8 + (lane&3) + 4][col]);
                mma_tf32(acc[0][j], a[0], b0, b1);
                mma_tf32(acc[1][j], a[1], b0, b1);
            }
        }
        __syncthreads();
    }
    #pragma unroll
    for (int mt = 0; mt < 2; ++mt)
    #pragma unroll
    for (int j = 0; j < 3; ++j) {
        int col = wn*24 + j*8 + (lane&3)*2;
        int row = m0 + wm*32 + mt*16 + (lane>>2);
        atomicAdd(&g_hlin[row*48 + col],   acc[mt][j][0]);
        atomicAdd(&g_hlin[row*48 + col+1], acc[mt][j][1]);
        atomicAdd(&g_hlin[(row+8)*48 + col],   acc[mt][j][2]);
        atomicAdd(&g_hlin[(row+8)*48 + col+1], acc[mt][j][3]);
    }
}

__global__ void k_hyp_fin(const float* __restrict__ hypb) {
    int idx = blockIdx.x*blockDim.x + threadIdx.x;
    if (idx >= NN*TT) return;
    int t = idx % TT, n = idx / TT;
    float s = 0.f;
    #pragma unroll
    for (int f = 0; f < 4; ++f) s += g_hlin[n*48 + t*4 + f] + hypb[t*4 + f];
    g_fs[n*TT + t] = s;
}

__global__ void __launch_bounds__(256) k_gemm64_mma(
        const float* __restrict__ X, const float* __restrict__ W,
        const float* __restrict__ bias, float* __restrict__ Y, int relu) {
    __shared__ float Xs[128][36];
    __shared__ float Ws[32][72];
    int r0 = blockIdx.x * 128;
    int tid = threadIdx.x;
    int warp = tid >> 5, lane = tid & 31;
    float acc[8][4];
    #pragma unroll
    for (int j=0;j<8;++j) for (int q=0;q<4;++q) acc[j][q]=0.f;
    for (int kc = 0; kc < 64; kc += 32) {
        #pragma unroll
        for (int i = 0; i < 4; ++i) {
            int idx = tid + i*256;
            int row = idx >> 3;
            int c4 = (idx & 7) * 4;
            *(float4*)&Xs[row][c4] = tf32x4(*(const float4*)&X[(size_t)(r0+row)*64 + kc + c4]);
        }
        #pragma unroll
        for (int i = 0; i < 2; ++i) {
            int idx = tid + i*256;
            int krow = idx >> 4;
            int c4 = (idx & 15) * 4;
            *(float4*)&Ws[krow][c4] = tf32x4(*(const float4*)&W[(size_t)(kc+krow)*64 + c4]);
        }
        __syncthreads();
        #pragma unroll
        for (int k8 = 0; k8 < 32; k8 += 8) {
            uint32_t a[4];
            int ar = warp*16 + (lane>>2);
            int ac = k8 + (lane&3);
            a[0] = __float_as_uint(Xs[ar][ac]);
            a[1] = __float_as_uint(Xs[ar+8][ac]);
            a[2] = __float_as_uint(Xs[ar][ac+4]);
            a[3] = __float_as_uint(Xs[ar+8][ac+4]);
            #pragma unroll
            for (int j = 0; j < 8; ++j) {
                uint32_t b0 = __float_as_uint(Ws[k8 + (lane&3)][j*8 + (lane>>2)]);
                uint32_t b1 = __float_as_uint(Ws[k8 + (lane&3) + 4][j*8 + (lane>>2)]);
                mma_tf32(acc[j], a, b0, b1);
            }
        }
        __syncthreads();
    }
    int row = r0 + warp*16 + (lane>>2);
    #pragma unroll
    for (int j = 0; j < 8; ++j) {
        int col = j*8 + (lane&3)*2;
        float b0 = bias ? bias[col] : 0.f, b1 = bias ? bias[col+1] : 0.f;
        float v0 = acc[j][0] + b0, v1 = acc[j][1] + b1;
        float v2 = acc[j][2] + b0, v3 = acc[j][3] + b1;
        if (relu) { v0=fmaxf(v0,0.f); v1=fmaxf(v1,0.f); v2=fmaxf(v2,0.f); v3=fmaxf(v3,0.f); }
        *(float2*)&Y[(size_t)row*64 + col] = make_float2(v0, v1);
        *(float2*)&Y[(size_t)(row+8)*64 + col] = make_float2(v2, v3);
    }
}

__global__ void k_attn(const float* __restrict__ bv) {
    __shared__ float qs[12][64], ks[12][64], vs[12][64];
    __shared__ float sc[2][12][12];
    int bn = blockIdx.x;
    int b = bn >> 9, n = bn & 511;
    int tid = threadIdx.x;
    for (int idx = tid; idx < 12*64; idx += 128) {
        int t = idx >> 6, c = idx & 63;
        size_t g = (((size_t)b*TT + t)*NN + n)*HH + c;
        qs[t][c] = g_q[g];
        ks[t][c] = g_k[g];
        vs[t][c] = g_fs[n*TT + t] * g_v[((size_t)b*NN + n)*64 + c] + bv[c];
    }
    __syncthreads();
    for (int idx = tid; idx < 288; idx += 128) {
        int h = idx / 144, rem = idx - h*144;
        int t = rem / 12, s = rem - t*12;
        float d = 0.f;
        #pragma unroll
        for (int k = 0; k < 32; ++k) d += qs[t][h*32 + k] * ks[s][h*32 + k];
        sc[h][t][s] = d * 0.17677669529663687f;
    }
    __syncthreads();
    if (tid < 24) {
        int h = tid / 12, t = tid - h*12;
        float mx = -1e30f;
        #pragma unroll
        for (int s = 0; s < 12; ++s) mx = fmaxf(mx, sc[h][t][s]);
        float sum = 0.f;
        #pragma unroll
        for (int s = 0; s < 12; ++s) { float e = __expf(sc[h][t][s] - mx); sc[h][t][s] = e; sum += e; }
        float inv = 1.f / sum;
        #pragma unroll
        for (int s = 0; s < 12; ++s) sc[h][t][s] *= inv;
    }
    __syncthreads();
    for (int idx = tid; idx < 768; idx += 128) {
        int h = idx / 384, rem = idx - h*384;
        int t = rem >> 5, d = rem & 31;
        float a = 0.f;
        #pragma unroll
        for (int s = 0; s < 12; ++s) a += sc[h][t][s] * vs[s][h*32 + d];
        g_o[(((size_t)b*TT + t)*NN + n)*HH + h*32 + d] = a;
    }
}

// ---------------- fused tail ----------------
__global__ void __launch_bounds__(256) k_tail(
        const float* __restrict__ o_, const float* __restrict__ res,
        const float* __restrict__ ln1g, const float* __restrict__ ln1b,
        const float* __restrict__ W1, const float* __restrict__ b1,
        const float* __restrict__ W2, const float* __restrict__ b2,
        const float* __restrict__ ln2g, const float* __restrict__ ln2b,
        const float* __restrict__ fcW, const float* __restrict__ fcb,
        float* __restrict__ y) {
    extern __shared__ float smp[];
    float* val = smp;
    float* f1  = smp + 8704;
    float* Ws  = smp + 17408;
    int tid = threadIdx.x, warp = tid >> 5, lane = tid & 31;
    size_t r0 = (size_t)blockIdx.x * 128;

    for (int it = 0; it < 16; ++it) {
        int rl = it*8 + warp;
        size_t row = r0 + rl;
        int c = lane*2;
        float2 a = *(const float2*)&o_[row*64 + c];
        float2 b = *(const float2*)&res[row*64 + c];
        float x0 = a.x + b.x, x1 = a.y + b.y;
        float s = x0 + x1, sq = x0*x0 + x1*x1;
        #pragma unroll
        for (int o = 16; o > 0; o >>= 1) {
            s  += __shfl_xor_sync(0xffffffffu, s, o);
            sq += __shfl_xor_sync(0xffffffffu, sq, o);
        }
        float mu = s * (1.f/64.f);
        float var = sq * (1.f/64.f) - mu*mu;
        float rstd = rsqrtf(var + 1e-5f);
        val[rl*68 + c]   = (x0 - mu) * rstd * ln1g[c]   + ln1b[c];
        val[rl*68 + c+1] = (x1 - mu) * rstd * ln1g[c+1] + ln1b[c+1];
    }
    __syncthreads();

    int rowl = warp*16 + (lane>>2);
    {
        float acc[8][4];
        #pragma unroll
        for (int j=0;j<8;++j){acc[j][0]=0.f;acc[j][1]=0.f;acc[j][2]=0.f;acc[j][3]=0.f;}
        for (int kc = 0; kc < 64; kc += 32) {
            #pragma unroll
            for (int i = 0; i < 2; ++i) {
                int idx = tid + i*256;
                int krow = idx >> 4;
                int c4 = (idx & 15) * 4;
                *(float4*)&Ws[krow*72 + c4] = tf32x4(*(const float4*)&W1[(size_t)(kc+krow)*64 + c4]);
            }
            __syncthreads();
            #pragma unroll
            for (int k8 = 0; k8 < 32; k8 += 8) {
                uint32_t a[4];
                int ac = kc + k8 + (lane&3);
                a[0] = cvu(val[rowl*68 + ac]);
                a[1] = cvu(val[(rowl+8)*68 + ac]);
                a[2] = cvu(val[rowl*68 + ac + 4]);
                a[3] = cvu(val[(rowl+8)*68 + ac + 4]);
                #pragma unroll
                for (int j = 0; j < 8; ++j) {
                    int col = j*8 + (lane>>2);
                    uint32_t b0 = __float_as_uint(Ws[(k8+(lane&3))*72 + col]);
                    uint32_t b1 = __float_as_uint(Ws[(k8+(lane&3)+4)*72 + col]);
                    mma_tf32(acc[j], a, b0, b1);
                }
            }
            __syncthreads();
        }
        #pragma unroll
        for (int j = 0; j < 8; ++j) {
            int col = j*8 + (lane&3)*2;
            float bb0 = b1[col], bb1 = b1[col+1];
            f1[rowl*68 + col]       = fmaxf(acc[j][0] + bb0, 0.f);
            f1[rowl*68 + col+1]     = fmaxf(acc[j][1] + bb1, 0.f);
            f1[(rowl+8)*68 + col]   = fmaxf(acc[j][2] + bb0, 0.f);
            f1[(rowl+8)*68 + col+1] = fmaxf(acc[j][3] + bb1, 0.f);
        }
    }
    __syncthreads();

    {
        float acc[8][4];
        #pragma unroll
        for (int j=0;j<8;++j){acc[j][0]=0.f;acc[j][1]=0.f;acc[j][2]=0.f;acc[j][3]=0.f;}
        for (int kc = 0; kc < 64; kc += 32) {
            #pragma unroll
            for (int i = 0; i < 2; ++i) {
                int idx = tid + i*256;
                int krow = idx >> 4;
                int c4 = (idx & 15) * 4;
                *(float4*)&Ws[krow*72 + c4] = tf32x4(*(const float4*)&W2[(size_t)(kc+krow)*64 + c4]);
            }
            __syncthreads();
            #pragma unroll
            for (int k8 = 0; k8 < 32; k8 += 8) {
                uint32_t a[4];
                int ac = kc + k8 + (lane&3);
                a[0] = cvu(f1[rowl*68 + ac]);
                a[1] = cvu(f1[(rowl+8)*68 + ac]);
                a[2] = cvu(f1[rowl*68 + ac + 4]);
                a[3] = cvu(f1[(rowl+8)*68 + ac + 4]);
                #pragma unroll
                for (int j = 0; j < 8; ++j) {
                    int col = j*8 + (lane>>2);
                    uint32_t b0 = __float_as_uint(Ws[(k8+(lane&3))*72 + col]);
                    uint32_t b1 = __float_as_uint(Ws[(k8+(lane&3)+4)*72 + col]);
                    mma_tf32(acc[j], a, b0, b1);
                }
            }
            __syncthreads();
        }
        float xs0[16], xs1[16];
        float s0=0.f, q0=0.f, s1=0.f, q1=0.f;
        #pragma unroll
        for (int j = 0; j < 8; ++j) {
            #pragma unroll
            for (int cc = 0; cc < 2; ++cc) {
                int col = j*8 + (lane&3)*2 + cc;
                float x0 = acc[j][cc]   + b2[col] + val[rowl*68 + col];
                float x1 = acc[j][2+cc] + b2[col] + val[(rowl+8)*68 + col];
                xs0[j*2+cc] = x0; s0 += x0; q0 += x0*x0;
                xs1[j*2+cc] = x1; s1 += x1; q1 += x1*x1;
            }
        }
        s0 += __shfl_xor_sync(0xffffffffu, s0, 1); s0 += __shfl_xor_sync(0xffffffffu, s0, 2);
        q0 += __shfl_xor_sync(0xffffffffu, q0, 1); q0 += __shfl_xor_sync(0xffffffffu, q0, 2);
        s1 += __shfl_xor_sync(0xffffffffu, s1, 1); s1 += __shfl_xor_sync(0xffffffffu, s1, 2);
        q1 += __shfl_xor_sync(0xffffffffu, q1, 1); q1 += __shfl_xor_sync(0xffffffffu, q1, 2);
        float mu0 = s0*(1.f/64.f), rstd0 = rsqrtf(q0*(1.f/64.f) - mu0*mu0 + 1e-5f);
        float mu1 = s1*(1.f/64.f), rstd1 = rsqrtf(q1*(1.f/64.f) - mu1*mu1 + 1e-5f);
        float y0 = 0.f, y1 = 0.f;
        #pragma unroll
        for (int j = 0; j < 8; ++j) {
            #pragma unroll
            for (int cc = 0; cc < 2; ++cc) {
                int col = j*8 + (lane&3)*2 + cc;
                float g = ln2g[col], be = ln2b[col], fw = fcW[col];
                y0 += ((xs0[j*2+cc] - mu0)*rstd0*g + be) * fw;
                y1 += ((xs1[j*2+cc] - mu1)*rstd1*g + be) * fw;
            }
        }
        y0 += __shfl_xor_sync(0xffffffffu, y0, 1); y0 += __shfl_xor_sync(0xffffffffu, y0, 2);
        y1 += __shfl_xor_sync(0xffffffffu, y1, 1); y1 += __shfl_xor_sync(0xffffffffu, y1, 2);
        if ((lane & 3) == 0) {
            float fb = fcb[0];
            y[r0 + rowl]     = y0 + fb;
            y[r0 + rowl + 8] = y1 + fb;
        }
    }
}

// ---------------- host ----------------
extern "C" void kernel_launch(void* const* d_in, const int* in_sizes, int n_in,
                              void* d_out, int out_size) {
    const float* src  = (const float*)d_in[0];
    const float* emb  = (const float*)d_in[2];
    const float* gwp0 = (const float*)d_in[3];
    const float* gbp0 = (const float*)d_in[4];
    const float* uwp0 = (const float*)d_in[5];
    const float* ubp0 = (const float*)d_in[6];
    const float* gwp1 = (const float*)d_in[7];
    const float* gbp1 = (const float*)d_in[8];
    const float* uwp1 = (const float*)d_in[9];
    const float* ubp1 = (const float*)d_in[10];
    const float* hypW = (const float*)d_in[11];
    const float* hypb = (const float*)d_in[12];

    const float *Wq,*Wk,*Wv,*ffW1,*ffW2,*bq,*bk,*bv,*ffb1,*ffb2,*ln1g,*ln1b,*ln2g,*ln2b,*fcW,*fcb;
    if (n_in > 14 && in_sizes[14] == 64) {
        Wq  = (const float*)d_in[13]; bq  = (const float*)d_in[14];
        Wk  = (const float*)d_in[15]; bk  = (const float*)d_in[16];
        Wv  = (const float*)d_in[17]; bv  = (const float*)d_in[18];
        ln1g= (const float*)d_in[19]; ln1b= (const float*)d_in[20];
        ffW1= (const float*)d_in[21]; ffb1= (const float*)d_in[22];
        ffW2= (const float*)d_in[23]; ffb2= (const float*)d_in[24];
        ln2g= (const float*)d_in[25]; ln2b= (const float*)d_in[26];
        fcW = (const float*)d_in[27]; fcb = (const float*)d_in[28];
    } else {
        Wq  = (const float*)d_in[13]; Wk  = (const float*)d_in[14];
        Wv  = (const float*)d_in[15]; ffW1= (const float*)d_in[16];
        ffW2= (const float*)d_in[17]; bq  = (const float*)d_in[18];
        bk  = (const float*)d_in[19]; bv  = (const float*)d_in[20];
        ffb1= (const float*)d_in[21]; ffb2= (const float*)d_in[22];
        ln1g= (const float*)d_in[23]; ln1b= (const float*)d_in[24];
        ln2g= (const float*)d_in[25]; ln2b= (const float*)d_in[26];
        fcW = (const float*)d_in[27]; fcb = (const float*)d_in[28];
    }

    float *p_gW,*p_gb,*p_uW,*p_ub,*p_cg,*p_cu,*p_mxt,*p_xt0t;
    float *p_hs0,*p_hs1,*p_hv,*p_q,*p_k,*p_v,*p_o;
    cudaGetSymbolAddress((void**)&p_gW, g_gW);
    cudaGetSymbolAddress((void**)&p_gb, g_gb);
    cudaGetSymbolAddress((void**)&p_uW, g_uW);
    cudaGetSymbolAddress((void**)&p_ub, g_ub);
    cudaGetSymbolAddress((void**)&p_cg, g_cg);
    cudaGetSymbolAddress((void**)&p_cu, g_cu);
    cudaGetSymbolAddress((void**)&p_mxt, g_mxt);
    cudaGetSymbolAddress((void**)&p_xt0t, g_xt0t);
    cudaGetSymbolAddress((void**)&p_hs0, g_hs0);
    cudaGetSymbolAddress((void**)&p_hs1, g_hs1);
    cudaGetSymbolAddress((void**)&p_hv, g_hv);
    cudaGetSymbolAddress((void**)&p_q, g_q);
    cudaGetSymbolAddress((void**)&p_k, g_k);
    cudaGetSymbolAddress((void**)&p_v, g_v);
    cudaGetSymbolAddress((void**)&p_o, g_o);

    cudaFuncSetAttribute(k_recur, cudaFuncAttributeMaxDynamicSharedMemorySize, RECUR_SMEM);
    cudaFuncSetAttribute(k_tail, cudaFuncAttributeMaxDynamicSharedMemorySize, TAIL_SMEM);

    for (int layer = 0; layer < 2; ++layer) {
        int Cin = (layer == 0) ? 2 : 64;
        int C = Cin + HH;
        int SgW4 = 2*C*128/4, SuW4 = 2*C*64/4;
        int work = NN*(SgW4 + 32 + SuW4 + 16) + ((layer == 0) ? ZT*NN*2 : 0);
        int grid = NN + (work + 255)/256;
        float* hs_out;
        float* hv_out;
        if (layer == 0) {
            k_fused_pre<<<grid, 256>>>(emb, gwp0, gbp0, uwp0, ubp0,
                                       p_gW, p_gb, p_uW, p_ub, SgW4, SuW4,
                                       src, p_xt0t, 1);
            k_mix64<<<dim3(8, (ZT*2)/64), 256>>>(p_xt0t, p_mxt);
            k_precomp<<<dim3(NN, 6), 192>>>(src, p_mxt, p_gW, p_uW, p_gb, p_ub, p_cg, p_cu, Cin);
            hs_out = p_hs0; hv_out = nullptr;
        } else {
            k_fused_pre<<<grid, 256>>>(emb, gwp1, gbp1, uwp1, ubp1,
                                       p_gW, p_gb, p_uW, p_ub, SgW4, SuW4,
                                       nullptr, nullptr, 0);
            k_mix64<<<dim3(8, ZT), 256>>>(p_hs0, p_mxt);
            k_precomp_mma<<<dim3(NN, 3), 256>>>(p_hs0, p_mxt, p_gW, p_uW, p_gb, p_ub, p_cg, p_cu);
            hs_out = p_hs1; hv_out = p_hv;
        }
        unsigned nbar0 = (layer == 0) ? 0u : 45u;
        k_recur<<<GRID_P, 256, RECUR_SMEM>>>(p_gW, p_uW, p_cg, p_cu, hs_out, C, Cin, nbar0, hv_out);
    }

    k_hyp_mma<<<dim3(4, 16), 256>>>(hypW);
    k_hyp_fin<<<(NN*TT + 255)/256, 256>>>(hypb);

    k_gemm64_mma<<<BTN/128, 256>>>(p_hs1, Wq, bq, p_q, 0);
    k_gemm64_mma<<<BTN/128, 256>>>(p_hs1, Wk, bk, p_k, 0);
    k_gemm64_mma<<<BB*NN/128, 256>>>(p_hv, Wv, nullptr, p_v, 0);

    k_attn<<<BB*NN, 128>>>(bv);

    k_tail<<<BTN/128, 256, TAIL_SMEM>>>(p_o, p_hs1, ln1g, ln1b,
                                        ffW1, ffb1, ffW2, ffb2,
                                        ln2g, ln2b, fcW, fcb, (float*)d_out);
}

// round 15
// speedup vs baseline: 1.1146x; 1.1146x over previous
#include <cuda_runtime.h>
#include <cuda_fp16.h>
#include <math.h>
#include <stdint.h>

#define BB 32
#define TT 12
#define NN 512
#define HH 64
#define EE 16
#define BTN (BB*TT*NN)
#define BTNH (BTN*HH)
#define ZT (BB*TT)
#define GRID_P 256
#define RECUR_SMEM 26112
#define TAIL_SMEM  78848

__device__ float g_adj[NN*NN];
__device__ __half g_adjh[NN*NN];
__device__ float g_gW[NN*2*128*128];
__device__ __half g_gWh[NN*2*128*128];
__device__ float g_gb[NN*128];
__device__ float g_uW[NN*2*128*64];
__device__ __half g_uWh[NN*2*128*64];
__device__ float g_ub[NN*64];
__device__ float g_state[BB*NN*HH];
__device__ __half g_sh[BB*NN*HH];
__device__ __half g_zsh[BB*NN*HH];
__device__ __half g_mixsh[BB*NN*HH];
__device__ __half g_mixzsh[BB*NN*HH];
__device__ float g_r[BB*NN*HH];
__device__ float g_cg[TT*BB*NN*128];
__device__ float g_cu[TT*BB*NN*64];
__device__ float g_mxt[ZT*NN*64];
__device__ float g_xt0t[TT*NN*64];
__device__ float g_hs0[BTNH];
__device__ float g_hs1[BTNH];
__device__ float g_fs[NN*TT];
__device__ float g_hlin[NN*48];
__device__ float g_hv[BB*NN*HH];
__device__ float g_q[BTNH];
__device__ float g_k[BTNH];
__device__ float g_v[BB*NN*HH];
__device__ float g_o[BTNH];
__device__ unsigned g_bar;

__device__ __forceinline__ float to_tf32(float x) {
    uint32_t u; asm("cvt.rna.tf32.f32 %0, %1;" : "=r"(u) : "f"(x));
    return __uint_as_float(u);
}
__device__ __forceinline__ uint32_t cvu(float x) {
    uint32_t u; asm("cvt.rna.tf32.f32 %0, %1;" : "=r"(u) : "f"(x));
    return u;
}
__device__ __forceinline__ float4 tf32x4(float4 v) {
    float4 w; w.x=to_tf32(v.x); w.y=to_tf32(v.y); w.z=to_tf32(v.z); w.w=to_tf32(v.w);
    return w;
}
__device__ __forceinline__ void mma_tf32(float* c, const uint32_t* a, uint32_t b0, uint32_t b1) {
    asm volatile("mma.sync.aligned.m16n8k8.row.col.f32.tf32.tf32.f32 "
        "{%0,%1,%2,%3}, {%4,%5,%6,%7}, {%8,%9}, {%0,%1,%2,%3};"
        : "+f"(c[0]), "+f"(c[1]), "+f"(c[2]), "+f"(c[3])
        : "r"(a[0]), "r"(a[1]), "r"(a[2]), "r"(a[3]), "r"(b0), "r"(b1));
}
__device__ __forceinline__ void mma_f16(float* c, const uint32_t* a, uint32_t b0, uint32_t b1) {
    asm volatile("mma.sync.aligned.m16n8k16.row.col.f32.f16.f16.f32 "
        "{%0,%1,%2,%3}, {%4,%5,%6,%7}, {%8,%9}, {%0,%1,%2,%3};"
        : "+f"(c[0]), "+f"(c[1]), "+f"(c[2]), "+f"(c[3])
        : "r"(a[0]), "r"(a[1]), "r"(a[2]), "r"(a[3]), "r"(b0), "r"(b1));
}
__device__ __forceinline__ void ldsm4(uint32_t& r0, uint32_t& r1, uint32_t& r2, uint32_t& r3, uint32_t addr) {
    asm volatile("ldmatrix.sync.aligned.m8n8.x4.shared.b16 {%0,%1,%2,%3}, [%4];"
        : "=r"(r0), "=r"(r1), "=r"(r2), "=r"(r3) : "r"(addr));
}
__device__ __forceinline__ void ldsm4t(uint32_t& r0, uint32_t& r1, uint32_t& r2, uint32_t& r3, uint32_t addr) {
    asm volatile("ldmatrix.sync.aligned.m8n8.x4.trans.shared.b16 {%0,%1,%2,%3}, [%4];"
        : "=r"(r0), "=r"(r1), "=r"(r2), "=r"(r3) : "r"(addr));
}
__device__ __forceinline__ float sigm(float v) { return 1.f / (1.f + __expf(-v)); }
__device__ __forceinline__ float tanhfast(float v) { return 1.f - 2.f / (__expf(2.f*v) + 1.f); }

__device__ __forceinline__ void gbar(unsigned n) {
    __syncthreads();
    if (threadIdx.x == 0) {
        __threadfence();
        atomicAdd(&g_bar, 1u);
        unsigned target = n * GRID_P;
        volatile unsigned* p = &g_bar;
        while (*p < target) __nanosleep(64);
        __threadfence();
    }
    __syncthreads();
}

// ---------------- fused pre-kernel ----------------
__global__ void k_fused_pre(const float* __restrict__ emb,
                            const float* __restrict__ gwp, const float* __restrict__ gbp,
                            const float* __restrict__ uwp, const float* __restrict__ ubp,
                            float* __restrict__ gW, float* __restrict__ gb,
                            float* __restrict__ uW, float* __restrict__ ub,
                            __half* __restrict__ gWh, __half* __restrict__ uWh,
                            int SgW4, int SuW4,
                            const float* __restrict__ src, float* __restrict__ xt0,
                            int do_adj) {
    __shared__ float semb[NN*EE];
    __shared__ float row[NN];
    __shared__ float red[256];
    if (blockIdx.x < NN) {
        if (!do_adj) return;
        if (blockIdx.x == 0 && threadIdx.x == 0) g_bar = 0u;
        for (int i = blockIdx.x*256 + threadIdx.x; i < NN*48; i += NN*256) g_hlin[i] = 0.f;
        int n = blockIdx.x;
        for (int i = threadIdx.x; i < NN*EE; i += 256) semb[i] = emb[i];
        __syncthreads();
        float lmax = -1e30f;
        for (int m = threadIdx.x; m < NN; m += 256) {
            float s = 0.f;
            #pragma unroll
            for (int e = 0; e < EE; ++e) s += semb[n*EE+e] * semb[m*EE+e];
            s = fmaxf(s, 0.f);
            row[m] = s;
            lmax = fmaxf(lmax, s);
        }
        red[threadIdx.x] = lmax; __syncthreads();
        for (int s = 128; s > 0; s >>= 1) {
            if (threadIdx.x < s) red[threadIdx.x] = fmaxf(red[threadIdx.x], red[threadIdx.x+s]);
            __syncthreads();
        }
        float mx = red[0];
        __syncthreads();
        float lsum = 0.f;
        for (int m = threadIdx.x; m < NN; m += 256) {
            float v = expf(row[m] - mx);
            row[m] = v; lsum += v;
        }
        red[threadIdx.x] = lsum; __syncthreads();
        for (int s = 128; s > 0; s >>= 1) {
            if (threadIdx.x < s) red[threadIdx.x] += red[threadIdx.x+s];
            __syncthreads();
        }
        float inv = 1.f / red[0];
        for (int m = threadIdx.x; m < NN; m += 256) {
            float a = row[m] * inv;
            g_adj[n*NN + m] = to_tf32(a);
            g_adjh[n*NN + m] = __float2half_rn(a);
        }
        return;
    }
    int idx = (blockIdx.x - NN)*256 + threadIdx.x;
    int t0 = NN*SgW4, t1 = t0 + NN*32, t2 = t1 + NN*SuW4, t3 = t2 + NN*16;
    if (idx < t3) {
        const float* pool; float* out; __half* outh; int S4, local, rnd;
        if (idx < t0)      { pool = gwp; out = gW; outh = gWh; S4 = SgW4; local = idx;      rnd = 1; }
        else if (idx < t1) { pool = gbp; out = gb; outh = 0;   S4 = 32;   local = idx - t0; rnd = 0; }
        else if (idx < t2) { pool = uwp; out = uW; outh = uWh; S4 = SuW4; local = idx - t1; rnd = 1; }
        else               { pool = ubp; out = ub; outh = 0;   S4 = 16;   local = idx - t2; rnd = 0; }
        int n = local / S4, i = local - n*S4;
        float4 a = make_float4(0.f,0.f,0.f,0.f);
        const float* e = emb + n*EE;
        const float4* p4 = (const float4*)pool;
        #pragma unroll
        for (int k = 0; k < EE; ++k) {
            float w = e[k];
            float4 p = p4[(size_t)k*S4 + i];
            a.x += w*p.x; a.y += w*p.y; a.z += w*p.z; a.w += w*p.w;
        }
        if (rnd) {
            ((__half2*)outh)[local*2]   = __floats2half2_rn(a.x, a.y);
            ((__half2*)outh)[local*2+1] = __floats2half2_rn(a.z, a.w);
            a = tf32x4(a);
        }
        ((float4*)out)[local] = a;
    } else if (src) {
        int t = idx - t3;
        if (t < ZT*NN*2) {
            int c = t & 1, m = (t >> 1) & 511, z = t >> 10;
            int g = z*2 + c;
            xt0[((size_t)(g>>6)*NN + m)*64 + (g&63)] = src[t];
        }
    }
}

// ---------------- fp32 tf32 mix tile (premix only) ----------------
__device__ __forceinline__ void mix_tile(const float* __restrict__ X, float* __restrict__ Y,
                                         float* sm, int tid, int z, int r0) {
    int warp = tid >> 5, lane = tid & 31;
    int wm = warp >> 1, wn = warp & 1;
    const float* Xb = X + (size_t)z * (NN*64);
    float* Yb = Y + (size_t)z * (NN*64);
    float acc[4][4];
    #pragma unroll
    for (int j=0;j<4;++j){acc[j][0]=0.f;acc[j][1]=0.f;acc[j][2]=0.f;acc[j][3]=0.f;}
    float4 ar0, ar1, xr0, xr1;
    int i0 = tid, i1 = tid + 256;
    ar0 = *(const float4*)&g_adj[(size_t)(r0 + (i0>>3))*NN + (i0&7)*4];
    ar1 = *(const float4*)&g_adj[(size_t)(r0 + (i1>>3))*NN + (i1&7)*4];
    xr0 = *(const float4*)&Xb[(size_t)(i0>>4)*64 + (i0&15)*4];
    xr1 = *(const float4*)&Xb[(size_t)(i1>>4)*64 + (i1&15)*4];
    {
        float* As = sm; float* Xs = sm + 4608;
        *(float4*)&As[(i0>>3)*36 + (i0&7)*4] = ar0;
        *(float4*)&As[(i1>>3)*36 + (i1&7)*4] = ar1;
        *(float4*)&Xs[(i0>>4)*72 + (i0&15)*4] = tf32x4(xr0);
        *(float4*)&Xs[(i1>>4)*72 + (i1&15)*4] = tf32x4(xr1);
    }
    for (int c = 0; c < 16; ++c) {
        __syncthreads();
        if (c < 15) {
            int kc = (c+1)*32;
            ar0 = *(const float4*)&g_adj[(size_t)(r0 + (i0>>3))*NN + kc + (i0&7)*4];
            ar1 = *(const float4*)&g_adj[(size_t)(r0 + (i1>>3))*NN + kc + (i1&7)*4];
            xr0 = *(const float4*)&Xb[(size_t)(kc + (i0>>4))*64 + (i0&15)*4];
            xr1 = *(const float4*)&Xb[(size_t)(kc + (i1>>4))*64 + (i1&15)*4];
        }
        float* As = sm + (c&1)*2304;
        float* Xs = sm + 4608 + (c&1)*2304;
        #pragma unroll
        for (int k8 = 0; k8 < 32; k8 += 8) {
            uint32_t a[4];
            int arow = wm*16 + (lane>>2);
            int ac = k8 + (lane&3);
            a[0] = __float_as_uint(As[arow*36 + ac]);
            a[1] = __float_as_uint(As[(arow+8)*36 + ac]);
            a[2] = __float_as_uint(As[arow*36 + ac + 4]);
            a[3] = __float_as_uint(As[(arow+8)*36 + ac + 4]);
            #pragma unroll
            for (int j = 0; j < 4; ++j) {
                int col = wn*32 + j*8 + (lane>>2);
                uint32_t b0 = __float_as_uint(Xs[(k8+(lane&3))*72 + col]);
                uint32_t b1 = __float_as_uint(Xs[(k8+(lane&3)+4)*72 + col]);
                mma_tf32(acc[j], a, b0, b1);
            }
        }
        if (c < 15) {
            float* Asn = sm + ((c+1)&1)*2304;
            float* Xsn = sm + 4608 + ((c+1)&1)*2304;
            *(float4*)&Asn[(i0>>3)*36 + (i0&7)*4] = ar0;
            *(float4*)&Asn[(i1>>3)*36 + (i1&7)*4] = ar1;
            *(float4*)&Xsn[(i0>>4)*72 + (i0&15)*4] = tf32x4(xr0);
            *(float4*)&Xsn[(i1>>4)*72 + (i1&15)*4] = tf32x4(xr1);
        }
    }
    int row = r0 + wm*16 + (lane>>2);
    #pragma unroll
    for (int j = 0; j < 4; ++j) {
        int col = wn*32 + j*8 + (lane&3)*2;
        *(float2*)&Yb[(size_t)row*64 + col] = make_float2(acc[j][0], acc[j][1]);
        *(float2*)&Yb[(size_t)(row+8)*64 + col] = make_float2(acc[j][2], acc[j][3]);
    }
}

__global__ void __launch_bounds__(256) k_mix64(const float* __restrict__ X, float* __restrict__ Y) {
    __shared__ float sm[9216];
    mix_tile(X, Y, sm, threadIdx.x, blockIdx.y, blockIdx.x*64);
}

// ---------------- fp16 ldmatrix mix tile (recurrence; half output) ----------------
// smem bytes: A0@0 (64x40h=5120), A1@5120, X0@10240 (32x72h=4608), X1@14848
__device__ __forceinline__ void mix16(const __half* __restrict__ Xh, __half* __restrict__ Yh,
                                      float* smf, int tid, int z, int r0) {
    char* smb = (char*)smf;
    uint32_t sb = (uint32_t)__cvta_generic_to_shared(smb);
    int warp = tid >> 5, lane = tid & 31;
    int wm = warp >> 1, wn = warp & 1;
    const __half* Xz = Xh + (size_t)z * (NN*64);
    __half* Yb = Yh + (size_t)z * (NN*64);
    float acc[4][4];
    #pragma unroll
    for (int j=0;j<4;++j){acc[j][0]=0.f;acc[j][1]=0.f;acc[j][2]=0.f;acc[j][3]=0.f;}
    int arow = tid >> 2, acolh = (tid & 3) * 8;
    int xrow = tid >> 3, xcolh = (tid & 7) * 8;
    uint4 av = *(const uint4*)&g_adjh[(size_t)(r0 + arow)*NN + acolh];
    uint4 xv = *(const uint4*)&Xz[(size_t)xrow*64 + xcolh];
    *(uint4*)(smb + arow*80 + (tid&3)*16) = av;
    *(uint4*)(smb + 10240 + xrow*144 + (tid&7)*16) = xv;
    uint32_t a_l = (wm*16 + (lane & 15)) * 80 + ((lane >> 4) * 8) * 2;
    uint32_t xk_l = (lane & 7) + ((lane >> 3) & 1) * 8;
    uint32_t xn_l = (lane >> 4) * 8;
    for (int c = 0; c < 16; ++c) {
        __syncthreads();
        if (c < 15) {
            int kc = (c+1)*32;
            av = *(const uint4*)&g_adjh[(size_t)(r0 + arow)*NN + kc + acolh];
            xv = *(const uint4*)&Xz[(size_t)(kc + xrow)*64 + xcolh];
        }
        uint32_t ab = sb + (c&1)*5120;
        uint32_t xb = sb + 10240 + (c&1)*4608;
        #pragma unroll
        for (int kb = 0; kb < 2; ++kb) {
            uint32_t a[4];
            ldsm4(a[0], a[1], a[2], a[3], ab + a_l + kb*32);
            #pragma unroll
            for (int cg = 0; cg < 2; ++cg) {
                int c0 = wn*32 + cg*16;
                uint32_t b0, b1, b2, b3;
                ldsm4t(b0, b1, b2, b3, xb + (kb*16 + xk_l)*144 + (c0 + xn_l)*2);
                mma_f16(acc[cg*2+0], a, b0, b1);
                mma_f16(acc[cg*2+1], a, b2, b3);
            }
        }
        if (c < 15) {
            *(uint4*)(smb + ((c+1)&1)*5120 + arow*80 + (tid&3)*16) = av;
            *(uint4*)(smb + 10240 + ((c+1)&1)*4608 + xrow*144 + (tid&7)*16) = xv;
        }
    }
    int row = r0 + wm*16 + (lane>>2);
    #pragma unroll
    for (int j = 0; j < 4; ++j) {
        int col = wn*32 + j*8 + (lane&3)*2;
        *(__half2*)&Yb[(size_t)row*64 + col] = __floats2half2_rn(acc[j][0], acc[j][1]);
        *(__half2*)&Yb[(size_t)(row+8)*64 + col] = __floats2half2_rn(acc[j][2], acc[j][3]);
    }
}

// ---------------- fp16 gate phase ----------------
// smem bytes: Ah @0 (32x136h=8704), Bs0 @8704 (32x136h=8704), Bs1 @17408
__device__ __forceinline__ void phase_gate(const __half* __restrict__ gWh, const float* __restrict__ cg_t,
                                           int C, int Cin, float* smf, int tid) {
    char* smb = (char*)smf;
    uint32_t sb = (uint32_t)__cvta_generic_to_shared(smb);
    int warp = tid >> 5, lane = tid & 31;
    int wm = warp >> 2, wn = warp & 3;
    uint32_t a_l = (wm*16 + (lane & 15)) * 272 + ((lane >> 4) * 8) * 2;
    uint32_t xk_l = (lane & 7) + ((lane >> 3) & 1) * 8;
    uint32_t xn_l = (lane >> 4) * 8;
    for (int n = blockIdx.x; n < NN; n += GRID_P) {
        __syncthreads();
        #pragma unroll
        for (int i = 0; i < 2; ++i) {
            int idx = tid + i*256;
            int row = idx >> 4, h8 = idx & 15;
            uint4 v = (h8 < 8)
                ? *(const uint4*)&g_sh[((size_t)row*NN + n)*64 + h8*8]
                : *(const uint4*)&g_mixsh[((size_t)row*NN + n)*64 + (h8-8)*8];
            *(uint4*)(smb + row*272 + h8*16) = v;
        }
        #pragma unroll
        for (int i = 0; i < 2; ++i) {
            int idx = tid + i*256;
            int kk = idx >> 4, h8 = idx & 15;
            *(uint4*)(smb + 8704 + kk*272 + h8*16) =
                *(const uint4*)&gWh[((size_t)(2*n)*C + Cin + kk)*128 + h8*8];
        }
        float acc[4][4];
        #pragma unroll
        for (int j=0;j<4;++j){acc[j][0]=0.f;acc[j][1]=0.f;acc[j][2]=0.f;acc[j][3]=0.f;}
        uint4 bv[2];
        for (int c = 0; c < 4; ++c) {
            __syncthreads();
            if (c < 3) {
                #pragma unroll
                for (int i = 0; i < 2; ++i) {
                    int idx = tid + i*256;
                    int kk = idx >> 4, h8 = idx & 15;
                    int kg = (c+1)*32 + kk;
                    bv[i] = *(const uint4*)&gWh[((size_t)(2*n + (kg>=64))*C + Cin + (kg&63))*128 + h8*8];
                }
            }
            uint32_t bbase = sb + 8704 + (c&1)*8704;
            #pragma unroll
            for (int kb = 0; kb < 2; ++kb) {
                int kg16 = c*32 + kb*16;
                uint32_t a[4];
                ldsm4(a[0], a[1], a[2], a[3], sb + a_l + kg16*2);
                #pragma unroll
                for (int cg = 0; cg < 2; ++cg) {
                    int c0 = wn*32 + cg*16;
                    uint32_t b0, b1, b2, b3;
                    ldsm4t(b0, b1, b2, b3, bbase + (kb*16 + xk_l)*272 + (c0 + xn_l)*2);
                    mma_f16(acc[cg*2+0], a, b0, b1);
                    mma_f16(acc[cg*2+1], a, b2, b3);
                }
            }
            if (c < 3) {
                char* Bsn = smb + 8704 + ((c+1)&1)*8704;
                #pragma unroll
                for (int i = 0; i < 2; ++i) {
                    int idx = tid + i*256;
                    int kk = idx >> 4, h8 = idx & 15;
                    *(uint4*)(Bsn + kk*272 + h8*16) = bv[i];
                }
            }
        }
        const __half* Ah = (const __half*)smb;
        #pragma unroll
        for (int j = 0; j < 4; ++j) {
            int col = wn*32 + j*8 + (lane&3)*2;
            #pragma unroll
            for (int half = 0; half < 2; ++half) {
                int b = wm*16 + (lane>>2) + half*8;
                float v0 = acc[j][half*2], v1 = acc[j][half*2+1];
                size_t base = (size_t)b*NN + n;
                float2 cgv = *(const float2*)&cg_t[base*128 + col];
                v0 += cgv.x; v1 += cgv.y;
                if (col < 64) {
                    float s0 = __half2float(Ah[b*136 + col]);
                    float s1 = __half2float(Ah[b*136 + col + 1]);
                    *(__half2*)&g_zsh[base*64 + col] =
                        __floats2half2_rn(sigm(v0) * s0, sigm(v1) * s1);
                } else {
                    *(float2*)&g_r[base*64 + col - 64] = make_float2(sigm(v0), sigm(v1));
                }
            }
        }
    }
}

// ---------------- fp16 upd phase ----------------
// smem bytes: Ah @0 (32x136h=8704), Bs0 @8704 (32x72h=4608), Bs1 @13312
__device__ __forceinline__ void phase_upd(const __half* __restrict__ uWh, const float* __restrict__ cu_t,
                                          int C, int Cin, float* __restrict__ hs, int t,
                                          float* smf, int tid, float* __restrict__ hv) {
    char* smb = (char*)smf;
    uint32_t sb = (uint32_t)__cvta_generic_to_shared(smb);
    int warp = tid >> 5, lane = tid & 31;
    int wm = warp >> 2, wn = warp & 3;
    uint32_t a_l = (wm*16 + (lane & 15)) * 272 + ((lane >> 4) * 8) * 2;
    uint32_t xk_l = (lane & 7) + ((lane >> 3) & 1) * 8;
    uint32_t xn_l = (lane >> 4) * 8;
    for (int n = blockIdx.x; n < NN; n += GRID_P) {
        __syncthreads();
        #pragma unroll
        for (int i = 0; i < 2; ++i) {
            int idx = tid + i*256;
            int row = idx >> 4, h8 = idx & 15;
            uint4 v = (h8 < 8)
                ? *(const uint4*)&g_zsh[((size_t)row*NN + n)*64 + h8*8]
                : *(const uint4*)&g_mixzsh[((size_t)row*NN + n)*64 + (h8-8)*8];
            *(uint4*)(smb + row*272 + h8*16) = v;
        }
        {
            int kk = tid >> 3, h8 = tid & 7;
            *(uint4*)(smb + 8704 + kk*144 + h8*16) =
                *(const uint4*)&uWh[((size_t)(2*n)*C + Cin + kk)*64 + h8*8];
        }
        float acc[2][4];
        #pragma unroll
        for (int j=0;j<2;++j){acc[j][0]=0.f;acc[j][1]=0.f;acc[j][2]=0.f;acc[j][3]=0.f;}
        uint4 bv;
        for (int c = 0; c < 4; ++c) {
            __syncthreads();
            if (c < 3) {
                int kk = tid >> 3, h8 = tid & 7;
                int kg = (c+1)*32 + kk;
                bv = *(const uint4*)&uWh[((size_t)(2*n + (kg>=64))*C + Cin + (kg&63))*64 + h8*8];
            }
            uint32_t bbase = sb + 8704 + (c&1)*4608;
            #pragma unroll
            for (int kb = 0; kb < 2; ++kb) {
                int kg16 = c*32 + kb*16;
                uint32_t a[4];
                ldsm4(a[0], a[1], a[2], a[3], sb + a_l + kg16*2);
                uint32_t b0, b1, b2, b3;
                ldsm4t(b0, b1, b2, b3, bbase + (kb*16 + xk_l)*144 + (wn*16 + xn_l)*2);
                mma_f16(acc[0], a, b0, b1);
                mma_f16(acc[1], a, b2, b3);
            }
            if (c < 3) {
                int kk = tid >> 3, h8 = tid & 7;
                *(uint4*)(smb + 8704 + ((c+1)&1)*4608 + kk*144 + h8*16) = bv;
            }
        }
        #pragma unroll
        for (int j = 0; j < 2; ++j) {
            int col = wn*16 + j*8 + (lane&3)*2;
            #pragma unroll
            for (int half = 0; half < 2; ++half) {
                int b = wm*16 + (lane>>2) + half*8;
                float v0 = acc[j][half*2], v1 = acc[j][half*2+1];
                size_t base = (size_t)b*NN + n;
                float2 cuv = *(const float2*)&cu_t[base*64 + col];
                float hc0 = tanhfast(v0 + cuv.x), hc1 = tanhfast(v1 + cuv.y);
                size_t idx = base*64 + col;
                float2 rr = *(const float2*)&g_r[idx];
                float2 st = *(const float2*)&g_state[idx];
                float h0 = rr.x*st.x + (1.f-rr.x)*hc0;
                float h1 = rr.y*st.y + (1.f-rr.y)*hc1;
                *(float2*)&g_state[idx] = make_float2(h0, h1);
                *(__half2*)&g_sh[idx] = __floats2half2_rn(h0, h1);
                *(float2*)&hs[(((size_t)b*TT + t)*NN + n)*64 + col] = make_float2(h0, h1);
                if (hv && t == TT-1)
                    *(float2*)&hv[idx] = make_float2(h0, h1);
            }
        }
    }
}

__global__ void __launch_bounds__(256, 2) k_recur(
        const __half* __restrict__ gWh, const __half* __restrict__ uWh,
        const float* __restrict__ cg, const float* __restrict__ cu,
        float* __restrict__ hs, int C, int Cin, unsigned nbar,
        float* __restrict__ hv) {
    extern __shared__ float sm[];
    int tid = threadIdx.x;
    for (int idx = blockIdx.x*256 + tid; idx < BB*NN*64; idx += GRID_P*256) {
        int c = idx & 63;
        int n = (idx >> 6) & 511;
        int b = idx >> 15;
        size_t base = (size_t)b*NN + n;
        float r = sigm(cg[base*128 + 64 + c]);
        float hc = tanhfast(cu[base*64 + c]);
        float h = (1.f - r) * hc;
        g_state[base*64 + c] = h;
        g_sh[base*64 + c] = __float2half_rn(h);
        hs[(((size_t)b*TT)*NN + n)*64 + c] = h;
    }
    gbar(++nbar);
    int z = blockIdx.x >> 3;
    int r0 = (blockIdx.x & 7) * 64;
    for (int t = 1; t < TT; ++t) {
        const float* cg_t = cg + (size_t)t*BB*NN*128;
        const float* cu_t = cu + (size_t)t*BB*NN*64;
        mix16(g_sh, g_mixsh, sm, tid, z, r0);
        gbar(++nbar);
        phase_gate(gWh, cg_t, C, Cin, sm, tid);
        gbar(++nbar);
        mix16(g_zsh, g_mixzsh, sm, tid, z, r0);
        gbar(++nbar);
        phase_upd(uWh, cu_t, C, Cin, hs, t, sm, tid, hv);
        gbar(++nbar);
    }
}

// ---------------- precompute ----------------
__global__ void __launch_bounds__(192) k_precomp(
        const float* __restrict__ xt, const float* __restrict__ mxt,
        const float* __restrict__ gW, const float* __restrict__ uW,
        const float* __restrict__ gb, const float* __restrict__ ub,
        float* __restrict__ cg, float* __restrict__ cu, int Cin) {
    const int C = Cin + HH;
    __shared__ float xs[64][2];
    __shared__ float ms[64][2];
    int n = blockIdx.x;
    int r0 = blockIdx.y * 64;
    int tid = threadIdx.x;
    for (int idx = tid; idx < 64*Cin; idx += 192) {
        int r = idx / Cin, c = idx - r*Cin;
        int z = r0 + r;
        xs[r][c] = xt[((size_t)z*NN + n)*Cin + c];
        int g = z*Cin + c;
        ms[r][c] = mxt[((size_t)(g>>6)*NN + n)*64 + (g&63)];
    }
    __syncthreads();
    float a[64];
    #pragma unroll
    for (int i = 0; i < 64; ++i) a[i] = 0.f;
    if (tid < 128) {
        int o = tid;
        const float* W0 = gW + (size_t)(n*2)*C*128 + o;
        const float* W1 = gW + (size_t)(n*2+1)*C*128 + o;
        for (int c = 0; c < Cin; ++c) {
            float w0 = W0[c*128], w1 = W1[c*128];
            #pragma unroll
            for (int r = 0; r < 64; ++r) a[r] += xs[r][c]*w0 + ms[r][c]*w1;
        }
        float bias = gb[n*128 + o];
        for (int r = 0; r < 64; ++r) {
            int z = r0 + r; int b = z / 12, t = z - b*12;
            cg[(((size_t)t*BB + b)*NN + n)*128 + o] = a[r] + bias;
        }
    } else {
        int o = tid - 128;
        const float* W0 = uW + (size_t)(n*2)*C*64 + o;
        const float* W1 = uW + (size_t)(n*2+1)*C*64 + o;
        for (int c = 0; c < Cin; ++c) {
            float w0 = W0[c*64], w1 = W1[c*64];
            #pragma unroll
            for (int r = 0; r < 64; ++r) a[r] += xs[r][c]*w0 + ms[r][c]*w1;
        }
        float bias = ub[n*64 + o];
        for (int r = 0; r < 64; ++r) {
            int z = r0 + r; int b = z / 12, t = z - b*12;
            cu[(((size_t)t*BB + b)*NN + n)*64 + o] = a[r] + bias;
        }
    }
}

__global__ void __launch_bounds__(256) k_precomp_mma(
        const float* __restrict__ xt, const float* __restrict__ mxt,
        const float* __restrict__ gW, const float* __restrict__ uW,
        const float* __restrict__ gb, const float* __restrict__ ub,
        float* __restrict__ cg, float* __restrict__ cu) {
    const int C = 128;
    __shared__ float As[128][36];
    __shared__ float Bs[32][200];
    int n = blockIdx.x;
    int m0 = blockIdx.y * 128;
    int tid = threadIdx.x;
    int warp = tid >> 5, lane = tid & 31;
    int wm = warp >> 1, wn = warp & 1;
    float acc[2][12][4];
    #pragma unroll
    for (int mt=0;mt<2;++mt) for (int j=0;j<12;++j) for (int q=0;q<4;++q) acc[mt][j][q]=0.f;
    for (int kc = 0; kc < 128; kc += 32) {
        #pragma unroll
        for (int i = 0; i < 4; ++i) {
            int idx = tid + i*256;
            int row = idx >> 3;
            int c4 = (idx & 7) * 4;
            int z = m0 + row;
            int k = kc + c4;
            float4 v = (k < 64)
                ? *(const float4*)&xt[((size_t)z*NN + n)*64 + k]
                : *(const float4*)&mxt[((size_t)z*NN + n)*64 + k - 64];
            *(float4*)&As[row][c4] = tf32x4(v);
        }
        #pragma unroll
        for (int i = 0; i < 6; ++i) {
            int idx = tid + i*256;
            int krow = idx / 48;
            int c4 = (idx % 48) * 4;
            int kk = kc + krow;
            const float* src = (c4 < 128)
                ? gW + ((size_t)(2*n + (kk>=64))*C + (kk&63))*128 + c4
                : uW + ((size_t)(2*n + (kk>=64))*C + (kk&63))*64 + (c4 - 128);
            *(float4*)&Bs[krow][c4] = *(const float4*)src;
        }
        __syncthreads();
        #pragma unroll
        for (int k8 = 0; k8 < 32; k8 += 8) {
            uint32_t a[2][4];
            int ac = k8 + (lane&3);
            #pragma unroll
            for (int mt = 0; mt < 2; ++mt) {
                int rr = wm*32 + mt*16 + (lane>>2);
                a[mt][0] = __float_as_uint(As[rr][ac]);
                a[mt][1] = __float_as_uint(As[rr+8][ac]);
                a[mt][2] = __float_as_uint(As[rr][ac+4]);
                a[mt][3] = __float_as_uint(As[rr+8][ac+4]);
            }
            #pragma unroll
            for (int j = 0; j < 12; ++j) {
                int col = wn*96 + j*8 + (lane>>2);
                uint32_t b0 = __float_as_uint(Bs[k8 + (lane&3)][col]);
                uint32_t b1 = __float_as_uint(Bs[k8 + (lane&3) + 4][col]);
                mma_tf32(acc[0][j], a[0], b0, b1);
                mma_tf32(acc[1][j], a[1], b0, b1);
            }
        }
        __syncthreads();
    }
    #pragma unroll
    for (int mt = 0; mt < 2; ++mt) {
        #pragma unroll
        for (int j = 0; j < 12; ++j) {
            int col = wn*96 + j*8 + (lane&3)*2;
            #pragma unroll
            for (int half = 0; half < 2; ++half) {
                int z = m0 + wm*32 + mt*16 + (lane>>2) + half*8;
                int b = z / 12, t = z - b*12;
                float v0 = acc[mt][j][half*2], v1 = acc[mt][j][half*2+1];
                if (col < 128) {
                    float2 bb = *(const float2*)&gb[n*128 + col];
                    *(float2*)&cg[(((size_t)t*BB + b)*NN + n)*128 + col] =
                        make_float2(v0 + bb.x, v1 + bb.y);
                } else {
                    int o = col - 128;
                    float2 bb = *(const float2*)&ub[n*64 + o];
                    *(float2*)&cu[(((size_t)t*BB + b)*NN + n)*64 + o] =
                        make_float2(v0 + bb.x, v1 + bb.y);
                }
            }
        }
    }
}

// ---------------- hypernetwork ----------------
__global__ void __launch_bounds__(256) k_hyp_mma(const float* __restrict__ hypW) {
    __shared__ float As[128][36];
    __shared__ float Bs[32][56];
    int m0 = blockIdx.x * 128;
    int k0 = blockIdx.y * 1024;
    int tid = threadIdx.x, warp = tid >> 5, lane = tid & 31;
    int wm = warp >> 1, wn = warp & 1;
    float acc[2][3][4];
    #pragma unroll
    for (int mt=0;mt<2;++mt) for (int j=0;j<3;++j) for (int q=0;q<4;++q) acc[mt][j][q]=0.f;
    for (int kc = k0; kc < k0 + 1024; kc += 32) {
        #pragma unroll
        for (int i = 0; i < 4; ++i) {
            int idx = tid + i*256;
            int row = idx >> 3;
            int c4 = (idx & 7) * 4;
            *(float4*)&As[row][c4] = *(const float4*)&g_uW[(size_t)(m0+row)*16384 + kc + c4];
        }
        if (tid < 128) {
            int krow = tid / 4, c4a = (tid % 4) * 4;
            #pragma unroll
            for (int seg = 0; seg < 3; ++seg) {
                int c4 = c4a + seg*16;
                if (c4 < 48)
                    *(float4*)&Bs[krow][c4] = tf32x4(*(const float4*)&hypW[(size_t)(kc+krow)*48 + c4]);
            }
        }
        __syncthreads();
        #pragma unroll
        for (int k8 = 0; k8 < 32; k8 += 8) {
            uint32_t a[2][4];
            int ac = k8 + (lane&3);
            #pragma unroll
            for (int mt = 0; mt < 2; ++mt) {
                int rr = wm*32 + mt*16 + (lane>>2);
                a[mt][0] = __float_as_uint(As[rr][ac]);
                a[mt][1] = __float_as_uint(As[rr+8][ac]);
                a[mt][2] = __float_as_uint(As[rr][ac+4]);
                a[mt][3] = __float_as_uint(As[rr+8][ac+4]);
            }
            #pragma unroll
            for (int j = 0; j < 3; ++j) {
                int col = wn*24 + j*8 + (lane>>2);
                uint32_t b0 = __float_as_uint(Bs[k8 + (lane&3)][col]);
                uint32_t b1 = __float_as_uint(Bs[k8 + (lane&3) + 4][col]);
                mma_tf32(acc[0][j], a[0], b0, b1);
                mma_tf32(acc[1][j], a[1], b0, b1);
            }
        }
        __syncthreads();
    }
    #pragma unroll
    for (int mt = 0; mt < 2; ++mt)
    #pragma unroll
    for (int j = 0; j < 3; ++j) {
        int col = wn*24 + j*8 + (lane&3)*2;
        int row = m0 + wm*32 + mt*16 + (lane>>2);
        atomicAdd(&g_hlin[row*48 + col],   acc[mt][j][0]);
        atomicAdd(&g_hlin[row*48 + col+1], acc[mt][j][1]);
        atomicAdd(&g_hlin[(row+8)*48 + col],   acc[mt][j][2]);
        atomicAdd(&g_hlin[(row+8)*48 + col+1], acc[mt][j][3]);
    }
}

__global__ void k_hyp_fin(const float* __restrict__ hypb) {
    int idx = blockIdx.x*blockDim.x + threadIdx.x;
    if (idx >= NN*TT) return;
    int t = idx % TT, n = idx / TT;
    float s = 0.f;
    #pragma unroll
    for (int f = 0; f < 4; ++f) s += g_hlin[n*48 + t*4 + f] + hypb[t*4 + f];
    g_fs[n*TT + t] = s;
}

__global__ void __launch_bounds__(256) k_gemm64_mma(
        const float* __restrict__ X, const float* __restrict__ W,
        const float* __restrict__ bias, float* __restrict__ Y, int relu) {
    __shared__ float Xs[128][36];
    __shared__ float Ws[32][72];
    int r0 = blockIdx.x * 128;
    int tid = threadIdx.x;
    int warp = tid >> 5, lane = tid & 31;
    float acc[8][4];
    #pragma unroll
    for (int j=0;j<8;++j) for (int q=0;q<4;++q) acc[j][q]=0.f;
    for (int kc = 0; kc < 64; kc += 32) {
        #pragma unroll
        for (int i = 0; i < 4; ++i) {
            int idx = tid + i*256;
            int row = idx >> 3;
            int c4 = (idx & 7) * 4;
            *(float4*)&Xs[row][c4] = tf32x4(*(const float4*)&X[(size_t)(r0+row)*64 + kc + c4]);
        }
        #pragma unroll
        for (int i = 0; i < 2; ++i) {
            int idx = tid + i*256;
            int krow = idx >> 4;
            int c4 = (idx & 15) * 4;
            *(float4*)&Ws[krow][c4] = tf32x4(*(const float4*)&W[(size_t)(kc+krow)*64 + c4]);
        }
        __syncthreads();
        #pragma unroll
        for (int k8 = 0; k8 < 32; k8 += 8) {
            uint32_t a[4];
            int ar = warp*16 + (lane>>2);
            int ac = k8 + (lane&3);
            a[0] = __float_as_uint(Xs[ar][ac]);
            a[1] = __float_as_uint(Xs[ar+8][ac]);
            a[2] = __float_as_uint(Xs[ar][ac+4]);
            a[3] = __float_as_uint(Xs[ar+8][ac+4]);
            #pragma unroll
            for (int j = 0; j < 8; ++j) {
                uint32_t b0 = __float_as_uint(Ws[k8 + (lane&3)][j*8 + (lane>>2)]);
                uint32_t b1 = __float_as_uint(Ws[k8 + (lane&3) + 4][j*8 + (lane>>2)]);
                mma_tf32(acc[j], a, b0, b1);
            }
        }
        __syncthreads();
    }
    int row = r0 + warp*16 + (lane>>2);
    #pragma unroll
    for (int j = 0; j < 8; ++j) {
        int col = j*8 + (lane&3)*2;
        float b0 = bias ? bias[col] : 0.f, b1 = bias ? bias[col+1] : 0.f;
        float v0 = acc[j][0] + b0, v1 = acc[j][1] + b1;
        float v2 = acc[j][2] + b0, v3 = acc[j][3] + b1;
        if (relu) { v0=fmaxf(v0,0.f); v1=fmaxf(v1,0.f); v2=fmaxf(v2,0.f); v3=fmaxf(v3,0.f); }
        *(float2*)&Y[(size_t)row*64 + col] = make_float2(v0, v1);
        *(float2*)&Y[(size_t)(row+8)*64 + col] = make_float2(v2, v3);
    }
}

__global__ void k_attn(const float* __restrict__ bv) {
    __shared__ float qs[12][64], ks[12][64], vs[12][64];
    __shared__ float sc[2][12][12];
    int bn = blockIdx.x;
    int b = bn >> 9, n = bn & 511;
    int tid = threadIdx.x;
    for (int idx = tid; idx < 12*64; idx += 128) {
        int t = idx >> 6, c = idx & 63;
        size_t g = (((size_t)b*TT + t)*NN + n)*HH + c;
        qs[t][c] = g_q[g];
        ks[t][c] = g_k[g];
        vs[t][c] = g_fs[n*TT + t] * g_v[((size_t)b*NN + n)*64 + c] + bv[c];
    }
    __syncthreads();
    for (int idx = tid; idx < 288; idx += 128) {
        int h = idx / 144, rem = idx - h*144;
        int t = rem / 12, s = rem - t*12;
        float d = 0.f;
        #pragma unroll
        for (int k = 0; k < 32; ++k) d += qs[t][h*32 + k] * ks[s][h*32 + k];
        sc[h][t][s] = d * 0.17677669529663687f;
    }
    __syncthreads();
    if (tid < 24) {
        int h = tid / 12, t = tid - h*12;
        float mx = -1e30f;
        #pragma unroll
        for (int s = 0; s < 12; ++s) mx = fmaxf(mx, sc[h][t][s]);
        float sum = 0.f;
        #pragma unroll
        for (int s = 0; s < 12; ++s) { float e = __expf(sc[h][t][s] - mx); sc[h][t][s] = e; sum += e; }
        float inv = 1.f / sum;
        #pragma unroll
        for (int s = 0; s < 12; ++s) sc[h][t][s] *= inv;
    }
    __syncthreads();
    for (int idx = tid; idx < 768; idx += 128) {
        int h = idx / 384, rem = idx - h*384;
        int t = rem >> 5, d = rem & 31;
        float a = 0.f;
        #pragma unroll
        for (int s = 0; s < 12; ++s) a += sc[h][t][s] * vs[s][h*32 + d];
        g_o[(((size_t)b*TT + t)*NN + n)*HH + h*32 + d] = a;
    }
}

// ---------------- fused tail ----------------
__global__ void __launch_bounds__(256) k_tail(
        const float* __restrict__ o_, const float* __restrict__ res,
        const float* __restrict__ ln1g, const float* __restrict__ ln1b,
        const float* __restrict__ W1, const float* __restrict__ b1,
        const float* __restrict__ W2, const float* __restrict__ b2,
        const float* __restrict__ ln2g, const float* __restrict__ ln2b,
        const float* __restrict__ fcW, const float* __restrict__ fcb,
        float* __restrict__ y) {
    extern __shared__ float smp[];
    float* val = smp;
    float* f1  = smp + 8704;
    float* Ws  = smp + 17408;
    int tid = threadIdx.x, warp = tid >> 5, lane = tid & 31;
    size_t r0 = (size_t)blockIdx.x * 128;

    for (int it = 0; it < 16; ++it) {
        int rl = it*8 + warp;
        size_t row = r0 + rl;
        int c = lane*2;
        float2 a = *(const float2*)&o_[row*64 + c];
        float2 b = *(const float2*)&res[row*64 + c];
        float x0 = a.x + b.x, x1 = a.y + b.y;
        float s = x0 + x1, sq = x0*x0 + x1*x1;
        #pragma unroll
        for (int o = 16; o > 0; o >>= 1) {
            s  += __shfl_xor_sync(0xffffffffu, s, o);
            sq += __shfl_xor_sync(0xffffffffu, sq, o);
        }
        float mu = s * (1.f/64.f);
        float var = sq * (1.f/64.f) - mu*mu;
        float rstd = rsqrtf(var + 1e-5f);
        val[rl*68 + c]   = (x0 - mu) * rstd * ln1g[c]   + ln1b[c];
        val[rl*68 + c+1] = (x1 - mu) * rstd * ln1g[c+1] + ln1b[c+1];
    }
    __syncthreads();

    int rowl = warp*16 + (lane>>2);
    {
        float acc[8][4];
        #pragma unroll
        for (int j=0;j<8;++j){acc[j][0]=0.f;acc[j][1]=0.f;acc[j][2]=0.f;acc[j][3]=0.f;}
        for (int kc = 0; kc < 64; kc += 32) {
            #pragma unroll
            for (int i = 0; i < 2; ++i) {
                int idx = tid + i*256;
                int krow = idx >> 4;
                int c4 = (idx & 15) * 4;
                *(float4*)&Ws[krow*72 + c4] = tf32x4(*(const float4*)&W1[(size_t)(kc+krow)*64 + c4]);
            }
            __syncthreads();
            #pragma unroll
            for (int k8 = 0; k8 < 32; k8 += 8) {
                uint32_t a[4];
                int ac = kc + k8 + (lane&3);
                a[0] = cvu(val[rowl*68 + ac]);
                a[1] = cvu(val[(rowl+8)*68 + ac]);
                a[2] = cvu(val[rowl*68 + ac + 4]);
                a[3] = cvu(val[(rowl+8)*68 + ac + 4]);
                #pragma unroll
                for (int j = 0; j < 8; ++j) {
                    int col = j*8 + (lane>>2);
                    uint32_t b0 = __float_as_uint(Ws[(k8+(lane&3))*72 + col]);
                    uint32_t b1 = __float_as_uint(Ws[(k8+(lane&3)+4)*72 + col]);
                    mma_tf32(acc[j], a, b0, b1);
                }
            }
            __syncthreads();
        }
        #pragma unroll
        for (int j = 0; j < 8; ++j) {
            int col = j*8 + (lane&3)*2;
            float bb0 = b1[col], bb1 = b1[col+1];
            f1[rowl*68 + col]       = fmaxf(acc[j][0] + bb0, 0.f);
            f1[rowl*68 + col+1]     = fmaxf(acc[j][1] + bb1, 0.f);
            f1[(rowl+8)*68 + col]   = fmaxf(acc[j][2] + bb0, 0.f);
            f1[(rowl+8)*68 + col+1] = fmaxf(acc[j][3] + bb1, 0.f);
        }
    }
    __syncthreads();

    {
        float acc[8][4];
        #pragma unroll
        for (int j=0;j<8;++j){acc[j][0]=0.f;acc[j][1]=0.f;acc[j][2]=0.f;acc[j][3]=0.f;}
        for (int kc = 0; kc < 64; kc += 32) {
            #pragma unroll
            for (int i = 0; i < 2; ++i) {
                int idx = tid + i*256;
                int krow = idx >> 4;
                int c4 = (idx & 15) * 4;
                *(float4*)&Ws[krow*72 + c4] = tf32x4(*(const float4*)&W2[(size_t)(kc+krow)*64 + c4]);
            }
            __syncthreads();
            #pragma unroll
            for (int k8 = 0; k8 < 32; k8 += 8) {
                uint32_t a[4];
                int ac = kc + k8 + (lane&3);
                a[0] = cvu(f1[rowl*68 + ac]);
                a[1] = cvu(f1[(rowl+8)*68 + ac]);
                a[2] = cvu(f1[rowl*68 + ac + 4]);
                a[3] = cvu(f1[(rowl+8)*68 + ac + 4]);
                #pragma unroll
                for (int j = 0; j < 8; ++j) {
                    int col = j*8 + (lane>>2);
                    uint32_t b0 = __float_as_uint(Ws[(k8+(lane&3))*72 + col]);
                    uint32_t b1 = __float_as_uint(Ws[(k8+(lane&3)+4)*72 + col]);
                    mma_tf32(acc[j], a, b0, b1);
                }
            }
            __syncthreads();
        }
        float xs0[16], xs1[16];
        float s0=0.f, q0=0.f, s1=0.f, q1=0.f;
        #pragma unroll
        for (int j = 0; j < 8; ++j) {
            #pragma unroll
            for (int cc = 0; cc < 2; ++cc) {
                int col = j*8 + (lane&3)*2 + cc;
                float x0 = acc[j][cc]   + b2[col] + val[rowl*68 + col];
                float x1 = acc[j][2+cc] + b2[col] + val[(rowl+8)*68 + col];
                xs0[j*2+cc] = x0; s0 += x0; q0 += x0*x0;
                xs1[j*2+cc] = x1; s1 += x1; q1 += x1*x1;
            }
        }
        s0 += __shfl_xor_sync(0xffffffffu, s0, 1); s0 += __shfl_xor_sync(0xffffffffu, s0, 2);
        q0 += __shfl_xor_sync(0xffffffffu, q0, 1); q0 += __shfl_xor_sync(0xffffffffu, q0, 2);
        s1 += __shfl_xor_sync(0xffffffffu, s1, 1); s1 += __shfl_xor_sync(0xffffffffu, s1, 2);
        q1 += __shfl_xor_sync(0xffffffffu, q1, 1); q1 += __shfl_xor_sync(0xffffffffu, q1, 2);
        float mu0 = s0*(1.f/64.f), rstd0 = rsqrtf(q0*(1.f/64.f) - mu0*mu0 + 1e-5f);
        float mu1 = s1*(1.f/64.f), rstd1 = rsqrtf(q1*(1.f/64.f) - mu1*mu1 + 1e-5f);
        float y0 = 0.f, y1 = 0.f;
        #pragma unroll
        for (int j = 0; j < 8; ++j) {
            #pragma unroll
            for (int cc = 0; cc < 2; ++cc) {
                int col = j*8 + (lane&3)*2 + cc;
                float g = ln2g[col], be = ln2b[col], fw = fcW[col];
                y0 += ((xs0[j*2+cc] - mu0)*rstd0*g + be) * fw;
                y1 += ((xs1[j*2+cc] - mu1)*rstd1*g + be) * fw;
            }
        }
        y0 += __shfl_xor_sync(0xffffffffu, y0, 1); y0 += __shfl_xor_sync(0xffffffffu, y0, 2);
        y1 += __shfl_xor_sync(0xffffffffu, y1, 1); y1 += __shfl_xor_sync(0xffffffffu, y1, 2);
        if ((lane & 3) == 0) {
            float fb = fcb[0];
            y[r0 + rowl]     = y0 + fb;
            y[r0 + rowl + 8] = y1 + fb;
        }
    }
}

// ---------------- host ----------------
extern "C" void kernel_launch(void* const* d_in, const int* in_sizes, int n_in,
                              void* d_out, int out_size) {
    const float* src  = (const float*)d_in[0];
    const float* emb  = (const float*)d_in[2];
    const float* gwp0 = (const float*)d_in[3];
    const float* gbp0 = (const float*)d_in[4];
    const float* uwp0 = (const float*)d_in[5];
    const float* ubp0 = (const float*)d_in[6];
    const float* gwp1 = (const float*)d_in[7];
    const float* gbp1 = (const float*)d_in[8];
    const float* uwp1 = (const float*)d_in[9];
    const float* ubp1 = (const float*)d_in[10];
    const float* hypW = (const float*)d_in[11];
    const float* hypb = (const float*)d_in[12];

    const float *Wq,*Wk,*Wv,*ffW1,*ffW2,*bq,*bk,*bv,*ffb1,*ffb2,*ln1g,*ln1b,*ln2g,*ln2b,*fcW,*fcb;
    if (n_in > 14 && in_sizes[14] == 64) {
        Wq  = (const float*)d_in[13]; bq  = (const float*)d_in[14];
        Wk  = (const float*)d_in[15]; bk  = (const float*)d_in[16];
        Wv  = (const float*)d_in[17]; bv  = (const float*)d_in[18];
        ln1g= (const float*)d_in[19]; ln1b= (const float*)d_in[20];
        ffW1= (const float*)d_in[21]; ffb1= (const float*)d_in[22];
        ffW2= (const float*)d_in[23]; ffb2= (const float*)d_in[24];
        ln2g= (const float*)d_in[25]; ln2b= (const float*)d_in[26];
        fcW = (const float*)d_in[27]; fcb = (const float*)d_in[28];
    } else {
        Wq  = (const float*)d_in[13]; Wk  = (const float*)d_in[14];
        Wv  = (const float*)d_in[15]; ffW1= (const float*)d_in[16];
        ffW2= (const float*)d_in[17]; bq  = (const float*)d_in[18];
        bk  = (const float*)d_in[19]; bv  = (const float*)d_in[20];
        ffb1= (const float*)d_in[21]; ffb2= (const float*)d_in[22];
        ln1g= (const float*)d_in[23]; ln1b= (const float*)d_in[24];
        ln2g= (const float*)d_in[25]; ln2b= (const float*)d_in[26];
        fcW = (const float*)d_in[27]; fcb = (const float*)d_in[28];
    }

    float *p_gW,*p_gb,*p_uW,*p_ub,*p_cg,*p_cu,*p_mxt,*p_xt0t;
    float *p_hs0,*p_hs1,*p_hv,*p_q,*p_k,*p_v,*p_o;
    __half *p_gWh,*p_uWh;
    cudaGetSymbolAddress((void**)&p_gW, g_gW);
    cudaGetSymbolAddress((void**)&p_gb, g_gb);
    cudaGetSymbolAddress((void**)&p_uW, g_uW);
    cudaGetSymbolAddress((void**)&p_ub, g_ub);
    cudaGetSymbolAddress((void**)&p_gWh, g_gWh);
    cudaGetSymbolAddress((void**)&p_uWh, g_uWh);
    cudaGetSymbolAddress((void**)&p_cg, g_cg);
    cudaGetSymbolAddress((void**)&p_cu, g_cu);
    cudaGetSymbolAddress((void**)&p_mxt, g_mxt);
    cudaGetSymbolAddress((void**)&p_xt0t, g_xt0t);
    cudaGetSymbolAddress((void**)&p_hs0, g_hs0);
    cudaGetSymbolAddress((void**)&p_hs1, g_hs1);
    cudaGetSymbolAddress((void**)&p_hv, g_hv);
    cudaGetSymbolAddress((void**)&p_q, g_q);
    cudaGetSymbolAddress((void**)&p_k, g_k);
    cudaGetSymbolAddress((void**)&p_v, g_v);
    cudaGetSymbolAddress((void**)&p_o, g_o);

    cudaFuncSetAttribute(k_recur, cudaFuncAttributeMaxDynamicSharedMemorySize, RECUR_SMEM);
    cudaFuncSetAttribute(k_tail, cudaFuncAttributeMaxDynamicSharedMemorySize, TAIL_SMEM);

    for (int layer = 0; layer < 2; ++layer) {
        int Cin = (layer == 0) ? 2 : 64;
        int C = Cin + HH;
        int SgW4 = 2*C*128/4, SuW4 = 2*C*64/4;
        int work = NN*(SgW4 + 32 + SuW4 + 16) + ((layer == 0) ? ZT*NN*2 : 0);
        int grid = NN + (work + 255)/256;
        float* hs_out;
        float* hv_out;
        if (layer == 0) {
            k_fused_pre<<<grid, 256>>>(emb, gwp0, gbp0, uwp0, ubp0,
                                       p_gW, p_gb, p_uW, p_ub, p_gWh, p_uWh, SgW4, SuW4,
                                       src, p_xt0t, 1);
            k_mix64<<<dim3(8, (ZT*2)/64), 256>>>(p_xt0t, p_mxt);
            k_precomp<<<dim3(NN, 6), 192>>>(src, p_mxt, p_gW, p_uW, p_gb, p_ub, p_cg, p_cu, Cin);
            hs_out = p_hs0; hv_out = nullptr;
        } else {
            k_fused_pre<<<grid, 256>>>(emb, gwp1, gbp1, uwp1, ubp1,
                                       p_gW, p_gb, p_uW, p_ub, p_gWh, p_uWh, SgW4, SuW4,
                                       nullptr, nullptr, 0);
            k_mix64<<<dim3(8, ZT), 256>>>(p_hs0, p_mxt);
            k_precomp_mma<<<dim3(NN, 3), 256>>>(p_hs0, p_mxt, p_gW, p_uW, p_gb, p_ub, p_cg, p_cu);
            hs_out = p_hs1; hv_out = p_hv;
        }
        unsigned nbar0 = (layer == 0) ? 0u : 45u;
        k_recur<<<GRID_P, 256, RECUR_SMEM>>>(p_gWh, p_uWh, p_cg, p_cu, hs_out, C, Cin, nbar0, hv_out);
    }

    k_hyp_mma<<<dim3(4, 16), 256>>>(hypW);
    k_hyp_fin<<<(NN*TT + 255)/256, 256>>>(hypb);

    k_gemm64_mma<<<BTN/128, 256>>>(p_hs1, Wq, bq, p_q, 0);
    k_gemm64_mma<<<BTN/128, 256>>>(p_hs1, Wk, bk, p_k, 0);
    k_gemm64_mma<<<BB*NN/128, 256>>>(p_hv, Wv, nullptr, p_v, 0);

    k_attn<<<BB*NN, 128>>>(bv);

    k_tail<<<BTN/128, 256, TAIL_SMEM>>>(p_o, p_hs1, ln1g, ln1b,
                                        ffW1, ffb1, ffW2, ffb2,
                                        ln2g, ln2b, fcW, fcb, (float*)d_out);
}

// round 16
// speedup vs baseline: 1.2580x; 1.1287x over previous
#include <cuda_runtime.h>
#include <cuda_fp16.h>
#include <math.h>
#include <stdint.h>

#define BB 32
#define TT 12
#define NN 512
#define HH 64
#define EE 16
#define BTN (BB*TT*NN)
#define BTNH (BTN*HH)
#define ZT (BB*TT)
#define GRID_P 256
#define RECUR_SMEM 26112
#define TAIL_SMEM  78848
#define PRE16_SMEM 47616

__device__ float g_adj[NN*NN];
__device__ __half g_adjh[NN*NN];
__device__ float g_gW[NN*2*128*128];
__device__ __half g_gWh[NN*2*128*128];
__device__ float g_gb[NN*128];
__device__ float g_uW[NN*2*128*64];
__device__ __half g_uWh[NN*2*128*64];
__device__ float g_ub[NN*64];
__device__ float g_state[BB*NN*HH];
__device__ __half g_sh[BB*NN*HH];
__device__ __half g_zsh[BB*NN*HH];
__device__ __half g_mixsh[BB*NN*HH];
__device__ __half g_mixzsh[BB*NN*HH];
__device__ float g_r[BB*NN*HH];
__device__ float g_cg[TT*BB*NN*128];
__device__ float g_cu[TT*BB*NN*64];
__device__ float g_mxt[ZT*NN*64];
__device__ __half g_mxth[ZT*NN*64];
__device__ float g_xt0t[TT*NN*64];
__device__ float g_hs0[BTNH];
__device__ __half g_hs0h[BTNH];
__device__ float g_hs1[BTNH];
__device__ float g_fs[NN*TT];
__device__ float g_hlin[NN*48];
__device__ float g_hv[BB*NN*HH];
__device__ float g_q[BTNH];
__device__ float g_k[BTNH];
__device__ float g_v[BB*NN*HH];
__device__ float g_o[BTNH];
__device__ unsigned g_bar;

__device__ __forceinline__ float to_tf32(float x) {
    uint32_t u; asm("cvt.rna.tf32.f32 %0, %1;" : "=r"(u) : "f"(x));
    return __uint_as_float(u);
}
__device__ __forceinline__ uint32_t cvu(float x) {
    uint32_t u; asm("cvt.rna.tf32.f32 %0, %1;" : "=r"(u) : "f"(x));
    return u;
}
__device__ __forceinline__ float4 tf32x4(float4 v) {
    float4 w; w.x=to_tf32(v.x); w.y=to_tf32(v.y); w.z=to_tf32(v.z); w.w=to_tf32(v.w);
    return w;
}
__device__ __forceinline__ void mma_tf32(float* c, const uint32_t* a, uint32_t b0, uint32_t b1) {
    asm volatile("mma.sync.aligned.m16n8k8.row.col.f32.tf32.tf32.f32 "
        "{%0,%1,%2,%3}, {%4,%5,%6,%7}, {%8,%9}, {%0,%1,%2,%3};"
        : "+f"(c[0]), "+f"(c[1]), "+f"(c[2]), "+f"(c[3])
        : "r"(a[0]), "r"(a[1]), "r"(a[2]), "r"(a[3]), "r"(b0), "r"(b1));
}
__device__ __forceinline__ void mma_f16(float* c, const uint32_t* a, uint32_t b0, uint32_t b1) {
    asm volatile("mma.sync.aligned.m16n8k16.row.col.f32.f16.f16.f32 "
        "{%0,%1,%2,%3}, {%4,%5,%6,%7}, {%8,%9}, {%0,%1,%2,%3};"
        : "+f"(c[0]), "+f"(c[1]), "+f"(c[2]), "+f"(c[3])
        : "r"(a[0]), "r"(a[1]), "r"(a[2]), "r"(a[3]), "r"(b0), "r"(b1));
}
__device__ __forceinline__ void ldsm4(uint32_t& r0, uint32_t& r1, uint32_t& r2, uint32_t& r3, uint32_t addr) {
    asm volatile("ldmatrix.sync.aligned.m8n8.x4.shared.b16 {%0,%1,%2,%3}, [%4];"
        : "=r"(r0), "=r"(r1), "=r"(r2), "=r"(r3) : "r"(addr));
}
__device__ __forceinline__ void ldsm4t(uint32_t& r0, uint32_t& r1, uint32_t& r2, uint32_t& r3, uint32_t addr) {
    asm volatile("ldmatrix.sync.aligned.m8n8.x4.trans.shared.b16 {%0,%1,%2,%3}, [%4];"
        : "=r"(r0), "=r"(r1), "=r"(r2), "=r"(r3) : "r"(addr));
}
__device__ __forceinline__ float sigm(float v) { return 1.f / (1.f + __expf(-v)); }
__device__ __forceinline__ float tanhfast(float v) { return 1.f - 2.f / (__expf(2.f*v) + 1.f); }

__device__ __forceinline__ void gbar(unsigned n) {
    __syncthreads();
    if (threadIdx.x == 0) {
        __threadfence();
        atomicAdd(&g_bar, 1u);
        unsigned target = n * GRID_P;
        volatile unsigned* p = &g_bar;
        while (*p < target) __nanosleep(64);
        __threadfence();
    }
    __syncthreads();
}

// ---------------- fused pre-kernel ----------------
__global__ void k_fused_pre(const float* __restrict__ emb,
                            const float* __restrict__ gwp, const float* __restrict__ gbp,
                            const float* __restrict__ uwp, const float* __restrict__ ubp,
                            float* __restrict__ gW, float* __restrict__ gb,
                            float* __restrict__ uW, float* __restrict__ ub,
                            __half* __restrict__ gWh, __half* __restrict__ uWh,
                            int SgW4, int SuW4,
                            const float* __restrict__ src, float* __restrict__ xt0,
                            int do_adj) {
    __shared__ float semb[NN*EE];
    __shared__ float row[NN];
    __shared__ float red[256];
    if (blockIdx.x < NN) {
        if (!do_adj) return;
        if (blockIdx.x == 0 && threadIdx.x == 0) g_bar = 0u;
        for (int i = blockIdx.x*256 + threadIdx.x; i < NN*48; i += NN*256) g_hlin[i] = 0.f;
        int n = blockIdx.x;
        for (int i = threadIdx.x; i < NN*EE; i += 256) semb[i] = emb[i];
        __syncthreads();
        float lmax = -1e30f;
        for (int m = threadIdx.x; m < NN; m += 256) {
            float s = 0.f;
            #pragma unroll
            for (int e = 0; e < EE; ++e) s += semb[n*EE+e] * semb[m*EE+e];
            s = fmaxf(s, 0.f);
            row[m] = s;
            lmax = fmaxf(lmax, s);
        }
        red[threadIdx.x] = lmax; __syncthreads();
        for (int s = 128; s > 0; s >>= 1) {
            if (threadIdx.x < s) red[threadIdx.x] = fmaxf(red[threadIdx.x], red[threadIdx.x+s]);
            __syncthreads();
        }
        float mx = red[0];
        __syncthreads();
        float lsum = 0.f;
        for (int m = threadIdx.x; m < NN; m += 256) {
            float v = expf(row[m] - mx);
            row[m] = v; lsum += v;
        }
        red[threadIdx.x] = lsum; __syncthreads();
        for (int s = 128; s > 0; s >>= 1) {
            if (threadIdx.x < s) red[threadIdx.x] += red[threadIdx.x+s];
            __syncthreads();
        }
        float inv = 1.f / red[0];
        for (int m = threadIdx.x; m < NN; m += 256) {
            float a = row[m] * inv;
            g_adj[n*NN + m] = to_tf32(a);
            g_adjh[n*NN + m] = __float2half_rn(a);
        }
        return;
    }
    int idx = (blockIdx.x - NN)*256 + threadIdx.x;
    int t0 = NN*SgW4, t1 = t0 + NN*32, t2 = t1 + NN*SuW4, t3 = t2 + NN*16;
    if (idx < t3) {
        const float* pool; float* out; __half* outh; int S4, local, rnd;
        if (idx < t0)      { pool = gwp; out = gW; outh = gWh; S4 = SgW4; local = idx;      rnd = 1; }
        else if (idx < t1) { pool = gbp; out = gb; outh = 0;   S4 = 32;   local = idx - t0; rnd = 0; }
        else if (idx < t2) { pool = uwp; out = uW; outh = uWh; S4 = SuW4; local = idx - t1; rnd = 1; }
        else               { pool = ubp; out = ub; outh = 0;   S4 = 16;   local = idx - t2; rnd = 0; }
        int n = local / S4, i = local - n*S4;
        float4 a = make_float4(0.f,0.f,0.f,0.f);
        const float* e = emb + n*EE;
        const float4* p4 = (const float4*)pool;
        #pragma unroll
        for (int k = 0; k < EE; ++k) {
            float w = e[k];
            float4 p = p4[(size_t)k*S4 + i];
            a.x += w*p.x; a.y += w*p.y; a.z += w*p.z; a.w += w*p.w;
        }
        if (rnd) {
            ((__half2*)outh)[local*2]   = __floats2half2_rn(a.x, a.y);
            ((__half2*)outh)[local*2+1] = __floats2half2_rn(a.z, a.w);
            a = tf32x4(a);
        }
        ((float4*)out)[local] = a;
    } else if (src) {
        int t = idx - t3;
        if (t < ZT*NN*2) {
            int c = t & 1, m = (t >> 1) & 511, z = t >> 10;
            int g = z*2 + c;
            xt0[((size_t)(g>>6)*NN + m)*64 + (g&63)] = src[t];
        }
    }
}

// ---------------- fp32 tf32 mix tile (layer-0 premix only) ----------------
__device__ __forceinline__ void mix_tile(const float* __restrict__ X, float* __restrict__ Y,
                                         float* sm, int tid, int z, int r0) {
    int warp = tid >> 5, lane = tid & 31;
    int wm = warp >> 1, wn = warp & 1;
    const float* Xb = X + (size_t)z * (NN*64);
    float* Yb = Y + (size_t)z * (NN*64);
    float acc[4][4];
    #pragma unroll
    for (int j=0;j<4;++j){acc[j][0]=0.f;acc[j][1]=0.f;acc[j][2]=0.f;acc[j][3]=0.f;}
    float4 ar0, ar1, xr0, xr1;
    int i0 = tid, i1 = tid + 256;
    ar0 = *(const float4*)&g_adj[(size_t)(r0 + (i0>>3))*NN + (i0&7)*4];
    ar1 = *(const float4*)&g_adj[(size_t)(r0 + (i1>>3))*NN + (i1&7)*4];
    xr0 = *(const float4*)&Xb[(size_t)(i0>>4)*64 + (i0&15)*4];
    xr1 = *(const float4*)&Xb[(size_t)(i1>>4)*64 + (i1&15)*4];
    {
        float* As = sm; float* Xs = sm + 4608;
        *(float4*)&As[(i0>>3)*36 + (i0&7)*4] = ar0;
        *(float4*)&As[(i1>>3)*36 + (i1&7)*4] = ar1;
        *(float4*)&Xs[(i0>>4)*72 + (i0&15)*4] = tf32x4(xr0);
        *(float4*)&Xs[(i1>>4)*72 + (i1&15)*4] = tf32x4(xr1);
    }
    for (int c = 0; c < 16; ++c) {
        __syncthreads();
        if (c < 15) {
            int kc = (c+1)*32;
            ar0 = *(const float4*)&g_adj[(size_t)(r0 + (i0>>3))*NN + kc + (i0&7)*4];
            ar1 = *(const float4*)&g_adj[(size_t)(r0 + (i1>>3))*NN + kc + (i1&7)*4];
            xr0 = *(const float4*)&Xb[(size_t)(kc + (i0>>4))*64 + (i0&15)*4];
            xr1 = *(const float4*)&Xb[(size_t)(kc + (i1>>4))*64 + (i1&15)*4];
        }
        float* As = sm + (c&1)*2304;
        float* Xs = sm + 4608 + (c&1)*2304;
        #pragma unroll
        for (int k8 = 0; k8 < 32; k8 += 8) {
            uint32_t a[4];
            int arow = wm*16 + (lane>>2);
            int ac = k8 + (lane&3);
            a[0] = __float_as_uint(As[arow*36 + ac]);
            a[1] = __float_as_uint(As[(arow+8)*36 + ac]);
            a[2] = __float_as_uint(As[arow*36 + ac + 4]);
            a[3] = __float_as_uint(As[(arow+8)*36 + ac + 4]);
            #pragma unroll
            for (int j = 0; j < 4; ++j) {
                int col = wn*32 + j*8 + (lane>>2);
                uint32_t b0 = __float_as_uint(Xs[(k8+(lane&3))*72 + col]);
                uint32_t b1 = __float_as_uint(Xs[(k8+(lane&3)+4)*72 + col]);
                mma_tf32(acc[j], a, b0, b1);
            }
        }
        if (c < 15) {
            float* Asn = sm + ((c+1)&1)*2304;
            float* Xsn = sm + 4608 + ((c+1)&1)*2304;
            *(float4*)&Asn[(i0>>3)*36 + (i0&7)*4] = ar0;
            *(float4*)&Asn[(i1>>3)*36 + (i1&7)*4] = ar1;
            *(float4*)&Xsn[(i0>>4)*72 + (i0&15)*4] = tf32x4(xr0);
            *(float4*)&Xsn[(i1>>4)*72 + (i1&15)*4] = tf32x4(xr1);
        }
    }
    int row = r0 + wm*16 + (lane>>2);
    #pragma unroll
    for (int j = 0; j < 4; ++j) {
        int col = wn*32 + j*8 + (lane&3)*2;
        *(float2*)&Yb[(size_t)row*64 + col] = make_float2(acc[j][0], acc[j][1]);
        *(float2*)&Yb[(size_t)(row+8)*64 + col] = make_float2(acc[j][2], acc[j][3]);
    }
}

__global__ void __launch_bounds__(256) k_mix64(const float* __restrict__ X, float* __restrict__ Y) {
    __shared__ float sm[9216];
    mix_tile(X, Y, sm, threadIdx.x, blockIdx.y, blockIdx.x*64);
}

// ---------------- fp16 ldmatrix mix tile (half in, half out) ----------------
__device__ __forceinline__ void mix16(const __half* __restrict__ Xh, __half* __restrict__ Yh,
                                      float* smf, int tid, int z, int r0) {
    char* smb = (char*)smf;
    uint32_t sb = (uint32_t)__cvta_generic_to_shared(smb);
    int warp = tid >> 5, lane = tid & 31;
    int wm = warp >> 1, wn = warp & 1;
    const __half* Xz = Xh + (size_t)z * (NN*64);
    __half* Yb = Yh + (size_t)z * (NN*64);
    float acc[4][4];
    #pragma unroll
    for (int j=0;j<4;++j){acc[j][0]=0.f;acc[j][1]=0.f;acc[j][2]=0.f;acc[j][3]=0.f;}
    int arow = tid >> 2, acolh = (tid & 3) * 8;
    int xrow = tid >> 3, xcolh = (tid & 7) * 8;
    uint4 av = *(const uint4*)&g_adjh[(size_t)(r0 + arow)*NN + acolh];
    uint4 xv = *(const uint4*)&Xz[(size_t)xrow*64 + xcolh];
    *(uint4*)(smb + arow*80 + (tid&3)*16) = av;
    *(uint4*)(smb + 10240 + xrow*144 + (tid&7)*16) = xv;
    uint32_t a_l = (wm*16 + (lane & 15)) * 80 + ((lane >> 4) * 8) * 2;
    uint32_t xk_l = (lane & 7) + ((lane >> 3) & 1) * 8;
    uint32_t xn_l = (lane >> 4) * 8;
    for (int c = 0; c < 16; ++c) {
        __syncthreads();
        if (c < 15) {
            int kc = (c+1)*32;
            av = *(const uint4*)&g_adjh[(size_t)(r0 + arow)*NN + kc + acolh];
            xv = *(const uint4*)&Xz[(size_t)(kc + xrow)*64 + xcolh];
        }
        uint32_t ab = sb + (c&1)*5120;
        uint32_t xb = sb + 10240 + (c&1)*4608;
        #pragma unroll
        for (int kb = 0; kb < 2; ++kb) {
            uint32_t a[4];
            ldsm4(a[0], a[1], a[2], a[3], ab + a_l + kb*32);
            #pragma unroll
            for (int cg = 0; cg < 2; ++cg) {
                int c0 = wn*32 + cg*16;
                uint32_t b0, b1, b2, b3;
                ldsm4t(b0, b1, b2, b3, xb + (kb*16 + xk_l)*144 + (c0 + xn_l)*2);
                mma_f16(acc[cg*2+0], a, b0, b1);
                mma_f16(acc[cg*2+1], a, b2, b3);
            }
        }
        if (c < 15) {
            *(uint4*)(smb + ((c+1)&1)*5120 + arow*80 + (tid&3)*16) = av;
            *(uint4*)(smb + 10240 + ((c+1)&1)*4608 + xrow*144 + (tid&7)*16) = xv;
        }
    }
    int row = r0 + wm*16 + (lane>>2);
    #pragma unroll
    for (int j = 0; j < 4; ++j) {
        int col = wn*32 + j*8 + (lane&3)*2;
        *(__half2*)&Yb[(size_t)row*64 + col] = __floats2half2_rn(acc[j][0], acc[j][1]);
        *(__half2*)&Yb[(size_t)(row+8)*64 + col] = __floats2half2_rn(acc[j][2], acc[j][3]);
    }
}

// standalone half premix (layer 1): grid (8, ZT)
__global__ void __launch_bounds__(256) k_mix64h(const __half* __restrict__ Xh, __half* __restrict__ Yh) {
    __shared__ float sm[4864];
    mix16(Xh, Yh, sm, threadIdx.x, blockIdx.y, blockIdx.x*64);
}

// ---------------- fp16 gate phase ----------------
__device__ __forceinline__ void phase_gate(const __half* __restrict__ gWh, const float* __restrict__ cg_t,
                                           int C, int Cin, float* smf, int tid) {
    char* smb = (char*)smf;
    uint32_t sb = (uint32_t)__cvta_generic_to_shared(smb);
    int warp = tid >> 5, lane = tid & 31;
    int wm = warp >> 2, wn = warp & 3;
    uint32_t a_l = (wm*16 + (lane & 15)) * 272 + ((lane >> 4) * 8) * 2;
    uint32_t xk_l = (lane & 7) + ((lane >> 3) & 1) * 8;
    uint32_t xn_l = (lane >> 4) * 8;
    for (int n = blockIdx.x; n < NN; n += GRID_P) {
        __syncthreads();
        #pragma unroll
        for (int i = 0; i < 2; ++i) {
            int idx = tid + i*256;
            int row = idx >> 4, h8 = idx & 15;
            uint4 v = (h8 < 8)
                ? *(const uint4*)&g_sh[((size_t)row*NN + n)*64 + h8*8]
                : *(const uint4*)&g_mixsh[((size_t)row*NN + n)*64 + (h8-8)*8];
            *(uint4*)(smb + row*272 + h8*16) = v;
        }
        #pragma unroll
        for (int i = 0; i < 2; ++i) {
            int idx = tid + i*256;
            int kk = idx >> 4, h8 = idx & 15;
            *(uint4*)(smb + 8704 + kk*272 + h8*16) =
                *(const uint4*)&gWh[((size_t)(2*n)*C + Cin + kk)*128 + h8*8];
        }
        float acc[4][4];
        #pragma unroll
        for (int j=0;j<4;++j){acc[j][0]=0.f;acc[j][1]=0.f;acc[j][2]=0.f;acc[j][3]=0.f;}
        uint4 bv[2];
        for (int c = 0; c < 4; ++c) {
            __syncthreads();
            if (c < 3) {
                #pragma unroll
                for (int i = 0; i < 2; ++i) {
                    int idx = tid + i*256;
                    int kk = idx >> 4, h8 = idx & 15;
                    int kg = (c+1)*32 + kk;
                    bv[i] = *(const uint4*)&gWh[((size_t)(2*n + (kg>=64))*C + Cin + (kg&63))*128 + h8*8];
                }
            }
            uint32_t bbase = sb + 8704 + (c&1)*8704;
            #pragma unroll
            for (int kb = 0; kb < 2; ++kb) {
                int kg16 = c*32 + kb*16;
                uint32_t a[4];
                ldsm4(a[0], a[1], a[2], a[3], sb + a_l + kg16*2);
                #pragma unroll
                for (int cg = 0; cg < 2; ++cg) {
                    int c0 = wn*32 + cg*16;
                    uint32_t b0, b1, b2, b3;
                    ldsm4t(b0, b1, b2, b3, bbase + (kb*16 + xk_l)*272 + (c0 + xn_l)*2);
                    mma_f16(acc[cg*2+0], a, b0, b1);
                    mma_f16(acc[cg*2+1], a, b2, b3);
                }
            }
            if (c < 3) {
                char* Bsn = smb + 8704 + ((c+1)&1)*8704;
                #pragma unroll
                for (int i = 0; i < 2; ++i) {
                    int idx = tid + i*256;
                    int kk = idx >> 4, h8 = idx & 15;
                    *(uint4*)(Bsn + kk*272 + h8*16) = bv[i];
                }
            }
        }
        const __half* Ah = (const __half*)smb;
        #pragma unroll
        for (int j = 0; j < 4; ++j) {
            int col = wn*32 + j*8 + (lane&3)*2;
            #pragma unroll
            for (int half = 0; half < 2; ++half) {
                int b = wm*16 + (lane>>2) + half*8;
                float v0 = acc[j][half*2], v1 = acc[j][half*2+1];
                size_t base = (size_t)b*NN + n;
                float2 cgv = *(const float2*)&cg_t[base*128 + col];
                v0 += cgv.x; v1 += cgv.y;
                if (col < 64) {
                    float s0 = __half2float(Ah[b*136 + col]);
                    float s1 = __half2float(Ah[b*136 + col + 1]);
                    *(__half2*)&g_zsh[base*64 + col] =
                        __floats2half2_rn(sigm(v0) * s0, sigm(v1) * s1);
                } else {
                    *(float2*)&g_r[base*64 + col - 64] = make_float2(sigm(v0), sigm(v1));
                }
            }
        }
    }
}

// ---------------- fp16 upd phase ----------------
__device__ __forceinline__ void phase_upd(const __half* __restrict__ uWh, const float* __restrict__ cu_t,
                                          int C, int Cin, float* __restrict__ hs, int t,
                                          float* smf, int tid, float* __restrict__ hv,
                                          __half* __restrict__ hsh) {
    char* smb = (char*)smf;
    uint32_t sb = (uint32_t)__cvta_generic_to_shared(smb);
    int warp = tid >> 5, lane = tid & 31;
    int wm = warp >> 2, wn = warp & 3;
    uint32_t a_l = (wm*16 + (lane & 15)) * 272 + ((lane >> 4) * 8) * 2;
    uint32_t xk_l = (lane & 7) + ((lane >> 3) & 1) * 8;
    uint32_t xn_l = (lane >> 4) * 8;
    for (int n = blockIdx.x; n < NN; n += GRID_P) {
        __syncthreads();
        #pragma unroll
        for (int i = 0; i < 2; ++i) {
            int idx = tid + i*256;
            int row = idx >> 4, h8 = idx & 15;
            uint4 v = (h8 < 8)
                ? *(const uint4*)&g_zsh[((size_t)row*NN + n)*64 + h8*8]
                : *(const uint4*)&g_mixzsh[((size_t)row*NN + n)*64 + (h8-8)*8];
            *(uint4*)(smb + row*272 + h8*16) = v;
        }
        {
            int kk = tid >> 3, h8 = tid & 7;
            *(uint4*)(smb + 8704 + kk*144 + h8*16) =
                *(const uint4*)&uWh[((size_t)(2*n)*C + Cin + kk)*64 + h8*8];
        }
        float acc[2][4];
        #pragma unroll
        for (int j=0;j<2;++j){acc[j][0]=0.f;acc[j][1]=0.f;acc[j][2]=0.f;acc[j][3]=0.f;}
        uint4 bv;
        for (int c = 0; c < 4; ++c) {
            __syncthreads();
            if (c < 3) {
                int kk = tid >> 3, h8 = tid & 7;
                int kg = (c+1)*32 + kk;
                bv = *(const uint4*)&uWh[((size_t)(2*n + (kg>=64))*C + Cin + (kg&63))*64 + h8*8];
            }
            uint32_t bbase = sb + 8704 + (c&1)*4608;
            #pragma unroll
            for (int kb = 0; kb < 2; ++kb) {
                int kg16 = c*32 + kb*16;
                uint32_t a[4];
                ldsm4(a[0], a[1], a[2], a[3], sb + a_l + kg16*2);
                uint32_t b0, b1, b2, b3;
                ldsm4t(b0, b1, b2, b3, bbase + (kb*16 + xk_l)*144 + (wn*16 + xn_l)*2);
                mma_f16(acc[0], a, b0, b1);
                mma_f16(acc[1], a, b2, b3);
            }
            if (c < 3) {
                int kk = tid >> 3, h8 = tid & 7;
                *(uint4*)(smb + 8704 + ((c+1)&1)*4608 + kk*144 + h8*16) = bv;
            }
        }
        #pragma unroll
        for (int j = 0; j < 2; ++j) {
            int col = wn*16 + j*8 + (lane&3)*2;
            #pragma unroll
            for (int half = 0; half < 2; ++half) {
                int b = wm*16 + (lane>>2) + half*8;
                float v0 = acc[j][half*2], v1 = acc[j][half*2+1];
                size_t base = (size_t)b*NN + n;
                float2 cuv = *(const float2*)&cu_t[base*64 + col];
                float hc0 = tanhfast(v0 + cuv.x), hc1 = tanhfast(v1 + cuv.y);
                size_t idx = base*64 + col;
                float2 rr = *(const float2*)&g_r[idx];
                float2 st = *(const float2*)&g_state[idx];
                float h0 = rr.x*st.x + (1.f-rr.x)*hc0;
                float h1 = rr.y*st.y + (1.f-rr.y)*hc1;
                *(float2*)&g_state[idx] = make_float2(h0, h1);
                __half2 hh = __floats2half2_rn(h0, h1);
                *(__half2*)&g_sh[idx] = hh;
                size_t hsidx = (((size_t)b*TT + t)*NN + n)*64 + col;
                *(float2*)&hs[hsidx] = make_float2(h0, h1);
                if (hsh) *(__half2*)&hsh[hsidx] = hh;
                if (hv && t == TT-1)
                    *(float2*)&hv[idx] = make_float2(h0, h1);
            }
        }
    }
}

__global__ void __launch_bounds__(256, 2) k_recur(
        const __half* __restrict__ gWh, const __half* __restrict__ uWh,
        const float* __restrict__ cg, const float* __restrict__ cu,
        float* __restrict__ hs, int C, int Cin, unsigned nbar,
        float* __restrict__ hv, __half* __restrict__ hsh) {
    extern __shared__ float sm[];
    int tid = threadIdx.x;
    for (int idx = blockIdx.x*256 + tid; idx < BB*NN*64; idx += GRID_P*256) {
        int c = idx & 63;
        int n = (idx >> 6) & 511;
        int b = idx >> 15;
        size_t base = (size_t)b*NN + n;
        float r = sigm(cg[base*128 + 64 + c]);
        float hc = tanhfast(cu[base*64 + c]);
        float h = (1.f - r) * hc;
        g_state[base*64 + c] = h;
        __half hh = __float2half_rn(h);
        g_sh[base*64 + c] = hh;
        size_t hsidx = (((size_t)b*TT)*NN + n)*64 + c;
        hs[hsidx] = h;
        if (hsh) hsh[hsidx] = hh;
    }
    gbar(++nbar);
    int z = blockIdx.x >> 3;
    int r0 = (blockIdx.x & 7) * 64;
    for (int t = 1; t < TT; ++t) {
        const float* cg_t = cg + (size_t)t*BB*NN*128;
        const float* cu_t = cu + (size_t)t*BB*NN*64;
        mix16(g_sh, g_mixsh, sm, tid, z, r0);
        gbar(++nbar);
        phase_gate(gWh, cg_t, C, Cin, sm, tid);
        gbar(++nbar);
        mix16(g_zsh, g_mixzsh, sm, tid, z, r0);
        gbar(++nbar);
        phase_upd(uWh, cu_t, C, Cin, hs, t, sm, tid, hv, hsh);
        gbar(++nbar);
    }
}

// ---------------- layer-0 precompute (SIMT, Cin=2) ----------------
__global__ void __launch_bounds__(192) k_precomp(
        const float* __restrict__ xt, const float* __restrict__ mxt,
        const float* __restrict__ gW, const float* __restrict__ uW,
        const float* __restrict__ gb, const float* __restrict__ ub,
        float* __restrict__ cg, float* __restrict__ cu, int Cin) {
    const int C = Cin + HH;
    __shared__ float xs[64][2];
    __shared__ float ms[64][2];
    int n = blockIdx.x;
    int r0 = blockIdx.y * 64;
    int tid = threadIdx.x;
    for (int idx = tid; idx < 64*Cin; idx += 192) {
        int r = idx / Cin, c = idx - r*Cin;
        int z = r0 + r;
        xs[r][c] = xt[((size_t)z*NN + n)*Cin + c];
        int g = z*Cin + c;
        ms[r][c] = mxt[((size_t)(g>>6)*NN + n)*64 + (g&63)];
    }
    __syncthreads();
    float a[64];
    #pragma unroll
    for (int i = 0; i < 64; ++i) a[i] = 0.f;
    if (tid < 128) {
        int o = tid;
        const float* W0 = gW + (size_t)(n*2)*C*128 + o;
        const float* W1 = gW + (size_t)(n*2+1)*C*128 + o;
        for (int c = 0; c < Cin; ++c) {
            float w0 = W0[c*128], w1 = W1[c*128];
            #pragma unroll
            for (int r = 0; r < 64; ++r) a[r] += xs[r][c]*w0 + ms[r][c]*w1;
        }
        float bias = gb[n*128 + o];
        for (int r = 0; r < 64; ++r) {
            int z = r0 + r; int b = z / 12, t = z - b*12;
            cg[(((size_t)t*BB + b)*NN + n)*128 + o] = a[r] + bias;
        }
    } else {
        int o = tid - 128;
        const float* W0 = uW + (size_t)(n*2)*C*64 + o;
        const float* W1 = uW + (size_t)(n*2+1)*C*64 + o;
        for (int c = 0; c < Cin; ++c) {
            float w0 = W0[c*64], w1 = W1[c*64];
            #pragma unroll
            for (int r = 0; r < 64; ++r) a[r] += xs[r][c]*w0 + ms[r][c]*w1;
        }
        float bias = ub[n*64 + o];
        for (int r = 0; r < 64; ++r) {
            int z = r0 + r; int b = z / 12, t = z - b*12;
            cu[(((size_t)t*BB + b)*NN + n)*64 + o] = a[r] + bias;
        }
    }
}

// ---------------- layer-1 precompute, fp16 ldmatrix ----------------
// per node n: M=384 (z, 3 chunks of 128), K=128 ([hs0h|mxth]), N=192 ([gate 128|upd 64])
// smem: Ah @0: 128 x 272B = 34816;  Bh @34816: 32 x 400B = 12800
__global__ void __launch_bounds__(256) k_precomp_mma16(
        const __half* __restrict__ xth, const __half* __restrict__ mxth,
        const __half* __restrict__ gWh, const __half* __restrict__ uWh,
        const float* __restrict__ gb, const float* __restrict__ ub,
        float* __restrict__ cg, float* __restrict__ cu) {
    const int C = 128;
    extern __shared__ float smf[];
    char* smb = (char*)smf;
    uint32_t sb = (uint32_t)__cvta_generic_to_shared(smb);
    int n = blockIdx.x;
    int m0 = blockIdx.y * 128;
    int tid = threadIdx.x;
    int warp = tid >> 5, lane = tid & 31;
    int wm = warp >> 1, wn = warp & 1;
    // load A: 128 rows x 128 half
    #pragma unroll
    for (int i = 0; i < 8; ++i) {
        int idx = tid + i*256;
        int row = idx >> 4, h8 = idx & 15;
        uint4 v = (h8 < 8)
            ? *(const uint4*)&xth[((size_t)(m0+row)*NN + n)*64 + h8*8]
            : *(const uint4*)&mxth[((size_t)(m0+row)*NN + n)*64 + (h8-8)*8];
        *(uint4*)(smb + row*272 + h8*16) = v;
    }
    float acc[2][12][4];
    #pragma unroll
    for (int mt=0;mt<2;++mt) for (int j=0;j<12;++j) for (int q=0;q<4;++q) acc[mt][j][q]=0.f;
    uint32_t xk_l = (lane & 7) + ((lane >> 3) & 1) * 8;
    uint32_t xn_l = (lane >> 4) * 8;
    for (int kc = 0; kc < 4; ++kc) {
        // load B chunk: 32 k-rows x 192 half
        __syncthreads();
        #pragma unroll
        for (int i = 0; i < 3; ++i) {
            int idx = tid + i*256;
            int kk = idx / 24, u = idx % 24;
            int kg = kc*32 + kk;
            int col8 = u*8;
            uint4 v = (col8 < 128)
                ? *(const uint4*)&gWh[((size_t)(2*n + (kg>=64))*C + (kg&63))*128 + col8]
                : *(const uint4*)&uWh[((size_t)(2*n + (kg>=64))*C + (kg&63))*64 + (col8-128)];
            *(uint4*)(smb + 34816 + kk*400 + u*16) = v;
        }
        __syncthreads();
        #pragma unroll
        for (int kb = 0; kb < 2; ++kb) {
            int kg16 = kc*32 + kb*16;
            uint32_t a[2][4];
            #pragma unroll
            for (int mt = 0; mt < 2; ++mt)
                ldsm4(a[mt][0], a[mt][1], a[mt][2], a[mt][3],
                      sb + (wm*32 + mt*16 + (lane & 15))*272 + ((lane >> 4)*8)*2 + kg16*2);
            #pragma unroll
            for (int cg2 = 0; cg2 < 6; ++cg2) {
                int c0 = wn*96 + cg2*16;
                uint32_t b0, b1, b2, b3;
                ldsm4t(b0, b1, b2, b3, sb + 34816 + (kb*16 + xk_l)*400 + (c0 + xn_l)*2);
                mma_f16(acc[0][cg2*2+0], a[0], b0, b1);
                mma_f16(acc[0][cg2*2+1], a[0], b2, b3);
                mma_f16(acc[1][cg2*2+0], a[1], b0, b1);
                mma_f16(acc[1][cg2*2+1], a[1], b2, b3);
            }
        }
    }
    #pragma unroll
    for (int mt = 0; mt < 2; ++mt) {
        #pragma unroll
        for (int j = 0; j < 12; ++j) {
            int col = wn*96 + j*8 + (lane&3)*2;
            #pragma unroll
            for (int half = 0; half < 2; ++half) {
                int z = m0 + wm*32 + mt*16 + (lane>>2) + half*8;
                int b = z / 12, t = z - b*12;
                float v0 = acc[mt][j][half*2], v1 = acc[mt][j][half*2+1];
                if (col < 128) {
                    float2 bb = *(const float2*)&gb[n*128 + col];
                    *(float2*)&cg[(((size_t)t*BB + b)*NN + n)*128 + col] =
                        make_float2(v0 + bb.x, v1 + bb.y);
                } else {
                    int o = col - 128;
                    float2 bb = *(const float2*)&ub[n*64 + o];
                    *(float2*)&cu[(((size_t)t*BB + b)*NN + n)*64 + o] =
                        make_float2(v0 + bb.x, v1 + bb.y);
                }
            }
        }
    }
}

// ---------------- hypernetwork ----------------
__global__ void __launch_bounds__(256) k_hyp_mma(const float* __restrict__ hypW) {
    __shared__ float As[128][36];
    __shared__ float Bs[32][56];
    int m0 = blockIdx.x * 128;
    int k0 = blockIdx.y * 1024;
    int tid = threadIdx.x, warp = tid >> 5, lane = tid & 31;
    int wm = warp >> 1, wn = warp & 1;
    float acc[2][3][4];
    #pragma unroll
    for (int mt=0;mt<2;++mt) for (int j=0;j<3;++j) for (int q=0;q<4;++q) acc[mt][j][q]=0.f;
    for (int kc = k0; kc < k0 + 1024; kc += 32) {
        #pragma unroll
        for (int i = 0; i < 4; ++i) {
            int idx = tid + i*256;
            int row = idx >> 3;
            int c4 = (idx & 7) * 4;
            *(float4*)&As[row][c4] = *(const float4*)&g_uW[(size_t)(m0+row)*16384 + kc + c4];
        }
        if (tid < 128) {
            int krow = tid / 4, c4a = (tid % 4) * 4;
            #pragma unroll
            for (int seg = 0; seg < 3; ++seg) {
                int c4 = c4a + seg*16;
                if (c4 < 48)
                    *(float4*)&Bs[krow][c4] = tf32x4(*(const float4*)&hypW[(size_t)(kc+krow)*48 + c4]);
            }
        }
        __syncthreads();
        #pragma unroll
        for (int k8 = 0; k8 < 32; k8 += 8) {
            uint32_t a[2][4];
            int ac = k8 + (lane&3);
            #pragma unroll
            for (int mt = 0; mt < 2; ++mt) {
                int rr = wm*32 + mt*16 + (lane>>2);
                a[mt][0] = __float_as_uint(As[rr][ac]);
                a[mt][1] = __float_as_uint(As[rr+8][ac]);
                a[mt][2] = __float_as_uint(As[rr][ac+4]);
                a[mt][3] = __float_as_uint(As[rr+8][ac+4]);
            }
            #pragma unroll
            for (int j = 0; j < 3; ++j) {
                int col = wn*24 + j*8 + (lane>>2);
                uint32_t b0 = __float_as_uint(Bs[k8 + (lane&3)][col]);
                uint32_t b1 = __float_as_uint(Bs[k8 + (lane&3) + 4][col]);
                mma_tf32(acc[0][j], a[0], b0, b1);
                mma_tf32(acc[1][j], a[1], b0, b1);
            }
        }
        __syncthreads();
    }
    #pragma unroll
    for (int mt = 0; mt < 2; ++mt)
    #pragma unroll
    for (int j = 0; j < 3; ++j) {
        int col = wn*24 + j*8 + (lane&3)*2;
        int row = m0 + wm*32 + mt*16 + (lane>>2);
        atomicAdd(&g_hlin[row*48 + col],   acc[mt][j][0]);
        atomicAdd(&g_hlin[row*48 + col+1], acc[mt][j][1]);
        atomicAdd(&g_hlin[(row+8)*48 + col],   acc[mt][j][2]);
        atomicAdd(&g_hlin[(row+8)*48 + col+1], acc[mt][j][3]);
    }
}

__global__ void k_hyp_fin(const float* __restrict__ hypb) {
    int idx = blockIdx.x*blockDim.x + threadIdx.x;
    if (idx >= NN*TT) return;
    int t = idx % TT, n = idx / TT;
    float s = 0.f;
    #pragma unroll
    for (int f = 0; f < 4; ++f) s += g_hlin[n*48 + t*4 + f] + hypb[t*4 + f];
    g_fs[n*TT + t] = s;
}

__global__ void __launch_bounds__(256) k_gemm64_mma(
        const float* __restrict__ X, const float* __restrict__ W,
        const float* __restrict__ bias, float* __restrict__ Y, int relu) {
    __shared__ float Xs[128][36];
    __shared__ float Ws[32][72];
    int r0 = blockIdx.x * 128;
    int tid = threadIdx.x;
    int warp = tid >> 5, lane = tid & 31;
    float acc[8][4];
    #pragma unroll
    for (int j=0;j<8;++j) for (int q=0;q<4;++q) acc[j][q]=0.f;
    for (int kc = 0; kc < 64; kc += 32) {
        #pragma unroll
        for (int i = 0; i < 4; ++i) {
            int idx = tid + i*256;
            int row = idx >> 3;
            int c4 = (idx & 7) * 4;
            *(float4*)&Xs[row][c4] = tf32x4(*(const float4*)&X[(size_t)(r0+row)*64 + kc + c4]);
        }
        #pragma unroll
        for (int i = 0; i < 2; ++i) {
            int idx = tid + i*256;
            int krow = idx >> 4;
            int c4 = (idx & 15) * 4;
            *(float4*)&Ws[krow][c4] = tf32x4(*(const float4*)&W[(size_t)(kc+krow)*64 + c4]);
        }
        __syncthreads();
        #pragma unroll
        for (int k8 = 0; k8 < 32; k8 += 8) {
            uint32_t a[4];
            int ar = warp*16 + (lane>>2);
            int ac = k8 + (lane&3);
            a[0] = __float_as_uint(Xs[ar][ac]);
            a[1] = __float_as_uint(Xs[ar+8][ac]);
            a[2] = __float_as_uint(Xs[ar][ac+4]);
            a[3] = __float_as_uint(Xs[ar+8][ac+4]);
            #pragma unroll
            for (int j = 0; j < 8; ++j) {
                uint32_t b0 = __float_as_uint(Ws[k8 + (lane&3)][j*8 + (lane>>2)]);
                uint32_t b1 = __float_as_uint(Ws[k8 + (lane&3) + 4][j*8 + (lane>>2)]);
                mma_tf32(acc[j], a, b0, b1);
            }
        }
        __syncthreads();
    }
    int row = r0 + warp*16 + (lane>>2);
    #pragma unroll
    for (int j = 0; j < 8; ++j) {
        int col = j*8 + (lane&3)*2;
        float b0 = bias ? bias[col] : 0.f, b1 = bias ? bias[col+1] : 0.f;
        float v0 = acc[j][0] + b0, v1 = acc[j][1] + b1;
        float v2 = acc[j][2] + b0, v3 = acc[j][3] + b1;
        if (relu) { v0=fmaxf(v0,0.f); v1=fmaxf(v1,0.f); v2=fmaxf(v2,0.f); v3=fmaxf(v3,0.f); }
        *(float2*)&Y[(size_t)row*64 + col] = make_float2(v0, v1);
        *(float2*)&Y[(size_t)(row+8)*64 + col] = make_float2(v2, v3);
    }
}

__global__ void k_attn(const float* __restrict__ bv) {
    __shared__ float qs[12][64], ks[12][64], vs[12][64];
    __shared__ float sc[2][12][12];
    int bn = blockIdx.x;
    int b = bn >> 9, n = bn & 511;
    int tid = threadIdx.x;
    for (int idx = tid; idx < 12*64; idx += 128) {
        int t = idx >> 6, c = idx & 63;
        size_t g = (((size_t)b*TT + t)*NN + n)*HH + c;
        qs[t][c] = g_q[g];
        ks[t][c] = g_k[g];
        vs[t][c] = g_fs[n*TT + t] * g_v[((size_t)b*NN + n)*64 + c] + bv[c];
    }
    __syncthreads();
    for (int idx = tid; idx < 288; idx += 128) {
        int h = idx / 144, rem = idx - h*144;
        int t = rem / 12, s = rem - t*12;
        float d = 0.f;
        #pragma unroll
        for (int k = 0; k < 32; ++k) d += qs[t][h*32 + k] * ks[s][h*32 + k];
        sc[h][t][s] = d * 0.17677669529663687f;
    }
    __syncthreads();
    if (tid < 24) {
        int h = tid / 12, t = tid - h*12;
        float mx = -1e30f;
        #pragma unroll
        for (int s = 0; s < 12; ++s) mx = fmaxf(mx, sc[h][t][s]);
        float sum = 0.f;
        #pragma unroll
        for (int s = 0; s < 12; ++s) { float e = __expf(sc[h][t][s] - mx); sc[h][t][s] = e; sum += e; }
        float inv = 1.f / sum;
        #pragma unroll
        for (int s = 0; s < 12; ++s) sc[h][t][s] *= inv;
    }
    __syncthreads();
    for (int idx = tid; idx < 768; idx += 128) {
        int h = idx / 384, rem = idx - h*384;
        int t = rem >> 5, d = rem & 31;
        float a = 0.f;
        #pragma unroll
        for (int s = 0; s < 12; ++s) a += sc[h][t][s] * vs[s][h*32 + d];
        g_o[(((size_t)b*TT + t)*NN + n)*HH + h*32 + d] = a;
    }
}

// ---------------- fused tail ----------------
__global__ void __launch_bounds__(256) k_tail(
        const float* __restrict__ o_, const float* __restrict__ res,
        const float* __restrict__ ln1g, const float* __restrict__ ln1b,
        const float* __restrict__ W1, const float* __restrict__ b1,
        const float* __restrict__ W2, const float* __restrict__ b2,
        const float* __restrict__ ln2g, const float* __restrict__ ln2b,
        const float* __restrict__ fcW, const float* __restrict__ fcb,
        float* __restrict__ y) {
    extern __shared__ float smp[];
    float* val = smp;
    float* f1  = smp + 8704;
    float* Ws  = smp + 17408;
    int tid = threadIdx.x, warp = tid >> 5, lane = tid & 31;
    size_t r0 = (size_t)blockIdx.x * 128;

    for (int it = 0; it < 16; ++it) {
        int rl = it*8 + warp;
        size_t row = r0 + rl;
        int c = lane*2;
        float2 a = *(const float2*)&o_[row*64 + c];
        float2 b = *(const float2*)&res[row*64 + c];
        float x0 = a.x + b.x, x1 = a.y + b.y;
        float s = x0 + x1, sq = x0*x0 + x1*x1;
        #pragma unroll
        for (int o = 16; o > 0; o >>= 1) {
            s  += __shfl_xor_sync(0xffffffffu, s, o);
            sq += __shfl_xor_sync(0xffffffffu, sq, o);
        }
        float mu = s * (1.f/64.f);
        float var = sq * (1.f/64.f) - mu*mu;
        float rstd = rsqrtf(var + 1e-5f);
        val[rl*68 + c]   = (x0 - mu) * rstd * ln1g[c]   + ln1b[c];
        val[rl*68 + c+1] = (x1 - mu) * rstd * ln1g[c+1] + ln1b[c+1];
    }
    __syncthreads();

    int rowl = warp*16 + (lane>>2);
    {
        float acc[8][4];
        #pragma unroll
        for (int j=0;j<8;++j){acc[j][0]=0.f;acc[j][1]=0.f;acc[j][2]=0.f;acc[j][3]=0.f;}
        for (int kc = 0; kc < 64; kc += 32) {
            #pragma unroll
            for (int i = 0; i < 2; ++i) {
                int idx = tid + i*256;
                int krow = idx >> 4;
                int c4 = (idx & 15) * 4;
                *(float4*)&Ws[krow*72 + c4] = tf32x4(*(const float4*)&W1[(size_t)(kc+krow)*64 + c4]);
            }
            __syncthreads();
            #pragma unroll
            for (int k8 = 0; k8 < 32; k8 += 8) {
                uint32_t a[4];
                int ac = kc + k8 + (lane&3);
                a[0] = cvu(val[rowl*68 + ac]);
                a[1] = cvu(val[(rowl+8)*68 + ac]);
                a[2] = cvu(val[rowl*68 + ac + 4]);
                a[3] = cvu(val[(rowl+8)*68 + ac + 4]);
                #pragma unroll
                for (int j = 0; j < 8; ++j) {
                    int col = j*8 + (lane>>2);
                    uint32_t b0 = __float_as_uint(Ws[(k8+(lane&3))*72 + col]);
                    uint32_t b1 = __float_as_uint(Ws[(k8+(lane&3)+4)*72 + col]);
                    mma_tf32(acc[j], a, b0, b1);
                }
            }
            __syncthreads();
        }
        #pragma unroll
        for (int j = 0; j < 8; ++j) {
            int col = j*8 + (lane&3)*2;
            float bb0 = b1[col], bb1 = b1[col+1];
            f1[rowl*68 + col]       = fmaxf(acc[j][0] + bb0, 0.f);
            f1[rowl*68 + col+1]     = fmaxf(acc[j][1] + bb1, 0.f);
            f1[(rowl+8)*68 + col]   = fmaxf(acc[j][2] + bb0, 0.f);
            f1[(rowl+8)*68 + col+1] = fmaxf(acc[j][3] + bb1, 0.f);
        }
    }
    __syncthreads();

    {
        float acc[8][4];
        #pragma unroll
        for (int j=0;j<8;++j){acc[j][0]=0.f;acc[j][1]=0.f;acc[j][2]=0.f;acc[j][3]=0.f;}
        for (int kc = 0; kc < 64; kc += 32) {
            #pragma unroll
            for (int i = 0; i < 2; ++i) {
                int idx = tid + i*256;
                int krow = idx >> 4;
                int c4 = (idx & 15) * 4;
                *(float4*)&Ws[krow*72 + c4] = tf32x4(*(const float4*)&W2[(size_t)(kc+krow)*64 + c4]);
            }
            __syncthreads();
            #pragma unroll
            for (int k8 = 0; k8 < 32; k8 += 8) {
                uint32_t a[4];
                int ac = kc + k8 + (lane&3);
                a[0] = cvu(f1[rowl*68 + ac]);
                a[1] = cvu(f1[(rowl+8)*68 + ac]);
                a[2] = cvu(f1[rowl*68 + ac + 4]);
                a[3] = cvu(f1[(rowl+8)*68 + ac + 4]);
                #pragma unroll
                for (int j = 0; j < 8; ++j) {
                    int col = j*8 + (lane>>2);
                    uint32_t b0 = __float_as_uint(Ws[(k8+(lane&3))*72 + col]);
                    uint32_t b1 = __float_as_uint(Ws[(k8+(lane&3)+4)*72 + col]);
                    mma_tf32(acc[j], a, b0, b1);
                }
            }
            __syncthreads();
        }
        float xs0[16], xs1[16];
        float s0=0.f, q0=0.f, s1=0.f, q1=0.f;
        #pragma unroll
        for (int j = 0; j < 8; ++j) {
            #pragma unroll
            for (int cc = 0; cc < 2; ++cc) {
                int col = j*8 + (lane&3)*2 + cc;
                float x0 = acc[j][cc]   + b2[col] + val[rowl*68 + col];
                float x1 = acc[j][2+cc] + b2[col] + val[(rowl+8)*68 + col];
                xs0[j*2+cc] = x0; s0 += x0; q0 += x0*x0;
                xs1[j*2+cc] = x1; s1 += x1; q1 += x1*x1;
            }
        }
        s0 += __shfl_xor_sync(0xffffffffu, s0, 1); s0 += __shfl_xor_sync(0xffffffffu, s0, 2);
        q0 += __shfl_xor_sync(0xffffffffu, q0, 1); q0 += __shfl_xor_sync(0xffffffffu, q0, 2);
        s1 += __shfl_xor_sync(0xffffffffu, s1, 1); s1 += __shfl_xor_sync(0xffffffffu, s1, 2);
        q1 += __shfl_xor_sync(0xffffffffu, q1, 1); q1 += __shfl_xor_sync(0xffffffffu, q1, 2);
        float mu0 = s0*(1.f/64.f), rstd0 = rsqrtf(q0*(1.f/64.f) - mu0*mu0 + 1e-5f);
        float mu1 = s1*(1.f/64.f), rstd1 = rsqrtf(q1*(1.f/64.f) - mu1*mu1 + 1e-5f);
        float y0 = 0.f, y1 = 0.f;
        #pragma unroll
        for (int j = 0; j < 8; ++j) {
            #pragma unroll
            for (int cc = 0; cc < 2; ++cc) {
                int col = j*8 + (lane&3)*2 + cc;
                float g = ln2g[col], be = ln2b[col], fw = fcW[col];
                y0 += ((xs0[j*2+cc] - mu0)*rstd0*g + be) * fw;
                y1 += ((xs1[j*2+cc] - mu1)*rstd1*g + be) * fw;
            }
        }
        y0 += __shfl_xor_sync(0xffffffffu, y0, 1); y0 += __shfl_xor_sync(0xffffffffu, y0, 2);
        y1 += __shfl_xor_sync(0xffffffffu, y1, 1); y1 += __shfl_xor_sync(0xffffffffu, y1, 2);
        if ((lane & 3) == 0) {
            float fb = fcb[0];
            y[r0 + rowl]     = y0 + fb;
            y[r0 + rowl + 8] = y1 + fb;
        }
    }
}

// ---------------- host ----------------
extern "C" void kernel_launch(void* const* d_in, const int* in_sizes, int n_in,
                              void* d_out, int out_size) {
    const float* src  = (const float*)d_in[0];
    const float* emb  = (const float*)d_in[2];
    const float* gwp0 = (const float*)d_in[3];
    const float* gbp0 = (const float*)d_in[4];
    const float* uwp0 = (const float*)d_in[5];
    const float* ubp0 = (const float*)d_in[6];
    const float* gwp1 = (const float*)d_in[7];
    const float* gbp1 = (const float*)d_in[8];
    const float* uwp1 = (const float*)d_in[9];
    const float* ubp1 = (const float*)d_in[10];
    const float* hypW = (const float*)d_in[11];
    const float* hypb = (const float*)d_in[12];

    const float *Wq,*Wk,*Wv,*ffW1,*ffW2,*bq,*bk,*bv,*ffb1,*ffb2,*ln1g,*ln1b,*ln2g,*ln2b,*fcW,*fcb;
    if (n_in > 14 && in_sizes[14] == 64) {
        Wq  = (const float*)d_in[13]; bq  = (const float*)d_in[14];
        Wk  = (const float*)d_in[15]; bk  = (const float*)d_in[16];
        Wv  = (const float*)d_in[17]; bv  = (const float*)d_in[18];
        ln1g= (const float*)d_in[19]; ln1b= (const float*)d_in[20];
        ffW1= (const float*)d_in[21]; ffb1= (const float*)d_in[22];
        ffW2= (const float*)d_in[23]; ffb2= (const float*)d_in[24];
        ln2g= (const float*)d_in[25]; ln2b= (const float*)d_in[26];
        fcW = (const float*)d_in[27]; fcb = (const float*)d_in[28];
    } else {
        Wq  = (const float*)d_in[13]; Wk  = (const float*)d_in[14];
        Wv  = (const float*)d_in[15]; ffW1= (const float*)d_in[16];
        ffW2= (const float*)d_in[17]; bq  = (const float*)d_in[18];
        bk  = (const float*)d_in[19]; bv  = (const float*)d_in[20];
        ffb1= (const float*)d_in[21]; ffb2= (const float*)d_in[22];
        ln1g= (const float*)d_in[23]; ln1b= (const float*)d_in[24];
        ln2g= (const float*)d_in[25]; ln2b= (const float*)d_in[26];
        fcW = (const float*)d_in[27]; fcb = (const float*)d_in[28];
    }

    float *p_gW,*p_gb,*p_uW,*p_ub,*p_cg,*p_cu,*p_mxt,*p_xt0t;
    float *p_hs0,*p_hs1,*p_hv,*p_q,*p_k,*p_v,*p_o;
    __half *p_gWh,*p_uWh,*p_hs0h,*p_mxth;
    cudaGetSymbolAddress((void**)&p_gW, g_gW);
    cudaGetSymbolAddress((void**)&p_gb, g_gb);
    cudaGetSymbolAddress((void**)&p_uW, g_uW);
    cudaGetSymbolAddress((void**)&p_ub, g_ub);
    cudaGetSymbolAddress((void**)&p_gWh, g_gWh);
    cudaGetSymbolAddress((void**)&p_uWh, g_uWh);
    cudaGetSymbolAddress((void**)&p_cg, g_cg);
    cudaGetSymbolAddress((void**)&p_cu, g_cu);
    cudaGetSymbolAddress((void**)&p_mxt, g_mxt);
    cudaGetSymbolAddress((void**)&p_mxth, g_mxth);
    cudaGetSymbolAddress((void**)&p_xt0t, g_xt0t);
    cudaGetSymbolAddress((void**)&p_hs0, g_hs0);
    cudaGetSymbolAddress((void**)&p_hs0h, g_hs0h);
    cudaGetSymbolAddress((void**)&p_hs1, g_hs1);
    cudaGetSymbolAddress((void**)&p_hv, g_hv);
    cudaGetSymbolAddress((void**)&p_q, g_q);
    cudaGetSymbolAddress((void**)&p_k, g_k);
    cudaGetSymbolAddress((void**)&p_v, g_v);
    cudaGetSymbolAddress((void**)&p_o, g_o);

    cudaFuncSetAttribute(k_recur, cudaFuncAttributeMaxDynamicSharedMemorySize, RECUR_SMEM);
    cudaFuncSetAttribute(k_tail, cudaFuncAttributeMaxDynamicSharedMemorySize, TAIL_SMEM);
    cudaFuncSetAttribute(k_precomp_mma16, cudaFuncAttributeMaxDynamicSharedMemorySize, PRE16_SMEM);

    for (int layer = 0; layer < 2; ++layer) {
        int Cin = (layer == 0) ? 2 : 64;
        int C = Cin + HH;
        int SgW4 = 2*C*128/4, SuW4 = 2*C*64/4;
        int work = NN*(SgW4 + 32 + SuW4 + 16) + ((layer == 0) ? ZT*NN*2 : 0);
        int grid = NN + (work + 255)/256;
        float* hs_out;
        float* hv_out;
        __half* hsh_out;
        if (layer == 0) {
            k_fused_pre<<<grid, 256>>>(emb, gwp0, gbp0, uwp0, ubp0,
                                       p_gW, p_gb, p_uW, p_ub, p_gWh, p_uWh, SgW4, SuW4,
                                       src, p_xt0t, 1);
            k_mix64<<<dim3(8, (ZT*2)/64), 256>>>(p_xt0t, p_mxt);
            k_precomp<<<dim3(NN, 6), 192>>>(src, p_mxt, p_gW, p_uW, p_gb, p_ub, p_cg, p_cu, Cin);
            hs_out = p_hs0; hv_out = nullptr; hsh_out = p_hs0h;
        } else {
            k_fused_pre<<<grid, 256>>>(emb, gwp1, gbp1, uwp1, ubp1,
                                       p_gW, p_gb, p_uW, p_ub, p_gWh, p_uWh, SgW4, SuW4,
                                       nullptr, nullptr, 0);
            k_mix64h<<<dim3(8, ZT), 256>>>(p_hs0h, p_mxth);
            k_precomp_mma16<<<dim3(NN, 3), 256, PRE16_SMEM>>>(p_hs0h, p_mxth, p_gWh, p_uWh,
                                                              p_gb, p_ub, p_cg, p_cu);
            hs_out = p_hs1; hv_out = p_hv; hsh_out = nullptr;
        }
        unsigned nbar0 = (layer == 0) ? 0u : 45u;
        k_recur<<<GRID_P, 256, RECUR_SMEM>>>(p_gWh, p_uWh, p_cg, p_cu, hs_out, C, Cin, nbar0,
                                             hv_out, hsh_out);
    }

    k_hyp_mma<<<dim3(4, 16), 256>>>(hypW);
    k_hyp_fin<<<(NN*TT + 255)/256, 256>>>(hypb);

    k_gemm64_mma<<<BTN/128, 256>>>(p_hs1, Wq, bq, p_q, 0);
    k_gemm64_mma<<<BTN/128, 256>>>(p_hs1, Wk, bk, p_k, 0);
    k_gemm64_mma<<<BB*NN/128, 256>>>(p_hv, Wv, nullptr, p_v, 0);

    k_attn<<<BB*NN, 128>>>(bv);

    k_tail<<<BTN/128, 256, TAIL_SMEM>>>(p_o, p_hs1, ln1g, ln1b,
                                        ffW1, ffb1, ffW2, ffb2,
                                        ln2g, ln2b, fcW, fcb, (float*)d_out);
}

// round 17
// speedup vs baseline: 1.2617x; 1.0029x over previous
#include <cuda_runtime.h>
#include <cuda_fp16.h>
#include <math.h>
#include <stdint.h>

#define BB 32
#define TT 12
#define NN 512
#define HH 64
#define EE 16
#define BTN (BB*TT*NN)
#define BTNH (BTN*HH)
#define ZT (BB*TT)
#define GRID_P 256
#define RECUR_SMEM 26112
#define TAIL_SMEM  78848
#define PRE16_SMEM 47616

__device__ float g_adj[NN*NN];
__device__ __half g_adjh[NN*NN];
__device__ float g_gW[NN*2*128*128];
__device__ __half g_gWh[NN*2*128*128];
__device__ float g_gb[NN*128];
__device__ float g_uW[NN*2*128*64];
__device__ __half g_uWh[NN*2*128*64];
__device__ float g_ub[NN*64];
__device__ float g_state[BB*NN*HH];
__device__ __half g_sh[BB*NN*HH];
__device__ __half g_zsh[BB*NN*HH];
__device__ __half g_mixsh[BB*NN*HH];
__device__ __half g_mixzsh[BB*NN*HH];
__device__ float g_r[BB*NN*HH];
__device__ float g_cg[TT*BB*NN*128];
__device__ float g_cu[TT*BB*NN*64];
__device__ float g_mxt[ZT*NN*64];
__device__ __half g_mxth[ZT*NN*64];
__device__ float g_xt0t[TT*NN*64];
__device__ float g_hs0[BTNH];
__device__ __half g_hs0h[BTNH];
__device__ float g_hs1[BTNH];
__device__ float g_fs[NN*TT];
__device__ float g_hlin[NN*48];
__device__ float g_hv[BB*NN*HH];
__device__ float g_q[BTNH];
__device__ float g_k[BTNH];
__device__ float g_v[BB*NN*HH];
__device__ float g_o[BTNH];
__device__ unsigned g_barc[256];   // 8 counters, stride 32 (128B apart)

__device__ __forceinline__ float to_tf32(float x) {
    uint32_t u; asm("cvt.rna.tf32.f32 %0, %1;" : "=r"(u) : "f"(x));
    return __uint_as_float(u);
}
__device__ __forceinline__ uint32_t cvu(float x) {
    uint32_t u; asm("cvt.rna.tf32.f32 %0, %1;" : "=r"(u) : "f"(x));
    return u;
}
__device__ __forceinline__ float4 tf32x4(float4 v) {
    float4 w; w.x=to_tf32(v.x); w.y=to_tf32(v.y); w.z=to_tf32(v.z); w.w=to_tf32(v.w);
    return w;
}
__device__ __forceinline__ void mma_tf32(float* c, const uint32_t* a, uint32_t b0, uint32_t b1) {
    asm volatile("mma.sync.aligned.m16n8k8.row.col.f32.tf32.tf32.f32 "
        "{%0,%1,%2,%3}, {%4,%5,%6,%7}, {%8,%9}, {%0,%1,%2,%3};"
        : "+f"(c[0]), "+f"(c[1]), "+f"(c[2]), "+f"(c[3])
        : "r"(a[0]), "r"(a[1]), "r"(a[2]), "r"(a[3]), "r"(b0), "r"(b1));
}
__device__ __forceinline__ void mma_f16(float* c, const uint32_t* a, uint32_t b0, uint32_t b1) {
    asm volatile("mma.sync.aligned.m16n8k16.row.col.f32.f16.f16.f32 "
        "{%0,%1,%2,%3}, {%4,%5,%6,%7}, {%8,%9}, {%0,%1,%2,%3};"
        : "+f"(c[0]), "+f"(c[1]), "+f"(c[2]), "+f"(c[3])
        : "r"(a[0]), "r"(a[1]), "r"(a[2]), "r"(a[3]), "r"(b0), "r"(b1));
}
__device__ __forceinline__ void ldsm4(uint32_t& r0, uint32_t& r1, uint32_t& r2, uint32_t& r3, uint32_t addr) {
    asm volatile("ldmatrix.sync.aligned.m8n8.x4.shared.b16 {%0,%1,%2,%3}, [%4];"
        : "=r"(r0), "=r"(r1), "=r"(r2), "=r"(r3) : "r"(addr));
}
__device__ __forceinline__ void ldsm4t(uint32_t& r0, uint32_t& r1, uint32_t& r2, uint32_t& r3, uint32_t addr) {
    asm volatile("ldmatrix.sync.aligned.m8n8.x4.trans.shared.b16 {%0,%1,%2,%3}, [%4];"
        : "=r"(r0), "=r"(r1), "=r"(r2), "=r"(r3) : "r"(addr));
}
__device__ __forceinline__ float sigm(float v) { return 1.f / (1.f + __expf(-v)); }
__device__ __forceinline__ float tanhfast(float v) { return 1.f - 2.f / (__expf(2.f*v) + 1.f); }

__device__ __forceinline__ void gbar(unsigned n) {
    __syncthreads();
    if (threadIdx.x == 0) {
        __threadfence();
        atomicAdd(&g_barc[(blockIdx.x & 7) << 5], 1u);
        unsigned target = n * GRID_P;
        for (;;) {
            unsigned s = 0;
            #pragma unroll
            for (int i = 0; i < 8; ++i) s += *(volatile unsigned*)&g_barc[i << 5];
            if (s >= target) break;
            __nanosleep(32);
        }
        __threadfence();
    }
    __syncthreads();
}

// ---------------- fused pre-kernel ----------------
__global__ void k_fused_pre(const float* __restrict__ emb,
                            const float* __restrict__ gwp, const float* __restrict__ gbp,
                            const float* __restrict__ uwp, const float* __restrict__ ubp,
                            float* __restrict__ gW, float* __restrict__ gb,
                            float* __restrict__ uW, float* __restrict__ ub,
                            __half* __restrict__ gWh, __half* __restrict__ uWh,
                            int SgW4, int SuW4,
                            const float* __restrict__ src, float* __restrict__ xt0,
                            int do_adj) {
    __shared__ float semb[NN*EE];
    __shared__ float row[NN];
    __shared__ float red[256];
    if (blockIdx.x < NN) {
        if (!do_adj) return;
        if (blockIdx.x == 0 && threadIdx.x < 8) g_barc[threadIdx.x << 5] = 0u;
        for (int i = blockIdx.x*256 + threadIdx.x; i < NN*48; i += NN*256) g_hlin[i] = 0.f;
        int n = blockIdx.x;
        for (int i = threadIdx.x; i < NN*EE; i += 256) semb[i] = emb[i];
        __syncthreads();
        float lmax = -1e30f;
        for (int m = threadIdx.x; m < NN; m += 256) {
            float s = 0.f;
            #pragma unroll
            for (int e = 0; e < EE; ++e) s += semb[n*EE+e] * semb[m*EE+e];
            s = fmaxf(s, 0.f);
            row[m] = s;
            lmax = fmaxf(lmax, s);
        }
        red[threadIdx.x] = lmax; __syncthreads();
        for (int s = 128; s > 0; s >>= 1) {
            if (threadIdx.x < s) red[threadIdx.x] = fmaxf(red[threadIdx.x], red[threadIdx.x+s]);
            __syncthreads();
        }
        float mx = red[0];
        __syncthreads();
        float lsum = 0.f;
        for (int m = threadIdx.x; m < NN; m += 256) {
            float v = expf(row[m] - mx);
            row[m] = v; lsum += v;
        }
        red[threadIdx.x] = lsum; __syncthreads();
        for (int s = 128; s > 0; s >>= 1) {
            if (threadIdx.x < s) red[threadIdx.x] += red[threadIdx.x+s];
            __syncthreads();
        }
        float inv = 1.f / red[0];
        for (int m = threadIdx.x; m < NN; m += 256) {
            float a = row[m] * inv;
            g_adj[n*NN + m] = to_tf32(a);
            g_adjh[n*NN + m] = __float2half_rn(a);
        }
        return;
    }
    int idx = (blockIdx.x - NN)*256 + threadIdx.x;
    int t0 = NN*SgW4, t1 = t0 + NN*32, t2 = t1 + NN*SuW4, t3 = t2 + NN*16;
    if (idx < t3) {
        const float* pool; float* out; __half* outh; int S4, local, rnd;
        if (idx < t0)      { pool = gwp; out = gW; outh = gWh; S4 = SgW4; local = idx;      rnd = 1; }
        else if (idx < t1) { pool = gbp; out = gb; outh = 0;   S4 = 32;   local = idx - t0; rnd = 0; }
        else if (idx < t2) { pool = uwp; out = uW; outh = uWh; S4 = SuW4; local = idx - t1; rnd = 1; }
        else               { pool = ubp; out = ub; outh = 0;   S4 = 16;   local = idx - t2; rnd = 0; }
        int n = local / S4, i = local - n*S4;
        float4 a = make_float4(0.f,0.f,0.f,0.f);
        const float* e = emb + n*EE;
        const float4* p4 = (const float4*)pool;
        #pragma unroll
        for (int k = 0; k < EE; ++k) {
            float w = e[k];
            float4 p = p4[(size_t)k*S4 + i];
            a.x += w*p.x; a.y += w*p.y; a.z += w*p.z; a.w += w*p.w;
        }
        if (rnd) {
            ((__half2*)outh)[local*2]   = __floats2half2_rn(a.x, a.y);
            ((__half2*)outh)[local*2+1] = __floats2half2_rn(a.z, a.w);
            a = tf32x4(a);
        }
        ((float4*)out)[local] = a;
    } else if (src) {
        int t = idx - t3;
        if (t < ZT*NN*2) {
            int c = t & 1, m = (t >> 1) & 511, z = t >> 10;
            int g = z*2 + c;
            xt0[((size_t)(g>>6)*NN + m)*64 + (g&63)] = src[t];
        }
    }
}

// ---------------- fp32 tf32 mix tile (layer-0 premix only) ----------------
__device__ __forceinline__ void mix_tile(const float* __restrict__ X, float* __restrict__ Y,
                                         float* sm, int tid, int z, int r0) {
    int warp = tid >> 5, lane = tid & 31;
    int wm = warp >> 1, wn = warp & 1;
    const float* Xb = X + (size_t)z * (NN*64);
    float* Yb = Y + (size_t)z * (NN*64);
    float acc[4][4];
    #pragma unroll
    for (int j=0;j<4;++j){acc[j][0]=0.f;acc[j][1]=0.f;acc[j][2]=0.f;acc[j][3]=0.f;}
    float4 ar0, ar1, xr0, xr1;
    int i0 = tid, i1 = tid + 256;
    ar0 = *(const float4*)&g_adj[(size_t)(r0 + (i0>>3))*NN + (i0&7)*4];
    ar1 = *(const float4*)&g_adj[(size_t)(r0 + (i1>>3))*NN + (i1&7)*4];
    xr0 = *(const float4*)&Xb[(size_t)(i0>>4)*64 + (i0&15)*4];
    xr1 = *(const float4*)&Xb[(size_t)(i1>>4)*64 + (i1&15)*4];
    {
        float* As = sm; float* Xs = sm + 4608;
        *(float4*)&As[(i0>>3)*36 + (i0&7)*4] = ar0;
        *(float4*)&As[(i1>>3)*36 + (i1&7)*4] = ar1;
        *(float4*)&Xs[(i0>>4)*72 + (i0&15)*4] = tf32x4(xr0);
        *(float4*)&Xs[(i1>>4)*72 + (i1&15)*4] = tf32x4(xr1);
    }
    for (int c = 0; c < 16; ++c) {
        __syncthreads();
        if (c < 15) {
            int kc = (c+1)*32;
            ar0 = *(const float4*)&g_adj[(size_t)(r0 + (i0>>3))*NN + kc + (i0&7)*4];
            ar1 = *(const float4*)&g_adj[(size_t)(r0 + (i1>>3))*NN + kc + (i1&7)*4];
            xr0 = *(const float4*)&Xb[(size_t)(kc + (i0>>4))*64 + (i0&15)*4];
            xr1 = *(const float4*)&Xb[(size_t)(kc + (i1>>4))*64 + (i1&15)*4];
        }
        float* As = sm + (c&1)*2304;
        float* Xs = sm + 4608 + (c&1)*2304;
        #pragma unroll
        for (int k8 = 0; k8 < 32; k8 += 8) {
            uint32_t a[4];
            int arow = wm*16 + (lane>>2);
            int ac = k8 + (lane&3);
            a[0] = __float_as_uint(As[arow*36 + ac]);
            a[1] = __float_as_uint(As[(arow+8)*36 + ac]);
            a[2] = __float_as_uint(As[arow*36 + ac + 4]);
            a[3] = __float_as_uint(As[(arow+8)*36 + ac + 4]);
            #pragma unroll
            for (int j = 0; j < 4; ++j) {
                int col = wn*32 + j*8 + (lane>>2);
                uint32_t b0 = __float_as_uint(Xs[(k8+(lane&3))*72 + col]);
                uint32_t b1 = __float_as_uint(Xs[(k8+(lane&3)+4)*72 + col]);
                mma_tf32(acc[j], a, b0, b1);
            }
        }
        if (c < 15) {
            float* Asn = sm + ((c+1)&1)*2304;
            float* Xsn = sm + 4608 + ((c+1)&1)*2304;
            *(float4*)&Asn[(i0>>3)*36 + (i0&7)*4] = ar0;
            *(float4*)&Asn[(i1>>3)*36 + (i1&7)*4] = ar1;
            *(float4*)&Xsn[(i0>>4)*72 + (i0&15)*4] = tf32x4(xr0);
            *(float4*)&Xsn[(i1>>4)*72 + (i1&15)*4] = tf32x4(xr1);
        }
    }
    int row = r0 + wm*16 + (lane>>2);
    #pragma unroll
    for (int j = 0; j < 4; ++j) {
        int col = wn*32 + j*8 + (lane&3)*2;
        *(float2*)&Yb[(size_t)row*64 + col] = make_float2(acc[j][0], acc[j][1]);
        *(float2*)&Yb[(size_t)(row+8)*64 + col] = make_float2(acc[j][2], acc[j][3]);
    }
}

__global__ void __launch_bounds__(256) k_mix64(const float* __restrict__ X, float* __restrict__ Y) {
    __shared__ float sm[9216];
    mix_tile(X, Y, sm, threadIdx.x, blockIdx.y, blockIdx.x*64);
}

// ---------------- fp16 ldmatrix mix tile (half in, half out) ----------------
__device__ __forceinline__ void mix16(const __half* __restrict__ Xh, __half* __restrict__ Yh,
                                      float* smf, int tid, int z, int r0) {
    char* smb = (char*)smf;
    uint32_t sb = (uint32_t)__cvta_generic_to_shared(smb);
    int warp = tid >> 5, lane = tid & 31;
    int wm = warp >> 1, wn = warp & 1;
    const __half* Xz = Xh + (size_t)z * (NN*64);
    __half* Yb = Yh + (size_t)z * (NN*64);
    float acc[4][4];
    #pragma unroll
    for (int j=0;j<4;++j){acc[j][0]=0.f;acc[j][1]=0.f;acc[j][2]=0.f;acc[j][3]=0.f;}
    int arow = tid >> 2, acolh = (tid & 3) * 8;
    int xrow = tid >> 3, xcolh = (tid & 7) * 8;
    uint4 av = *(const uint4*)&g_adjh[(size_t)(r0 + arow)*NN + acolh];
    uint4 xv = *(const uint4*)&Xz[(size_t)xrow*64 + xcolh];
    *(uint4*)(smb + arow*80 + (tid&3)*16) = av;
    *(uint4*)(smb + 10240 + xrow*144 + (tid&7)*16) = xv;
    uint32_t a_l = (wm*16 + (lane & 15)) * 80 + ((lane >> 4) * 8) * 2;
    uint32_t xk_l = (lane & 7) + ((lane >> 3) & 1) * 8;
    uint32_t xn_l = (lane >> 4) * 8;
    for (int c = 0; c < 16; ++c) {
        __syncthreads();
        if (c < 15) {
            int kc = (c+1)*32;
            av = *(const uint4*)&g_adjh[(size_t)(r0 + arow)*NN + kc + acolh];
            xv = *(const uint4*)&Xz[(size_t)(kc + xrow)*64 + xcolh];
        }
        uint32_t ab = sb + (c&1)*5120;
        uint32_t xb = sb + 10240 + (c&1)*4608;
        #pragma unroll
        for (int kb = 0; kb < 2; ++kb) {
            uint32_t a[4];
            ldsm4(a[0], a[1], a[2], a[3], ab + a_l + kb*32);
            #pragma unroll
            for (int cg = 0; cg < 2; ++cg) {
                int c0 = wn*32 + cg*16;
                uint32_t b0, b1, b2, b3;
                ldsm4t(b0, b1, b2, b3, xb + (kb*16 + xk_l)*144 + (c0 + xn_l)*2);
                mma_f16(acc[cg*2+0], a, b0, b1);
                mma_f16(acc[cg*2+1], a, b2, b3);
            }
        }
        if (c < 15) {
            *(uint4*)(smb + ((c+1)&1)*5120 + arow*80 + (tid&3)*16) = av;
            *(uint4*)(smb + 10240 + ((c+1)&1)*4608 + xrow*144 + (tid&7)*16) = xv;
        }
    }
    int row = r0 + wm*16 + (lane>>2);
    #pragma unroll
    for (int j = 0; j < 4; ++j) {
        int col = wn*32 + j*8 + (lane&3)*2;
        *(__half2*)&Yb[(size_t)row*64 + col] = __floats2half2_rn(acc[j][0], acc[j][1]);
        *(__half2*)&Yb[(size_t)(row+8)*64 + col] = __floats2half2_rn(acc[j][2], acc[j][3]);
    }
}

__global__ void __launch_bounds__(256) k_mix64h(const __half* __restrict__ Xh, __half* __restrict__ Yh) {
    __shared__ float sm[4864];
    mix16(Xh, Yh, sm, threadIdx.x, blockIdx.y, blockIdx.x*64);
}

// ---------------- fp16 gate phase ----------------
__device__ __forceinline__ void phase_gate(const __half* __restrict__ gWh, const float* __restrict__ cg_t,
                                           int C, int Cin, float* smf, int tid) {
    char* smb = (char*)smf;
    uint32_t sb = (uint32_t)__cvta_generic_to_shared(smb);
    int warp = tid >> 5, lane = tid & 31;
    int wm = warp >> 2, wn = warp & 3;
    uint32_t a_l = (wm*16 + (lane & 15)) * 272 + ((lane >> 4) * 8) * 2;
    uint32_t xk_l = (lane & 7) + ((lane >> 3) & 1) * 8;
    uint32_t xn_l = (lane >> 4) * 8;
    for (int n = blockIdx.x; n < NN; n += GRID_P) {
        __syncthreads();
        #pragma unroll
        for (int i = 0; i < 2; ++i) {
            int idx = tid + i*256;
            int row = idx >> 4, h8 = idx & 15;
            uint4 v = (h8 < 8)
                ? *(const uint4*)&g_sh[((size_t)row*NN + n)*64 + h8*8]
                : *(const uint4*)&g_mixsh[((size_t)row*NN + n)*64 + (h8-8)*8];
            *(uint4*)(smb + row*272 + h8*16) = v;
        }
        #pragma unroll
        for (int i = 0; i < 2; ++i) {
            int idx = tid + i*256;
            int kk = idx >> 4, h8 = idx & 15;
            *(uint4*)(smb + 8704 + kk*272 + h8*16) =
                *(const uint4*)&gWh[((size_t)(2*n)*C + Cin + kk)*128 + h8*8];
        }
        float acc[4][4];
        #pragma unroll
        for (int j=0;j<4;++j){acc[j][0]=0.f;acc[j][1]=0.f;acc[j][2]=0.f;acc[j][3]=0.f;}
        uint4 bv[2];
        for (int c = 0; c < 4; ++c) {
            __syncthreads();
            if (c < 3) {
                #pragma unroll
                for (int i = 0; i < 2; ++i) {
                    int idx = tid + i*256;
                    int kk = idx >> 4, h8 = idx & 15;
                    int kg = (c+1)*32 + kk;
                    bv[i] = *(const uint4*)&gWh[((size_t)(2*n + (kg>=64))*C + Cin + (kg&63))*128 + h8*8];
                }
            }
            uint32_t bbase = sb + 8704 + (c&1)*8704;
            #pragma unroll
            for (int kb = 0; kb < 2; ++kb) {
                int kg16 = c*32 + kb*16;
                uint32_t a[4];
                ldsm4(a[0], a[1], a[2], a[3], sb + a_l + kg16*2);
                #pragma unroll
                for (int cg = 0; cg < 2; ++cg) {
                    int c0 = wn*32 + cg*16;
                    uint32_t b0, b1, b2, b3;
                    ldsm4t(b0, b1, b2, b3, bbase + (kb*16 + xk_l)*272 + (c0 + xn_l)*2);
                    mma_f16(acc[cg*2+0], a, b0, b1);
                    mma_f16(acc[cg*2+1], a, b2, b3);
                }
            }
            if (c < 3) {
                char* Bsn = smb + 8704 + ((c+1)&1)*8704;
                #pragma unroll
                for (int i = 0; i < 2; ++i) {
                    int idx = tid + i*256;
                    int kk = idx >> 4, h8 = idx & 15;
                    *(uint4*)(Bsn + kk*272 + h8*16) = bv[i];
                }
            }
        }
        const __half* Ah = (const __half*)smb;
        #pragma unroll
        for (int j = 0; j < 4; ++j) {
            int col = wn*32 + j*8 + (lane&3)*2;
            #pragma unroll
            for (int half = 0; half < 2; ++half) {
                int b = wm*16 + (lane>>2) + half*8;
                float v0 = acc[j][half*2], v1 = acc[j][half*2+1];
                size_t base = (size_t)b*NN + n;
                float2 cgv = *(const float2*)&cg_t[base*128 + col];
                v0 += cgv.x; v1 += cgv.y;
                if (col < 64) {
                    float s0 = __half2float(Ah[b*136 + col]);
                    float s1 = __half2float(Ah[b*136 + col + 1]);
                    *(__half2*)&g_zsh[base*64 + col] =
                        __floats2half2_rn(sigm(v0) * s0, sigm(v1) * s1);
                } else {
                    *(float2*)&g_r[base*64 + col - 64] = make_float2(sigm(v0), sigm(v1));
                }
            }
        }
    }
}

// ---------------- fp16 upd phase ----------------
__device__ __forceinline__ void phase_upd(const __half* __restrict__ uWh, const float* __restrict__ cu_t,
                                          int C, int Cin, float* __restrict__ hs, int t,
                                          float* smf, int tid, float* __restrict__ hv,
                                          __half* __restrict__ hsh) {
    char* smb = (char*)smf;
    uint32_t sb = (uint32_t)__cvta_generic_to_shared(smb);
    int warp = tid >> 5, lane = tid & 31;
    int wm = warp >> 2, wn = warp & 3;
    uint32_t a_l = (wm*16 + (lane & 15)) * 272 + ((lane >> 4) * 8) * 2;
    uint32_t xk_l = (lane & 7) + ((lane >> 3) & 1) * 8;
    uint32_t xn_l = (lane >> 4) * 8;
    for (int n = blockIdx.x; n < NN; n += GRID_P) {
        __syncthreads();
        #pragma unroll
        for (int i = 0; i < 2; ++i) {
            int idx = tid + i*256;
            int row = idx >> 4, h8 = idx & 15;
            uint4 v = (h8 < 8)
                ? *(const uint4*)&g_zsh[((size_t)row*NN + n)*64 + h8*8]
                : *(const uint4*)&g_mixzsh[((size_t)row*NN + n)*64 + (h8-8)*8];
            *(uint4*)(smb + row*272 + h8*16) = v;
        }
        {
            int kk = tid >> 3, h8 = tid & 7;
            *(uint4*)(smb + 8704 + kk*144 + h8*16) =
                *(const uint4*)&uWh[((size_t)(2*n)*C + Cin + kk)*64 + h8*8];
        }
        float acc[2][4];
        #pragma unroll
        for (int j=0;j<2;++j){acc[j][0]=0.f;acc[j][1]=0.f;acc[j][2]=0.f;acc[j][3]=0.f;}
        uint4 bv;
        for (int c = 0; c < 4; ++c) {
            __syncthreads();
            if (c < 3) {
                int kk = tid >> 3, h8 = tid & 7;
                int kg = (c+1)*32 + kk;
                bv = *(const uint4*)&uWh[((size_t)(2*n + (kg>=64))*C + Cin + (kg&63))*64 + h8*8];
            }
            uint32_t bbase = sb + 8704 + (c&1)*4608;
            #pragma unroll
            for (int kb = 0; kb < 2; ++kb) {
                int kg16 = c*32 + kb*16;
                uint32_t a[4];
                ldsm4(a[0], a[1], a[2], a[3], sb + a_l + kg16*2);
                uint32_t b0, b1, b2, b3;
                ldsm4t(b0, b1, b2, b3, bbase + (kb*16 + xk_l)*144 + (wn*16 + xn_l)*2);
                mma_f16(acc[0], a, b0, b1);
                mma_f16(acc[1], a, b2, b3);
            }
            if (c < 3) {
                int kk = tid >> 3, h8 = tid & 7;
                *(uint4*)(smb + 8704 + ((c+1)&1)*4608 + kk*144 + h8*16) = bv;
            }
        }
        #pragma unroll
        for (int j = 0; j < 2; ++j) {
            int col = wn*16 + j*8 + (lane&3)*2;
            #pragma unroll
            for (int half = 0; half < 2; ++half) {
                int b = wm*16 + (lane>>2) + half*8;
                float v0 = acc[j][half*2], v1 = acc[j][half*2+1];
                size_t base = (size_t)b*NN + n;
                float2 cuv = *(const float2*)&cu_t[base*64 + col];
                float hc0 = tanhfast(v0 + cuv.x), hc1 = tanhfast(v1 + cuv.y);
                size_t idx = base*64 + col;
                float2 rr = *(const float2*)&g_r[idx];
                float2 st = *(const float2*)&g_state[idx];
                float h0 = rr.x*st.x + (1.f-rr.x)*hc0;
                float h1 = rr.y*st.y + (1.f-rr.y)*hc1;
                *(float2*)&g_state[idx] = make_float2(h0, h1);
                __half2 hh = __floats2half2_rn(h0, h1);
                *(__half2*)&g_sh[idx] = hh;
                size_t hsidx = (((size_t)b*TT + t)*NN + n)*64 + col;
                *(float2*)&hs[hsidx] = make_float2(h0, h1);
                if (hsh) *(__half2*)&hsh[hsidx] = hh;
                if (hv && t == TT-1)
                    *(float2*)&hv[idx] = make_float2(h0, h1);
            }
        }
    }
}

__global__ void __launch_bounds__(256, 2) k_recur(
        const __half* __restrict__ gWh, const __half* __restrict__ uWh,
        const float* __restrict__ cg, const float* __restrict__ cu,
        float* __restrict__ hs, int C, int Cin, unsigned nbar,
        float* __restrict__ hv, __half* __restrict__ hsh) {
    extern __shared__ float sm[];
    int tid = threadIdx.x;
    for (int idx = blockIdx.x*256 + tid; idx < BB*NN*64; idx += GRID_P*256) {
        int c = idx & 63;
        int n = (idx >> 6) & 511;
        int b = idx >> 15;
        size_t base = (size_t)b*NN + n;
        float r = sigm(cg[base*128 + 64 + c]);
        float hc = tanhfast(cu[base*64 + c]);
        float h = (1.f - r) * hc;
        g_state[base*64 + c] = h;
        __half hh = __float2half_rn(h);
        g_sh[base*64 + c] = hh;
        size_t hsidx = (((size_t)b*TT)*NN + n)*64 + c;
        hs[hsidx] = h;
        if (hsh) hsh[hsidx] = hh;
    }
    gbar(++nbar);
    int z = blockIdx.x >> 3;
    int r0 = (blockIdx.x & 7) * 64;
    for (int t = 1; t < TT; ++t) {
        const float* cg_t = cg + (size_t)t*BB*NN*128;
        const float* cu_t = cu + (size_t)t*BB*NN*64;
        mix16(g_sh, g_mixsh, sm, tid, z, r0);
        gbar(++nbar);
        phase_gate(gWh, cg_t, C, Cin, sm, tid);
        gbar(++nbar);
        mix16(g_zsh, g_mixzsh, sm, tid, z, r0);
        gbar(++nbar);
        phase_upd(uWh, cu_t, C, Cin, hs, t, sm, tid, hv, hsh);
        gbar(++nbar);
    }
}

// ---------------- layer-0 precompute (SIMT, Cin=2) ----------------
__global__ void __launch_bounds__(192) k_precomp(
        const float* __restrict__ xt, const float* __restrict__ mxt,
        const float* __restrict__ gW, const float* __restrict__ uW,
        const float* __restrict__ gb, const float* __restrict__ ub,
        float* __restrict__ cg, float* __restrict__ cu, int Cin) {
    const int C = Cin + HH;
    __shared__ float xs[64][2];
    __shared__ float ms[64][2];
    int n = blockIdx.x;
    int r0 = blockIdx.y * 64;
    int tid = threadIdx.x;
    for (int idx = tid; idx < 64*Cin; idx += 192) {
        int r = idx / Cin, c = idx - r*Cin;
        int z = r0 + r;
        xs[r][c] = xt[((size_t)z*NN + n)*Cin + c];
        int g = z*Cin + c;
        ms[r][c] = mxt[((size_t)(g>>6)*NN + n)*64 + (g&63)];
    }
    __syncthreads();
    float a[64];
    #pragma unroll
    for (int i = 0; i < 64; ++i) a[i] = 0.f;
    if (tid < 128) {
        int o = tid;
        const float* W0 = gW + (size_t)(n*2)*C*128 + o;
        const float* W1 = gW + (size_t)(n*2+1)*C*128 + o;
        for (int c = 0; c < Cin; ++c) {
            float w0 = W0[c*128], w1 = W1[c*128];
            #pragma unroll
            for (int r = 0; r < 64; ++r) a[r] += xs[r][c]*w0 + ms[r][c]*w1;
        }
        float bias = gb[n*128 + o];
        for (int r = 0; r < 64; ++r) {
            int z = r0 + r; int b = z / 12, t = z - b*12;
            cg[(((size_t)t*BB + b)*NN + n)*128 + o] = a[r] + bias;
        }
    } else {
        int o = tid - 128;
        const float* W0 = uW + (size_t)(n*2)*C*64 + o;
        const float* W1 = uW + (size_t)(n*2+1)*C*64 + o;
        for (int c = 0; c < Cin; ++c) {
            float w0 = W0[c*64], w1 = W1[c*64];
            #pragma unroll
            for (int r = 0; r < 64; ++r) a[r] += xs[r][c]*w0 + ms[r][c]*w1;
        }
        float bias = ub[n*64 + o];
        for (int r = 0; r < 64; ++r) {
            int z = r0 + r; int b = z / 12, t = z - b*12;
            cu[(((size_t)t*BB + b)*NN + n)*64 + o] = a[r] + bias;
        }
    }
}

// ---------------- layer-1 precompute, fp16 ldmatrix ----------------
__global__ void __launch_bounds__(256) k_precomp_mma16(
        const __half* __restrict__ xth, const __half* __restrict__ mxth,
        const __half* __restrict__ gWh, const __half* __restrict__ uWh,
        const float* __restrict__ gb, const float* __restrict__ ub,
        float* __restrict__ cg, float* __restrict__ cu) {
    const int C = 128;
    extern __shared__ float smf[];
    char* smb = (char*)smf;
    uint32_t sb = (uint32_t)__cvta_generic_to_shared(smb);
    int n = blockIdx.x;
    int m0 = blockIdx.y * 128;
    int tid = threadIdx.x;
    int warp = tid >> 5, lane = tid & 31;
    int wm = warp >> 1, wn = warp & 1;
    #pragma unroll
    for (int i = 0; i < 8; ++i) {
        int idx = tid + i*256;
        int row = idx >> 4, h8 = idx & 15;
        uint4 v = (h8 < 8)
            ? *(const uint4*)&xth[((size_t)(m0+row)*NN + n)*64 + h8*8]
            : *(const uint4*)&mxth[((size_t)(m0+row)*NN + n)*64 + (h8-8)*8];
        *(uint4*)(smb + row*272 + h8*16) = v;
    }
    float acc[2][12][4];
    #pragma unroll
    for (int mt=0;mt<2;++mt) for (int j=0;j<12;++j) for (int q=0;q<4;++q) acc[mt][j][q]=0.f;
    uint32_t xk_l = (lane & 7) + ((lane >> 3) & 1) * 8;
    uint32_t xn_l = (lane >> 4) * 8;
    for (int kc = 0; kc < 4; ++kc) {
        __syncthreads();
        #pragma unroll
        for (int i = 0; i < 3; ++i) {
            int idx = tid + i*256;
            int kk = idx / 24, u = idx % 24;
            int kg = kc*32 + kk;
            int col8 = u*8;
            uint4 v = (col8 < 128)
                ? *(const uint4*)&gWh[((size_t)(2*n + (kg>=64))*C + (kg&63))*128 + col8]
                : *(const uint4*)&uWh[((size_t)(2*n + (kg>=64))*C + (kg&63))*64 + (col8-128)];
            *(uint4*)(smb + 34816 + kk*400 + u*16) = v;
        }
        __syncthreads();
        #pragma unroll
        for (int kb = 0; kb < 2; ++kb) {
            int kg16 = kc*32 + kb*16;
            uint32_t a[2][4];
            #pragma unroll
            for (int mt = 0; mt < 2; ++mt)
                ldsm4(a[mt][0], a[mt][1], a[mt][2], a[mt][3],
                      sb + (wm*32 + mt*16 + (lane & 15))*272 + ((lane >> 4)*8)*2 + kg16*2);
            #pragma unroll
            for (int cg2 = 0; cg2 < 6; ++cg2) {
                int c0 = wn*96 + cg2*16;
                uint32_t b0, b1, b2, b3;
                ldsm4t(b0, b1, b2, b3, sb + 34816 + (kb*16 + xk_l)*400 + (c0 + xn_l)*2);
                mma_f16(acc[0][cg2*2+0], a[0], b0, b1);
                mma_f16(acc[0][cg2*2+1], a[0], b2, b3);
                mma_f16(acc[1][cg2*2+0], a[1], b0, b1);
                mma_f16(acc[1][cg2*2+1], a[1], b2, b3);
            }
        }
    }
    #pragma unroll
    for (int mt = 0; mt < 2; ++mt) {
        #pragma unroll
        for (int j = 0; j < 12; ++j) {
            int col = wn*96 + j*8 + (lane&3)*2;
            #pragma unroll
            for (int half = 0; half < 2; ++half) {
                int z = m0 + wm*32 + mt*16 + (lane>>2) + half*8;
                int b = z / 12, t = z - b*12;
                float v0 = acc[mt][j][half*2], v1 = acc[mt][j][half*2+1];
                if (col < 128) {
                    float2 bb = *(const float2*)&gb[n*128 + col];
                    *(float2*)&cg[(((size_t)t*BB + b)*NN + n)*128 + col] =
                        make_float2(v0 + bb.x, v1 + bb.y);
                } else {
                    int o = col - 128;
                    float2 bb = *(const float2*)&ub[n*64 + o];
                    *(float2*)&cu[(((size_t)t*BB + b)*NN + n)*64 + o] =
                        make_float2(v0 + bb.x, v1 + bb.y);
                }
            }
        }
    }
}

// ---------------- hypernetwork ----------------
__global__ void __launch_bounds__(256) k_hyp_mma(const float* __restrict__ hypW) {
    __shared__ float As[128][36];
    __shared__ float Bs[32][56];
    int m0 = blockIdx.x * 128;
    int k0 = blockIdx.y * 1024;
    int tid = threadIdx.x, warp = tid >> 5, lane = tid & 31;
    int wm = warp >> 1, wn = warp & 1;
    float acc[2][3][4];
    #pragma unroll
    for (int mt=0;mt<2;++mt) for (int j=0;j<3;++j) for (int q=0;q<4;++q) acc[mt][j][q]=0.f;
    for (int kc = k0; kc < k0 + 1024; kc += 32) {
        #pragma unroll
        for (int i = 0; i < 4; ++i) {
            int idx = tid + i*256;
            int row = idx >> 3;
            int c4 = (idx & 7) * 4;
            *(float4*)&As[row][c4] = *(const float4*)&g_uW[(size_t)(m0+row)*16384 + kc + c4];
        }
        if (tid < 128) {
            int krow = tid / 4, c4a = (tid % 4) * 4;
            #pragma unroll
            for (int seg = 0; seg < 3; ++seg) {
                int c4 = c4a + seg*16;
                if (c4 < 48)
                    *(float4*)&Bs[krow][c4] = tf32x4(*(const float4*)&hypW[(size_t)(kc+krow)*48 + c4]);
            }
        }
        __syncthreads();
        #pragma unroll
        for (int k8 = 0; k8 < 32; k8 += 8) {
            uint32_t a[2][4];
            int ac = k8 + (lane&3);
            #pragma unroll
            for (int mt = 0; mt < 2; ++mt) {
                int rr = wm*32 + mt*16 + (lane>>2);
                a[mt][0] = __float_as_uint(As[rr][ac]);
                a[mt][1] = __float_as_uint(As[rr+8][ac]);
                a[mt][2] = __float_as_uint(As[rr][ac+4]);
                a[mt][3] = __float_as_uint(As[rr+8][ac+4]);
            }
            #pragma unroll
            for (int j = 0; j < 3; ++j) {
                int col = wn*24 + j*8 + (lane>>2);
                uint32_t b0 = __float_as_uint(Bs[k8 + (lane&3)][col]);
                uint32_t b1 = __float_as_uint(Bs[k8 + (lane&3) + 4][col]);
                mma_tf32(acc[0][j], a[0], b0, b1);
                mma_tf32(acc[1][j], a[1], b0, b1);
            }
        }
        __syncthreads();
    }
    #pragma unroll
    for (int mt = 0; mt < 2; ++mt)
    #pragma unroll
    for (int j = 0; j < 3; ++j) {
        int col = wn*24 + j*8 + (lane&3)*2;
        int row = m0 + wm*32 + mt*16 + (lane>>2);
        atomicAdd(&g_hlin[row*48 + col],   acc[mt][j][0]);
        atomicAdd(&g_hlin[row*48 + col+1], acc[mt][j][1]);
        atomicAdd(&g_hlin[(row+8)*48 + col],   acc[mt][j][2]);
        atomicAdd(&g_hlin[(row+8)*48 + col+1], acc[mt][j][3]);
    }
}

__global__ void k_hyp_fin(const float* __restrict__ hypb) {
    int idx = blockIdx.x*blockDim.x + threadIdx.x;
    if (idx >= NN*TT) return;
    int t = idx % TT, n = idx / TT;
    float s = 0.f;
    #pragma unroll
    for (int f = 0; f < 4; ++f) s += g_hlin[n*48 + t*4 + f] + hypb[t*4 + f];
    g_fs[n*TT + t] = s;
}

__global__ void __launch_bounds__(256) k_gemm64_mma(
        const float* __restrict__ X, const float* __restrict__ W,
        const float* __restrict__ bias, float* __restrict__ Y, int relu) {
    __shared__ float Xs[128][36];
    __shared__ float Ws[32][72];
    int r0 = blockIdx.x * 128;
    int tid = threadIdx.x;
    int warp = tid >> 5, lane = tid & 31;
    float acc[8][4];
    #pragma unroll
    for (int j=0;j<8;++j) for (int q=0;q<4;++q) acc[j][q]=0.f;
    for (int kc = 0; kc < 64; kc += 32) {
        #pragma unroll
        for (int i = 0; i < 4; ++i) {
            int idx = tid + i*256;
            int row = idx >> 3;
            int c4 = (idx & 7) * 4;
            *(float4*)&Xs[row][c4] = tf32x4(*(const float4*)&X[(size_t)(r0+row)*64 + kc + c4]);
        }
        #pragma unroll
        for (int i = 0; i < 2; ++i) {
            int idx = tid + i*256;
            int krow = idx >> 4;
            int c4 = (idx & 15) * 4;
            *(float4*)&Ws[krow][c4] = tf32x4(*(const float4*)&W[(size_t)(kc+krow)*64 + c4]);
        }
        __syncthreads();
        #pragma unroll
        for (int k8 = 0; k8 < 32; k8 += 8) {
            uint32_t a[4];
            int ar = warp*16 + (lane>>2);
            int ac = k8 + (lane&3);
            a[0] = __float_as_uint(Xs[ar][ac]);
            a[1] = __float_as_uint(Xs[ar+8][ac]);
            a[2] = __float_as_uint(Xs[ar][ac+4]);
            a[3] = __float_as_uint(Xs[ar+8][ac+4]);
            #pragma unroll
            for (int j = 0; j < 8; ++j) {
                uint32_t b0 = __float_as_uint(Ws[k8 + (lane&3)][j*8 + (lane>>2)]);
                uint32_t b1 = __float_as_uint(Ws[k8 + (lane&3) + 4][j*8 + (lane>>2)]);
                mma_tf32(acc[j], a, b0, b1);
            }
        }
        __syncthreads();
    }
    int row = r0 + warp*16 + (lane>>2);
    #pragma unroll
    for (int j = 0; j < 8; ++j) {
        int col = j*8 + (lane&3)*2;
        float b0 = bias ? bias[col] : 0.f, b1 = bias ? bias[col+1] : 0.f;
        float v0 = acc[j][0] + b0, v1 = acc[j][1] + b1;
        float v2 = acc[j][2] + b0, v3 = acc[j][3] + b1;
        if (relu) { v0=fmaxf(v0,0.f); v1=fmaxf(v1,0.f); v2=fmaxf(v2,0.f); v3=fmaxf(v3,0.f); }
        *(float2*)&Y[(size_t)row*64 + col] = make_float2(v0, v1);
        *(float2*)&Y[(size_t)(row+8)*64 + col] = make_float2(v2, v3);
    }
}

__global__ void k_attn(const float* __restrict__ bv) {
    __shared__ float qs[12][64], ks[12][64], vs[12][64];
    __shared__ float sc[2][12][12];
    int bn = blockIdx.x;
    int b = bn >> 9, n = bn & 511;
    int tid = threadIdx.x;
    for (int idx = tid; idx < 12*64; idx += 128) {
        int t = idx >> 6, c = idx & 63;
        size_t g = (((size_t)b*TT + t)*NN + n)*HH + c;
        qs[t][c] = g_q[g];
        ks[t][c] = g_k[g];
        vs[t][c] = g_fs[n*TT + t] * g_v[((size_t)b*NN + n)*64 + c] + bv[c];
    }
    __syncthreads();
    for (int idx = tid; idx < 288; idx += 128) {
        int h = idx / 144, rem = idx - h*144;
        int t = rem / 12, s = rem - t*12;
        float d = 0.f;
        #pragma unroll
        for (int k = 0; k < 32; ++k) d += qs[t][h*32 + k] * ks[s][h*32 + k];
        sc[h][t][s] = d * 0.17677669529663687f;
    }
    __syncthreads();
    if (tid < 24) {
        int h = tid / 12, t = tid - h*12;
        float mx = -1e30f;
        #pragma unroll
        for (int s = 0; s < 12; ++s) mx = fmaxf(mx, sc[h][t][s]);
        float sum = 0.f;
        #pragma unroll
        for (int s = 0; s < 12; ++s) { float e = __expf(sc[h][t][s] - mx); sc[h][t][s] = e; sum += e; }
        float inv = 1.f / sum;
        #pragma unroll
        for (int s = 0; s < 12; ++s) sc[h][t][s] *= inv;
    }
    __syncthreads();
    for (int idx = tid; idx < 768; idx += 128) {
        int h = idx / 384, rem = idx - h*384;
        int t = rem >> 5, d = rem & 31;
        float a = 0.f;
        #pragma unroll
        for (int s = 0; s < 12; ++s) a += sc[h][t][s] * vs[s][h*32 + d];
        g_o[(((size_t)b*TT + t)*NN + n)*HH + h*32 + d] = a;
    }
}

// ---------------- fused tail ----------------
__global__ void __launch_bounds__(256) k_tail(
        const float* __restrict__ o_, const float* __restrict__ res,
        const float* __restrict__ ln1g, const float* __restrict__ ln1b,
        const float* __restrict__ W1, const float* __restrict__ b1,
        const float* __restrict__ W2, const float* __restrict__ b2,
        const float* __restrict__ ln2g, const float* __restrict__ ln2b,
        const float* __restrict__ fcW, const float* __restrict__ fcb,
        float* __restrict__ y) {
    extern __shared__ float smp[];
    float* val = smp;
    float* f1  = smp + 8704;
    float* Ws  = smp + 17408;
    int tid = threadIdx.x, warp = tid >> 5, lane = tid & 31;
    size_t r0 = (size_t)blockIdx.x * 128;

    for (int it = 0; it < 16; ++it) {
        int rl = it*8 + warp;
        size_t row = r0 + rl;
        int c = lane*2;
        float2 a = *(const float2*)&o_[row*64 + c];
        float2 b = *(const float2*)&res[row*64 + c];
        float x0 = a.x + b.x, x1 = a.y + b.y;
        float s = x0 + x1, sq = x0*x0 + x1*x1;
        #pragma unroll
        for (int o = 16; o > 0; o >>= 1) {
            s  += __shfl_xor_sync(0xffffffffu, s, o);
            sq += __shfl_xor_sync(0xffffffffu, sq, o);
        }
        float mu = s * (1.f/64.f);
        float var = sq * (1.f/64.f) - mu*mu;
        float rstd = rsqrtf(var + 1e-5f);
        val[rl*68 + c]   = (x0 - mu) * rstd * ln1g[c]   + ln1b[c];
        val[rl*68 + c+1] = (x1 - mu) * rstd * ln1g[c+1] + ln1b[c+1];
    }
    __syncthreads();

    int rowl = warp*16 + (lane>>2);
    {
        float acc[8][4];
        #pragma unroll
        for (int j=0;j<8;++j){acc[j][0]=0.f;acc[j][1]=0.f;acc[j][2]=0.f;acc[j][3]=0.f;}
        for (int kc = 0; kc < 64; kc += 32) {
            #pragma unroll
            for (int i = 0; i < 2; ++i) {
                int idx = tid + i*256;
                int krow = idx >> 4;
                int c4 = (idx & 15) * 4;
                *(float4*)&Ws[krow*72 + c4] = tf32x4(*(const float4*)&W1[(size_t)(kc+krow)*64 + c4]);
            }
            __syncthreads();
            #pragma unroll
            for (int k8 = 0; k8 < 32; k8 += 8) {
                uint32_t a[4];
                int ac = kc + k8 + (lane&3);
                a[0] = cvu(val[rowl*68 + ac]);
                a[1] = cvu(val[(rowl+8)*68 + ac]);
                a[2] = cvu(val[rowl*68 + ac + 4]);
                a[3] = cvu(val[(rowl+8)*68 + ac + 4]);
                #pragma unroll
                for (int j = 0; j < 8; ++j) {
                    int col = j*8 + (lane>>2);
                    uint32_t b0 = __float_as_uint(Ws[(k8+(lane&3))*72 + col]);
                    uint32_t b1 = __float_as_uint(Ws[(k8+(lane&3)+4)*72 + col]);
                    mma_tf32(acc[j], a, b0, b1);
                }
            }
            __syncthreads();
        }
        #pragma unroll
        for (int j = 0; j < 8; ++j) {
            int col = j*8 + (lane&3)*2;
            float bb0 = b1[col], bb1 = b1[col+1];
            f1[rowl*68 + col]       = fmaxf(acc[j][0] + bb0, 0.f);
            f1[rowl*68 + col+1]     = fmaxf(acc[j][1] + bb1, 0.f);
            f1[(rowl+8)*68 + col]   = fmaxf(acc[j][2] + bb0, 0.f);
            f1[(rowl+8)*68 + col+1] = fmaxf(acc[j][3] + bb1, 0.f);
        }
    }
    __syncthreads();

    {
        float acc[8][4];
        #pragma unroll
        for (int j=0;j<8;++j){acc[j][0]=0.f;acc[j][1]=0.f;acc[j][2]=0.f;acc[j][3]=0.f;}
        for (int kc = 0; kc < 64; kc += 32) {
            #pragma unroll
            for (int i = 0; i < 2; ++i) {
                int idx = tid + i*256;
                int krow = idx >> 4;
                int c4 = (idx & 15) * 4;
                *(float4*)&Ws[krow*72 + c4] = tf32x4(*(const float4*)&W2[(size_t)(kc+krow)*64 + c4]);
            }
            __syncthreads();
            #pragma unroll
            for (int k8 = 0; k8 < 32; k8 += 8) {
                uint32_t a[4];
                int ac = kc + k8 + (lane&3);
                a[0] = cvu(f1[rowl*68 + ac]);
                a[1] = cvu(f1[(rowl+8)*68 + ac]);
                a[2] = cvu(f1[rowl*68 + ac + 4]);
                a[3] = cvu(f1[(rowl+8)*68 + ac + 4]);
                #pragma unroll
                for (int j = 0; j < 8; ++j) {
                    int col = j*8 + (lane>>2);
                    uint32_t b0 = __float_as_uint(Ws[(k8+(lane&3))*72 + col]);
                    uint32_t b1 = __float_as_uint(Ws[(k8+(lane&3)+4)*72 + col]);
                    mma_tf32(acc[j], a, b0, b1);
                }
            }
            __syncthreads();
        }
        float xs0[16], xs1[16];
        float s0=0.f, q0=0.f, s1=0.f, q1=0.f;
        #pragma unroll
        for (int j = 0; j < 8; ++j) {
            #pragma unroll
            for (int cc = 0; cc < 2; ++cc) {
                int col = j*8 + (lane&3)*2 + cc;
                float x0 = acc[j][cc]   + b2[col] + val[rowl*68 + col];
                float x1 = acc[j][2+cc] + b2[col] + val[(rowl+8)*68 + col];
                xs0[j*2+cc] = x0; s0 += x0; q0 += x0*x0;
                xs1[j*2+cc] = x1; s1 += x1; q1 += x1*x1;
            }
        }
        s0 += __shfl_xor_sync(0xffffffffu, s0, 1); s0 += __shfl_xor_sync(0xffffffffu, s0, 2);
        q0 += __shfl_xor_sync(0xffffffffu, q0, 1); q0 += __shfl_xor_sync(0xffffffffu, q0, 2);
        s1 += __shfl_xor_sync(0xffffffffu, s1, 1); s1 += __shfl_xor_sync(0xffffffffu, s1, 2);
        q1 += __shfl_xor_sync(0xffffffffu, q1, 1); q1 += __shfl_xor_sync(0xffffffffu, q1, 2);
        float mu0 = s0*(1.f/64.f), rstd0 = rsqrtf(q0*(1.f/64.f) - mu0*mu0 + 1e-5f);
        float mu1 = s1*(1.f/64.f), rstd1 = rsqrtf(q1*(1.f/64.f) - mu1*mu1 + 1e-5f);
        float y0 = 0.f, y1 = 0.f;
        #pragma unroll
        for (int j = 0; j < 8; ++j) {
            #pragma unroll
            for (int cc = 0; cc < 2; ++cc) {
                int col = j*8 + (lane&3)*2 + cc;
                float g = ln2g[col], be = ln2b[col], fw = fcW[col];
                y0 += ((xs0[j*2+cc] - mu0)*rstd0*g + be) * fw;
                y1 += ((xs1[j*2+cc] - mu1)*rstd1*g + be) * fw;
            }
        }
        y0 += __shfl_xor_sync(0xffffffffu, y0, 1); y0 += __shfl_xor_sync(0xffffffffu, y0, 2);
        y1 += __shfl_xor_sync(0xffffffffu, y1, 1); y1 += __shfl_xor_sync(0xffffffffu, y1, 2);
        if ((lane & 3) == 0) {
            float fb = fcb[0];
            y[r0 + rowl]     = y0 + fb;
            y[r0 + rowl + 8] = y1 + fb;
        }
    }
}

// ---------------- host ----------------
extern "C" void kernel_launch(void* const* d_in, const int* in_sizes, int n_in,
                              void* d_out, int out_size) {
    const float* src  = (const float*)d_in[0];
    const float* emb  = (const float*)d_in[2];
    const float* gwp0 = (const float*)d_in[3];
    const float* gbp0 = (const float*)d_in[4];
    const float* uwp0 = (const float*)d_in[5];
    const float* ubp0 = (const float*)d_in[6];
    const float* gwp1 = (const float*)d_in[7];
    const float* gbp1 = (const float*)d_in[8];
    const float* uwp1 = (const float*)d_in[9];
    const float* ubp1 = (const float*)d_in[10];
    const float* hypW = (const float*)d_in[11];
    const float* hypb = (const float*)d_in[12];

    const float *Wq,*Wk,*Wv,*ffW1,*ffW2,*bq,*bk,*bv,*ffb1,*ffb2,*ln1g,*ln1b,*ln2g,*ln2b,*fcW,*fcb;
    if (n_in > 14 && in_sizes[14] == 64) {
        Wq  = (const float*)d_in[13]; bq  = (const float*)d_in[14];
        Wk  = (const float*)d_in[15]; bk  = (const float*)d_in[16];
        Wv  = (const float*)d_in[17]; bv  = (const float*)d_in[18];
        ln1g= (const float*)d_in[19]; ln1b= (const float*)d_in[20];
        ffW1= (const float*)d_in[21]; ffb1= (const float*)d_in[22];
        ffW2= (const float*)d_in[23]; ffb2= (const float*)d_in[24];
        ln2g= (const float*)d_in[25]; ln2b= (const float*)d_in[26];
        fcW = (const float*)d_in[27]; fcb = (const float*)d_in[28];
    } else {
        Wq  = (const float*)d_in[13]; Wk  = (const float*)d_in[14];
        Wv  = (const float*)d_in[15]; ffW1= (const float*)d_in[16];
        ffW2= (const float*)d_in[17]; bq  = (const float*)d_in[18];
        bk  = (const float*)d_in[19]; bv  = (const float*)d_in[20];
        ffb1= (const float*)d_in[21]; ffb2= (const float*)d_in[22];
        ln1g= (const float*)d_in[23]; ln1b= (const float*)d_in[24];
        ln2g= (const float*)d_in[25]; ln2b= (const float*)d_in[26];
        fcW = (const float*)d_in[27]; fcb = (const float*)d_in[28];
    }

    float *p_gW,*p_gb,*p_uW,*p_ub,*p_cg,*p_cu,*p_mxt,*p_xt0t;
    float *p_hs0,*p_hs1,*p_hv,*p_q,*p_k,*p_v,*p_o;
    __half *p_gWh,*p_uWh,*p_hs0h,*p_mxth;
    cudaGetSymbolAddress((void**)&p_gW, g_gW);
    cudaGetSymbolAddress((void**)&p_gb, g_gb);
    cudaGetSymbolAddress((void**)&p_uW, g_uW);
    cudaGetSymbolAddress((void**)&p_ub, g_ub);
    cudaGetSymbolAddress((void**)&p_gWh, g_gWh);
    cudaGetSymbolAddress((void**)&p_uWh, g_uWh);
    cudaGetSymbolAddress((void**)&p_cg, g_cg);
    cudaGetSymbolAddress((void**)&p_cu, g_cu);
    cudaGetSymbolAddress((void**)&p_mxt, g_mxt);
    cudaGetSymbolAddress((void**)&p_mxth, g_mxth);
    cudaGetSymbolAddress((void**)&p_xt0t, g_xt0t);
    cudaGetSymbolAddress((void**)&p_hs0, g_hs0);
    cudaGetSymbolAddress((void**)&p_hs0h, g_hs0h);
    cudaGetSymbolAddress((void**)&p_hs1, g_hs1);
    cudaGetSymbolAddress((void**)&p_hv, g_hv);
    cudaGetSymbolAddress((void**)&p_q, g_q);
    cudaGetSymbolAddress((void**)&p_k, g_k);
    cudaGetSymbolAddress((void**)&p_v, g_v);
    cudaGetSymbolAddress((void**)&p_o, g_o);

    cudaFuncSetAttribute(k_recur, cudaFuncAttributeMaxDynamicSharedMemorySize, RECUR_SMEM);
    cudaFuncSetAttribute(k_tail, cudaFuncAttributeMaxDynamicSharedMemorySize, TAIL_SMEM);
    cudaFuncSetAttribute(k_precomp_mma16, cudaFuncAttributeMaxDynamicSharedMemorySize, PRE16_SMEM);

    for (int layer = 0; layer < 2; ++layer) {
        int Cin = (layer == 0) ? 2 : 64;
        int C = Cin + HH;
        int SgW4 = 2*C*128/4, SuW4 = 2*C*64/4;
        int work = NN*(SgW4 + 32 + SuW4 + 16) + ((layer == 0) ? ZT*NN*2 : 0);
        int grid = NN + (work + 255)/256;
        float* hs_out;
        float* hv_out;
        __half* hsh_out;
        if (layer == 0) {
            k_fused_pre<<<grid, 256>>>(emb, gwp0, gbp0, uwp0, ubp0,
                                       p_gW, p_gb, p_uW, p_ub, p_gWh, p_uWh, SgW4, SuW4,
                                       src, p_xt0t, 1);
            k_mix64<<<dim3(8, (ZT*2)/64), 256>>>(p_xt0t, p_mxt);
            k_precomp<<<dim3(NN, 6), 192>>>(src, p_mxt, p_gW, p_uW, p_gb, p_ub, p_cg, p_cu, Cin);
            hs_out = p_hs0; hv_out = nullptr; hsh_out = p_hs0h;
        } else {
            k_fused_pre<<<grid, 256>>>(emb, gwp1, gbp1, uwp1, ubp1,
                                       p_gW, p_gb, p_uW, p_ub, p_gWh, p_uWh, SgW4, SuW4,
                                       nullptr, nullptr, 0);
            k_mix64h<<<dim3(8, ZT), 256>>>(p_hs0h, p_mxth);
            k_precomp_mma16<<<dim3(NN, 3), 256, PRE16_SMEM>>>(p_hs0h, p_mxth, p_gWh, p_uWh,
                                                              p_gb, p_ub, p_cg, p_cu);
            hs_out = p_hs1; hv_out = p_hv; hsh_out = nullptr;
        }
        unsigned nbar0 = (layer == 0) ? 0u : 45u;
        k_recur<<<GRID_P, 256, RECUR_SMEM>>>(p_gWh, p_uWh, p_cg, p_cu, hs_out, C, Cin, nbar0,
                                             hv_out, hsh_out);
    }

    k_hyp_mma<<<dim3(4, 16), 256>>>(hypW);
    k_hyp_fin<<<(NN*TT + 255)/256, 256>>>(hypb);

    k_gemm64_mma<<<BTN/128, 256>>>(p_hs1, Wq, bq, p_q, 0);
    k_gemm64_mma<<<BTN/128, 256>>>(p_hs1, Wk, bk, p_k, 0);
    k_gemm64_mma<<<BB*NN/128, 256>>>(p_hv, Wv, nullptr, p_v, 0);

    k_attn<<<BB*NN, 128>>>(bv);

    k_tail<<<BTN/128, 256, TAIL_SMEM>>>(p_o, p_hs1, ln1g, ln1b,
                                        ffW1, ffb1, ffW2, ffb2,
                                        ln2g, ln2b, fcW, fcb, (float*)d_out);
}